// round 1
// baseline (speedup 1.0000x reference)
#include <cuda_runtime.h>
#include <math.h>

// ---------------- problem constants ----------------
#define SEQ 2048
#define HID 2560
#define NH 40
#define DQK 96          // 64 nope + 32 rope
#define DV 64
#define RD 32           // rope dim
#define QA_DIM 768
#define KVA_DIM 288     // 256 ckv + 32 k_pe
#define CKV_DIM 256
#define QB_DIM (NH*DQK)         // 3840
#define KVB_DIM (NH*(64+DV))    // 5120
#define OUT_DIM 2560
#define EPSV 1e-6f
#define QSCALE 0.10206207261596577f   // 96^-0.5

// ---------------- scratch (device globals; no allocation allowed) ----------------
__device__ float g_qa  [SEQ*QA_DIM];
__device__ float g_qan [SEQ*QA_DIM];
__device__ float g_ckv [SEQ*KVA_DIM];
__device__ float g_ckvn[SEQ*CKV_DIM];
__device__ float g_kpe [SEQ*RD];
__device__ float g_q   [SEQ*QB_DIM];
__device__ float g_kv  [SEQ*KVB_DIM];
__device__ float g_Q   [NH*SEQ*DQK];
__device__ float g_K   [NH*SEQ*DQK];
__device__ float g_V   [NH*SEQ*DV];
__device__ float g_attn[SEQ*NH*DV];

// ---------------- GEMM: C[M,N] = A[M,K] @ B[K,N], row-major, fp32 ----------------
// 128x128 tile, BK=16, 256 threads, 8x8 per thread.
#define GBM 128
#define GBN 128
#define GBK 16
#define AS_STRIDE 132   // padded (mult of 4 for float4-aligned reads)

__global__ __launch_bounds__(256) void sgemm128(const float* __restrict__ A,
                                                const float* __restrict__ B,
                                                float* __restrict__ C,
                                                int M, int N, int K) {
    __shared__ float As[GBK * AS_STRIDE];      // stored transposed: As[k][m]
    __shared__ float Bs[GBK * GBN];            // Bs[k][n]
    int tid = threadIdx.x;
    int tx = tid & 15, ty = tid >> 4;
    int row0 = blockIdx.y * GBM;
    int col0 = blockIdx.x * GBN;

    float acc[8][8];
#pragma unroll
    for (int i = 0; i < 8; i++)
#pragma unroll
        for (int j = 0; j < 8; j++) acc[i][j] = 0.f;

    for (int k0 = 0; k0 < K; k0 += GBK) {
        // load A tile (128x16) as float4, store transposed
#pragma unroll
        for (int i = 0; i < 2; i++) {
            int idx4 = tid + i * 256;          // 0..511
            int r = idx4 >> 2;                 // 0..127
            int c4 = idx4 & 3;                 // 0..3
            float4 v = *reinterpret_cast<const float4*>(
                &A[(size_t)(row0 + r) * K + k0 + c4 * 4]);
            As[(c4 * 4 + 0) * AS_STRIDE + r] = v.x;
            As[(c4 * 4 + 1) * AS_STRIDE + r] = v.y;
            As[(c4 * 4 + 2) * AS_STRIDE + r] = v.z;
            As[(c4 * 4 + 3) * AS_STRIDE + r] = v.w;
        }
        // load B tile (16x128) as float4 (N is always a multiple of 4)
#pragma unroll
        for (int i = 0; i < 2; i++) {
            int idx4 = tid + i * 256;          // 0..511
            int r = idx4 >> 5;                 // 0..15
            int c4 = idx4 & 31;                // 0..31
            int gc = col0 + c4 * 4;
            float4 v = make_float4(0.f, 0.f, 0.f, 0.f);
            if (gc < N)
                v = *reinterpret_cast<const float4*>(
                    &B[(size_t)(k0 + r) * N + gc]);
            *reinterpret_cast<float4*>(&Bs[r * GBN + c4 * 4]) = v;
        }
        __syncthreads();
#pragma unroll
        for (int kk = 0; kk < GBK; kk++) {
            float a[8], b[8];
            float4 a0 = *reinterpret_cast<const float4*>(&As[kk * AS_STRIDE + ty * 8]);
            float4 a1 = *reinterpret_cast<const float4*>(&As[kk * AS_STRIDE + ty * 8 + 4]);
            float4 b0 = *reinterpret_cast<const float4*>(&Bs[kk * GBN + tx * 8]);
            float4 b1 = *reinterpret_cast<const float4*>(&Bs[kk * GBN + tx * 8 + 4]);
            a[0]=a0.x;a[1]=a0.y;a[2]=a0.z;a[3]=a0.w;a[4]=a1.x;a[5]=a1.y;a[6]=a1.z;a[7]=a1.w;
            b[0]=b0.x;b[1]=b0.y;b[2]=b0.z;b[3]=b0.w;b[4]=b1.x;b[5]=b1.y;b[6]=b1.z;b[7]=b1.w;
#pragma unroll
            for (int i = 0; i < 8; i++)
#pragma unroll
                for (int j = 0; j < 8; j++) acc[i][j] = fmaf(a[i], b[j], acc[i][j]);
        }
        __syncthreads();
    }
#pragma unroll
    for (int i = 0; i < 8; i++) {
        int gr = row0 + ty * 8 + i;
#pragma unroll
        for (int j4 = 0; j4 < 2; j4++) {
            int gc = col0 + tx * 8 + j4 * 4;
            if (gc < N) {
                float4 v = make_float4(acc[i][j4*4+0], acc[i][j4*4+1],
                                       acc[i][j4*4+2], acc[i][j4*4+3]);
                *reinterpret_cast<float4*>(&C[(size_t)gr * N + gc]) = v;
            }
        }
    }
}

// ---------------- RMSNorm: one block per row ----------------
__global__ __launch_bounds__(256) void rmsnorm_kernel(const float* __restrict__ x,
                                                      const float* __restrict__ w,
                                                      float* __restrict__ y,
                                                      int ncols, int xstride, int ystride) {
    int row = blockIdx.x;
    const float* xr = x + (size_t)row * xstride;
    float ss = 0.f;
    for (int c = threadIdx.x; c < ncols; c += blockDim.x) {
        float v = xr[c];
        ss += v * v;
    }
    // block reduce
    __shared__ float warp_s[8];
    __shared__ float snorm;
    for (int off = 16; off > 0; off >>= 1) ss += __shfl_down_sync(0xffffffffu, ss, off);
    int lane = threadIdx.x & 31, wid = threadIdx.x >> 5;
    if (lane == 0) warp_s[wid] = ss;
    __syncthreads();
    if (threadIdx.x == 0) {
        float t = 0.f;
        for (int i = 0; i < (int)(blockDim.x >> 5); i++) t += warp_s[i];
        snorm = rsqrtf(t / (float)ncols + EPSV);
    }
    __syncthreads();
    float r = snorm;
    for (int c = threadIdx.x; c < ncols; c += blockDim.x)
        y[(size_t)row * ystride + c] = xr[c] * r * w[c];
}

// ---------------- k_pe RoPE: 2048 blocks x 32 threads ----------------
__global__ void kpe_rope_kernel(const float* __restrict__ ckv,
                                const float* __restrict__ cosb,
                                const float* __restrict__ sinb,
                                float* __restrict__ kpe) {
    int s = blockIdx.x;
    int d = threadIdx.x;  // 0..31
    const float* base = ckv + (size_t)s * KVA_DIM + CKV_DIM;
    float x = base[d];
    float rot = (d < 16) ? -base[d + 16] : base[d - 16];
    kpe[(size_t)s * RD + d] = x * cosb[(size_t)s * RD + d] + rot * sinb[(size_t)s * RD + d];
}

// ---------------- build per-head Q (roped+scaled), K, V ----------------
__global__ void prep_kernel(const float* __restrict__ q,
                            const float* __restrict__ kv,
                            const float* __restrict__ kpe,
                            const float* __restrict__ cosb,
                            const float* __restrict__ sinb,
                            float* __restrict__ Q, float* __restrict__ K,
                            float* __restrict__ V) {
    int s = blockIdx.x;
    int h = blockIdx.y;
    int d = threadIdx.x;  // 0..95
    size_t qbase = (size_t)s * QB_DIM + (size_t)h * DQK;
    size_t kvbase = (size_t)s * KVB_DIM + (size_t)h * 128;
    size_t hs = ((size_t)h * SEQ + s);

    float qv;
    if (d < 64) {
        qv = q[qbase + d];
    } else {
        int i = d - 64;
        float x = q[qbase + 64 + i];
        float rot = (i < 16) ? -q[qbase + 64 + i + 16] : q[qbase + 64 + i - 16];
        qv = x * cosb[(size_t)s * RD + i] + rot * sinb[(size_t)s * RD + i];
    }
    Q[hs * DQK + d] = qv * QSCALE;

    float kvv = (d < 64) ? kv[kvbase + d] : kpe[(size_t)s * RD + (d - 64)];
    K[hs * DQK + d] = kvv;

    if (d < DV) V[hs * DV + d] = kv[kvbase + 64 + d];
}

// ---------------- flash attention: 64x64 tiles, causal, fp32 ----------------
#define FBM 64
#define FBN 64
#define QK_STRIDE 97
#define PV_STRIDE 65
// smem floats: Qs + Ks (64*97 each) + Vs + Ps (64*65 each) + red(64*16) + m/l/a(64*3)
#define FLASH_SMEM_FLOATS (2*64*QK_STRIDE + 2*64*PV_STRIDE + 64*16 + 64*3)
#define FLASH_SMEM_BYTES (FLASH_SMEM_FLOATS * 4)

__global__ __launch_bounds__(256) void flash_kernel(const float* __restrict__ Q,
                                                    const float* __restrict__ K,
                                                    const float* __restrict__ V,
                                                    float* __restrict__ O) {
    extern __shared__ float sm[];
    float* Qs = sm;
    float* Ks = Qs + 64 * QK_STRIDE;
    float* Vs = Ks + 64 * QK_STRIDE;
    float* Ps = Vs + 64 * PV_STRIDE;
    float* red = Ps + 64 * PV_STRIDE;
    float* mrow = red + 64 * 16;
    float* lrow = mrow + 64;
    float* arow = lrow + 64;

    int h = blockIdx.y;
    int qt = blockIdx.x;
    int tid = threadIdx.x;
    int tx = tid & 15, ty = tid >> 4;
    const float* Qh = Q + (size_t)h * SEQ * DQK;
    const float* Kh = K + (size_t)h * SEQ * DQK;
    const float* Vh = V + (size_t)h * SEQ * DV;
    int q0 = qt * FBM;

    for (int idx = tid; idx < FBM * DQK; idx += 256) {
        int r = idx / DQK, c = idx % DQK;
        Qs[r * QK_STRIDE + c] = Qh[(size_t)(q0 + r) * DQK + c];
    }
    if (tid < 64) { mrow[tid] = -1e30f; lrow[tid] = 0.f; }
    float oacc[4][4];
#pragma unroll
    for (int i = 0; i < 4; i++)
#pragma unroll
        for (int j = 0; j < 4; j++) oacc[i][j] = 0.f;
    __syncthreads();

    for (int kt = 0; kt <= qt; kt++) {
        int k0 = kt * FBN;
        for (int idx = tid; idx < FBN * DQK; idx += 256) {
            int r = idx / DQK, c = idx % DQK;
            Ks[r * QK_STRIDE + c] = Kh[(size_t)(k0 + r) * DQK + c];
        }
        for (int idx = tid; idx < FBN * DV; idx += 256) {
            int r = idx >> 6, c = idx & 63;
            Vs[r * PV_STRIDE + c] = Vh[(size_t)(k0 + r) * DV + c];
        }
        __syncthreads();

        // S = Q K^T  (4x4 per thread)
        float s[4][4];
#pragma unroll
        for (int i = 0; i < 4; i++)
#pragma unroll
            for (int j = 0; j < 4; j++) s[i][j] = 0.f;
        for (int k = 0; k < DQK; k++) {
            float a[4], b[4];
#pragma unroll
            for (int i = 0; i < 4; i++) a[i] = Qs[(ty * 4 + i) * QK_STRIDE + k];
#pragma unroll
            for (int j = 0; j < 4; j++) b[j] = Ks[(tx * 4 + j) * QK_STRIDE + k];
#pragma unroll
            for (int i = 0; i < 4; i++)
#pragma unroll
                for (int j = 0; j < 4; j++) s[i][j] = fmaf(a[i], b[j], s[i][j]);
        }
        if (kt == qt) {
#pragma unroll
            for (int i = 0; i < 4; i++)
#pragma unroll
                for (int j = 0; j < 4; j++)
                    if (k0 + tx * 4 + j > q0 + ty * 4 + i) s[i][j] = -1e30f;
        }
        // partial row max
#pragma unroll
        for (int i = 0; i < 4; i++) {
            float mx = fmaxf(fmaxf(s[i][0], s[i][1]), fmaxf(s[i][2], s[i][3]));
            red[(ty * 4 + i) * 16 + tx] = mx;
        }
        __syncthreads();
        if (tid < 64) {
            float mx = red[tid * 16];
#pragma unroll
            for (int j = 1; j < 16; j++) mx = fmaxf(mx, red[tid * 16 + j]);
            float mold = mrow[tid];
            float mnew = fmaxf(mold, mx);
            float al = __expf(mold - mnew);
            mrow[tid] = mnew;
            arow[tid] = al;
            lrow[tid] *= al;
        }
        __syncthreads();
        // P = exp(S - m), partial row sums
#pragma unroll
        for (int i = 0; i < 4; i++) {
            int row = ty * 4 + i;
            float mn = mrow[row];
            float rs = 0.f;
#pragma unroll
            for (int j = 0; j < 4; j++) {
                float p = __expf(s[i][j] - mn);
                Ps[row * PV_STRIDE + tx * 4 + j] = p;
                rs += p;
            }
            red[row * 16 + tx] = rs;
        }
        __syncthreads();
        if (tid < 64) {
            float rs = 0.f;
#pragma unroll
            for (int j = 0; j < 16; j++) rs += red[tid * 16 + j];
            lrow[tid] += rs;
        }
        // rescale O then O += P V
        float al[4];
#pragma unroll
        for (int i = 0; i < 4; i++) al[i] = arow[ty * 4 + i];
#pragma unroll
        for (int i = 0; i < 4; i++)
#pragma unroll
            for (int j = 0; j < 4; j++) oacc[i][j] *= al[i];
        for (int k = 0; k < FBN; k++) {
            float a[4], b[4];
#pragma unroll
            for (int i = 0; i < 4; i++) a[i] = Ps[(ty * 4 + i) * PV_STRIDE + k];
#pragma unroll
            for (int j = 0; j < 4; j++) b[j] = Vs[k * PV_STRIDE + tx * 4 + j];
#pragma unroll
            for (int i = 0; i < 4; i++)
#pragma unroll
                for (int j = 0; j < 4; j++) oacc[i][j] = fmaf(a[i], b[j], oacc[i][j]);
        }
        __syncthreads();
    }
    // epilogue: O / l  -> g_attn[s][h*64+d]
#pragma unroll
    for (int i = 0; i < 4; i++) {
        int row = ty * 4 + i;
        float inv = 1.f / lrow[row];
        int srow = q0 + row;
#pragma unroll
        for (int j = 0; j < 4; j++)
            O[(size_t)srow * (NH * DV) + h * DV + tx * 4 + j] = oacc[i][j] * inv;
    }
}

// ---------------- launch ----------------
extern "C" void kernel_launch(void* const* d_in, const int* in_sizes, int n_in,
                              void* d_out, int out_size) {
    const float* hidden   = (const float*)d_in[0];
    const float* cosb     = (const float*)d_in[1];
    const float* sinb     = (const float*)d_in[2];
    const float* wq_a     = (const float*)d_in[3];
    const float* q_a_ln_w = (const float*)d_in[4];
    const float* wq_b     = (const float*)d_in[5];
    const float* wkv_a    = (const float*)d_in[6];
    const float* kv_a_ln  = (const float*)d_in[7];
    const float* wkv_b    = (const float*)d_in[8];
    const float* wo       = (const float*)d_in[9];
    float* out = (float*)d_out;

    float *qa, *qan, *ckv, *ckvn, *kpe, *q, *kv, *Qp, *Kp, *Vp, *attn;
    cudaGetSymbolAddress((void**)&qa,   g_qa);
    cudaGetSymbolAddress((void**)&qan,  g_qan);
    cudaGetSymbolAddress((void**)&ckv,  g_ckv);
    cudaGetSymbolAddress((void**)&ckvn, g_ckvn);
    cudaGetSymbolAddress((void**)&kpe,  g_kpe);
    cudaGetSymbolAddress((void**)&q,    g_q);
    cudaGetSymbolAddress((void**)&kv,   g_kv);
    cudaGetSymbolAddress((void**)&Qp,   g_Q);
    cudaGetSymbolAddress((void**)&Kp,   g_K);
    cudaGetSymbolAddress((void**)&Vp,   g_V);
    cudaGetSymbolAddress((void**)&attn, g_attn);

    cudaFuncSetAttribute(flash_kernel, cudaFuncAttributeMaxDynamicSharedMemorySize,
                         FLASH_SMEM_BYTES);

    dim3 blk(256);

    // 1) hidden @ wq_a -> qa (2048x768)
    sgemm128<<<dim3((QA_DIM + GBN - 1) / GBN, SEQ / GBM), blk>>>(hidden, wq_a, qa,
                                                                 SEQ, QA_DIM, HID);
    // 2) hidden @ wkv_a -> ckv (2048x288)
    sgemm128<<<dim3((KVA_DIM + GBN - 1) / GBN, SEQ / GBM), blk>>>(hidden, wkv_a, ckv,
                                                                  SEQ, KVA_DIM, HID);
    // 3) rmsnorm q
    rmsnorm_kernel<<<SEQ, 256>>>(qa, q_a_ln_w, qan, QA_DIM, QA_DIM, QA_DIM);
    // 4) rmsnorm ckv[:, :256]
    rmsnorm_kernel<<<SEQ, 256>>>(ckv, kv_a_ln, ckvn, CKV_DIM, KVA_DIM, CKV_DIM);
    // 5) rope on k_pe
    kpe_rope_kernel<<<SEQ, RD>>>(ckv, cosb, sinb, kpe);
    // 6) qan @ wq_b -> q (2048x3840)
    sgemm128<<<dim3(QB_DIM / GBN, SEQ / GBM), blk>>>(qan, wq_b, q, SEQ, QB_DIM, QA_DIM);
    // 7) ckvn @ wkv_b -> kv (2048x5120)
    sgemm128<<<dim3(KVB_DIM / GBN, SEQ / GBM), blk>>>(ckvn, wkv_b, kv, SEQ, KVB_DIM, CKV_DIM);
    // 8) assemble per-head Q (roped, scaled), K, V
    prep_kernel<<<dim3(SEQ, NH), DQK>>>(q, kv, kpe, cosb, sinb, Qp, Kp, Vp);
    // 9) causal flash attention
    flash_kernel<<<dim3(SEQ / FBM, NH), blk, FLASH_SMEM_BYTES>>>(Qp, Kp, Vp, attn);
    // 10) attn @ wo -> out (2048x2560)
    sgemm128<<<dim3(OUT_DIM / GBN, SEQ / GBM), blk>>>(attn, wo, out, SEQ, OUT_DIM,
                                                      NH * DV);
}

// round 2
// speedup vs baseline: 1.7808x; 1.7808x over previous
#include <cuda_runtime.h>
#include <math.h>
#include <stdint.h>

// ---------------- problem constants ----------------
#define SEQ 2048
#define HID 2560
#define NH 40
#define DQK 96          // 64 nope + 32 rope
#define DV 64
#define RD 32           // rope dim
#define QA_DIM 768
#define KVA_DIM 288     // 256 ckv + 32 k_pe
#define CKV_DIM 256
#define QB_DIM (NH*DQK)         // 3840
#define KVB_DIM (NH*(64+DV))    // 5120
#define OUT_DIM 2560
#define EPSV 1e-6f
#define QSCALE 0.10206207261596577f   // 96^-0.5

// ---------------- scratch (device globals; no allocation allowed) ----------------
__device__ float g_qa  [SEQ*QA_DIM];
__device__ float g_qan [SEQ*QA_DIM];
__device__ float g_ckv [SEQ*KVA_DIM];
__device__ float g_ckvn[SEQ*CKV_DIM];
__device__ float g_kpe [SEQ*RD];
__device__ float g_q   [SEQ*QB_DIM];
__device__ float g_kv  [SEQ*KVB_DIM];
__device__ float g_Q   [NH*SEQ*DQK];
__device__ float g_K   [NH*SEQ*DQK];
__device__ float g_V   [NH*SEQ*DV];
__device__ float g_attn[SEQ*NH*DV];

// ================= TF32 tensor-core GEMM =================
// C[M,N] = A[M,K] @ B[K,N], row-major fp32 in/out, tf32 mma.sync.
// Tile 128x128x32, 256 threads (8 warps as 2x4), warp tile 64x32,
// cp.async double-buffered smem, conflict-free strides.
#define TBM 128
#define TBN 128
#define TBK 32
#define ASTR 36    // A smem row stride (floats): banks (4g+t) unique
#define BSTR 136   // B smem row stride (floats): banks (8t+g) unique
#define ABUF (TBM*ASTR)   // 4608 floats
#define BBUF (TBK*BSTR)   // 4352 floats
#define TG_SMEM_BYTES ((2*ABUF + 2*BBUF) * 4)   // 71680

__device__ __forceinline__ uint32_t f2tf32(float f) {
    uint32_t u;
    asm("cvt.rna.tf32.f32 %0, %1;" : "=r"(u) : "f"(f));
    return u;
}

__device__ __forceinline__ void cp16(uint32_t dst, const void* src, bool pred) {
    int sz = pred ? 16 : 0;
    asm volatile("cp.async.cg.shared.global [%0], [%1], 16, %2;\n"
                 :: "r"(dst), "l"(src), "r"(sz));
}
__device__ __forceinline__ void cp_commit() {
    asm volatile("cp.async.commit_group;\n");
}
template <int N>
__device__ __forceinline__ void cp_wait() {
    asm volatile("cp.async.wait_group %0;\n" :: "n"(N));
}

#define MMA_TF32(c, a, b) \
    asm volatile("mma.sync.aligned.m16n8k8.row.col.f32.tf32.tf32.f32 " \
                 "{%0,%1,%2,%3},{%4,%5,%6,%7},{%8,%9},{%0,%1,%2,%3};" \
                 : "+f"(c[0]), "+f"(c[1]), "+f"(c[2]), "+f"(c[3]) \
                 : "r"(a[0]), "r"(a[1]), "r"(a[2]), "r"(a[3]), \
                   "r"(b[0]), "r"(b[1]))

__global__ __launch_bounds__(256) void tgemm(const float* __restrict__ A,
                                             const float* __restrict__ B,
                                             float* __restrict__ C,
                                             int M, int N, int K) {
    extern __shared__ float sm[];
    float* sA = sm;                 // 2 buffers of [128][ASTR]
    float* sB = sm + 2 * ABUF;      // 2 buffers of [32][BSTR]
    uint32_t sA_u = (uint32_t)__cvta_generic_to_shared(sA);
    uint32_t sB_u = (uint32_t)__cvta_generic_to_shared(sB);

    int tid = threadIdx.x;
    int warp = tid >> 5, lane = tid & 31;
    int g = lane >> 2, t = lane & 3;
    int wrow = (warp >> 2) * 64;     // 0 or 64
    int wcol = (warp & 3) * 32;      // 0,32,64,96
    int row0 = blockIdx.y * TBM;
    int col0 = blockIdx.x * TBN;

    float c[4][4][4];
#pragma unroll
    for (int mi = 0; mi < 4; mi++)
#pragma unroll
        for (int ni = 0; ni < 4; ni++)
#pragma unroll
            for (int r = 0; r < 4; r++) c[mi][ni][r] = 0.f;

    int kt_total = K / TBK;

    // ---- tile load lambda (manual) ----
    // A: 128 rows x 8 float4   B: 32 rows x 32 float4 (guard col<N)
    {
        int k0 = 0;
#pragma unroll
        for (int i = 0; i < 4; i++) {
            int idx = tid + i * 256;
            int r = idx >> 3, c4 = idx & 7;
            cp16(sA_u + (uint32_t)((r * ASTR + c4 * 4) * 4),
                 A + (size_t)(row0 + r) * K + k0 + c4 * 4, true);
        }
#pragma unroll
        for (int i = 0; i < 4; i++) {
            int idx = tid + i * 256;
            int r = idx >> 5, c4 = idx & 31;
            int col = col0 + c4 * 4;
            bool p = col < N;
            const float* src = p ? (B + (size_t)(k0 + r) * N + col) : B;
            cp16(sB_u + (uint32_t)((r * BSTR + c4 * 4) * 4), src, p);
        }
        cp_commit();
    }

    for (int kt = 0; kt < kt_total; kt++) {
        int cur = kt & 1;
        if (kt + 1 < kt_total) {
            int k0 = (kt + 1) * TBK;
            int nb = cur ^ 1;
#pragma unroll
            for (int i = 0; i < 4; i++) {
                int idx = tid + i * 256;
                int r = idx >> 3, c4 = idx & 7;
                cp16(sA_u + (uint32_t)((nb * ABUF + r * ASTR + c4 * 4) * 4),
                     A + (size_t)(row0 + r) * K + k0 + c4 * 4, true);
            }
#pragma unroll
            for (int i = 0; i < 4; i++) {
                int idx = tid + i * 256;
                int r = idx >> 5, c4 = idx & 31;
                int col = col0 + c4 * 4;
                bool p = col < N;
                const float* src = p ? (B + (size_t)(k0 + r) * N + col) : B;
                cp16(sB_u + (uint32_t)((nb * BBUF + r * BSTR + c4 * 4) * 4), src, p);
            }
            cp_commit();
            cp_wait<1>();
        } else {
            cp_wait<0>();
        }
        __syncthreads();

        const float* As = sA + cur * ABUF;
        const float* Bs = sB + cur * BBUF;
#pragma unroll
        for (int k0 = 0; k0 < TBK; k0 += 8) {
            uint32_t a[4][4], b[4][2];
#pragma unroll
            for (int mi = 0; mi < 4; mi++) {
                int r0 = wrow + mi * 16 + g;
                a[mi][0] = f2tf32(As[r0 * ASTR + k0 + t]);
                a[mi][1] = f2tf32(As[(r0 + 8) * ASTR + k0 + t]);
                a[mi][2] = f2tf32(As[r0 * ASTR + k0 + t + 4]);
                a[mi][3] = f2tf32(As[(r0 + 8) * ASTR + k0 + t + 4]);
            }
#pragma unroll
            for (int ni = 0; ni < 4; ni++) {
                int cB = wcol + ni * 8 + g;
                b[ni][0] = f2tf32(Bs[(k0 + t) * BSTR + cB]);
                b[ni][1] = f2tf32(Bs[(k0 + t + 4) * BSTR + cB]);
            }
#pragma unroll
            for (int mi = 0; mi < 4; mi++)
#pragma unroll
                for (int ni = 0; ni < 4; ni++)
                    MMA_TF32(c[mi][ni], a[mi], b[ni]);
        }
        __syncthreads();
    }

    // epilogue: c0,c1 -> (row g, cols 2t,2t+1); c2,c3 -> (row g+8)
#pragma unroll
    for (int mi = 0; mi < 4; mi++) {
#pragma unroll
        for (int ni = 0; ni < 4; ni++) {
            int row = row0 + wrow + mi * 16 + g;
            int col = col0 + wcol + ni * 8 + 2 * t;
            if (col < N) {
                float2 v0 = make_float2(c[mi][ni][0], c[mi][ni][1]);
                float2 v1 = make_float2(c[mi][ni][2], c[mi][ni][3]);
                *reinterpret_cast<float2*>(&C[(size_t)row * N + col]) = v0;
                *reinterpret_cast<float2*>(&C[(size_t)(row + 8) * N + col]) = v1;
            }
        }
    }
}

// ---------------- RMSNorm: one block per row ----------------
__global__ __launch_bounds__(256) void rmsnorm_kernel(const float* __restrict__ x,
                                                      const float* __restrict__ w,
                                                      float* __restrict__ y,
                                                      int ncols, int xstride, int ystride) {
    int row = blockIdx.x;
    const float* xr = x + (size_t)row * xstride;
    float ss = 0.f;
    for (int c = threadIdx.x; c < ncols; c += blockDim.x) {
        float v = xr[c];
        ss += v * v;
    }
    __shared__ float warp_s[8];
    __shared__ float snorm;
    for (int off = 16; off > 0; off >>= 1) ss += __shfl_down_sync(0xffffffffu, ss, off);
    int lane = threadIdx.x & 31, wid = threadIdx.x >> 5;
    if (lane == 0) warp_s[wid] = ss;
    __syncthreads();
    if (threadIdx.x == 0) {
        float tt = 0.f;
        for (int i = 0; i < (int)(blockDim.x >> 5); i++) tt += warp_s[i];
        snorm = rsqrtf(tt / (float)ncols + EPSV);
    }
    __syncthreads();
    float r = snorm;
    for (int c = threadIdx.x; c < ncols; c += blockDim.x)
        y[(size_t)row * ystride + c] = xr[c] * r * w[c];
}

// ---------------- k_pe RoPE ----------------
__global__ void kpe_rope_kernel(const float* __restrict__ ckv,
                                const float* __restrict__ cosb,
                                const float* __restrict__ sinb,
                                float* __restrict__ kpe) {
    int s = blockIdx.x;
    int d = threadIdx.x;  // 0..31
    const float* base = ckv + (size_t)s * KVA_DIM + CKV_DIM;
    float x = base[d];
    float rot = (d < 16) ? -base[d + 16] : base[d - 16];
    kpe[(size_t)s * RD + d] = x * cosb[(size_t)s * RD + d] + rot * sinb[(size_t)s * RD + d];
}

// ---------------- build per-head Q (roped+scaled), K, V ----------------
__global__ void prep_kernel(const float* __restrict__ q,
                            const float* __restrict__ kv,
                            const float* __restrict__ kpe,
                            const float* __restrict__ cosb,
                            const float* __restrict__ sinb,
                            float* __restrict__ Q, float* __restrict__ K,
                            float* __restrict__ V) {
    int s = blockIdx.x;
    int h = blockIdx.y;
    int d = threadIdx.x;  // 0..95
    size_t qbase = (size_t)s * QB_DIM + (size_t)h * DQK;
    size_t kvbase = (size_t)s * KVB_DIM + (size_t)h * 128;
    size_t hs = ((size_t)h * SEQ + s);

    float qv;
    if (d < 64) {
        qv = q[qbase + d];
    } else {
        int i = d - 64;
        float x = q[qbase + 64 + i];
        float rot = (i < 16) ? -q[qbase + 64 + i + 16] : q[qbase + 64 + i - 16];
        qv = x * cosb[(size_t)s * RD + i] + rot * sinb[(size_t)s * RD + i];
    }
    Q[hs * DQK + d] = qv * QSCALE;

    float kvv = (d < 64) ? kv[kvbase + d] : kpe[(size_t)s * RD + (d - 64)];
    K[hs * DQK + d] = kvv;

    if (d < DV) V[hs * DV + d] = kv[kvbase + 64 + d];
}

// ---------------- flash attention: 64x64 tiles, causal, fp32 ----------------
#define FBM 64
#define FBN 64
#define QK_STRIDE 97
#define PV_STRIDE 65
#define FLASH_SMEM_FLOATS (2*64*QK_STRIDE + 2*64*PV_STRIDE + 64*16 + 64*3)
#define FLASH_SMEM_BYTES (FLASH_SMEM_FLOATS * 4)

__global__ __launch_bounds__(256) void flash_kernel(const float* __restrict__ Q,
                                                    const float* __restrict__ K,
                                                    const float* __restrict__ V,
                                                    float* __restrict__ O) {
    extern __shared__ float smf[];
    float* Qs = smf;
    float* Ks = Qs + 64 * QK_STRIDE;
    float* Vs = Ks + 64 * QK_STRIDE;
    float* Ps = Vs + 64 * PV_STRIDE;
    float* red = Ps + 64 * PV_STRIDE;
    float* mrow = red + 64 * 16;
    float* lrow = mrow + 64;
    float* arow = lrow + 64;

    int h = blockIdx.y;
    int qt = blockIdx.x;
    int tid = threadIdx.x;
    int tx = tid & 15, ty = tid >> 4;
    const float* Qh = Q + (size_t)h * SEQ * DQK;
    const float* Kh = K + (size_t)h * SEQ * DQK;
    const float* Vh = V + (size_t)h * SEQ * DV;
    int q0 = qt * FBM;

    for (int idx = tid; idx < FBM * DQK; idx += 256) {
        int r = idx / DQK, c = idx % DQK;
        Qs[r * QK_STRIDE + c] = Qh[(size_t)(q0 + r) * DQK + c];
    }
    if (tid < 64) { mrow[tid] = -1e30f; lrow[tid] = 0.f; }
    float oacc[4][4];
#pragma unroll
    for (int i = 0; i < 4; i++)
#pragma unroll
        for (int j = 0; j < 4; j++) oacc[i][j] = 0.f;
    __syncthreads();

    for (int kt = 0; kt <= qt; kt++) {
        int k0 = kt * FBN;
        for (int idx = tid; idx < FBN * DQK; idx += 256) {
            int r = idx / DQK, c = idx % DQK;
            Ks[r * QK_STRIDE + c] = Kh[(size_t)(k0 + r) * DQK + c];
        }
        for (int idx = tid; idx < FBN * DV; idx += 256) {
            int r = idx >> 6, c = idx & 63;
            Vs[r * PV_STRIDE + c] = Vh[(size_t)(k0 + r) * DV + c];
        }
        __syncthreads();

        float s[4][4];
#pragma unroll
        for (int i = 0; i < 4; i++)
#pragma unroll
            for (int j = 0; j < 4; j++) s[i][j] = 0.f;
        for (int k = 0; k < DQK; k++) {
            float a[4], b[4];
#pragma unroll
            for (int i = 0; i < 4; i++) a[i] = Qs[(ty * 4 + i) * QK_STRIDE + k];
#pragma unroll
            for (int j = 0; j < 4; j++) b[j] = Ks[(tx * 4 + j) * QK_STRIDE + k];
#pragma unroll
            for (int i = 0; i < 4; i++)
#pragma unroll
                for (int j = 0; j < 4; j++) s[i][j] = fmaf(a[i], b[j], s[i][j]);
        }
        if (kt == qt) {
#pragma unroll
            for (int i = 0; i < 4; i++)
#pragma unroll
                for (int j = 0; j < 4; j++)
                    if (k0 + tx * 4 + j > q0 + ty * 4 + i) s[i][j] = -1e30f;
        }
#pragma unroll
        for (int i = 0; i < 4; i++) {
            float mx = fmaxf(fmaxf(s[i][0], s[i][1]), fmaxf(s[i][2], s[i][3]));
            red[(ty * 4 + i) * 16 + tx] = mx;
        }
        __syncthreads();
        if (tid < 64) {
            float mx = red[tid * 16];
#pragma unroll
            for (int j = 1; j < 16; j++) mx = fmaxf(mx, red[tid * 16 + j]);
            float mold = mrow[tid];
            float mnew = fmaxf(mold, mx);
            float al = __expf(mold - mnew);
            mrow[tid] = mnew;
            arow[tid] = al;
            lrow[tid] *= al;
        }
        __syncthreads();
#pragma unroll
        for (int i = 0; i < 4; i++) {
            int row = ty * 4 + i;
            float mn = mrow[row];
            float rs = 0.f;
#pragma unroll
            for (int j = 0; j < 4; j++) {
                float p = __expf(s[i][j] - mn);
                Ps[row * PV_STRIDE + tx * 4 + j] = p;
                rs += p;
            }
            red[row * 16 + tx] = rs;
        }
        __syncthreads();
        if (tid < 64) {
            float rs = 0.f;
#pragma unroll
            for (int j = 0; j < 16; j++) rs += red[tid * 16 + j];
            lrow[tid] += rs;
        }
        float al[4];
#pragma unroll
        for (int i = 0; i < 4; i++) al[i] = arow[ty * 4 + i];
#pragma unroll
        for (int i = 0; i < 4; i++)
#pragma unroll
            for (int j = 0; j < 4; j++) oacc[i][j] *= al[i];
        for (int k = 0; k < FBN; k++) {
            float a[4], b[4];
#pragma unroll
            for (int i = 0; i < 4; i++) a[i] = Ps[(ty * 4 + i) * PV_STRIDE + k];
#pragma unroll
            for (int j = 0; j < 4; j++) b[j] = Vs[k * PV_STRIDE + tx * 4 + j];
#pragma unroll
            for (int i = 0; i < 4; i++)
#pragma unroll
                for (int j = 0; j < 4; j++) oacc[i][j] = fmaf(a[i], b[j], oacc[i][j]);
        }
        __syncthreads();
    }
#pragma unroll
    for (int i = 0; i < 4; i++) {
        int row = ty * 4 + i;
        float inv = 1.f / lrow[row];
        int srow = q0 + row;
#pragma unroll
        for (int j = 0; j < 4; j++)
            O[(size_t)srow * (NH * DV) + h * DV + tx * 4 + j] = oacc[i][j] * inv;
    }
}

// ---------------- launch ----------------
extern "C" void kernel_launch(void* const* d_in, const int* in_sizes, int n_in,
                              void* d_out, int out_size) {
    const float* hidden   = (const float*)d_in[0];
    const float* cosb     = (const float*)d_in[1];
    const float* sinb     = (const float*)d_in[2];
    const float* wq_a     = (const float*)d_in[3];
    const float* q_a_ln_w = (const float*)d_in[4];
    const float* wq_b     = (const float*)d_in[5];
    const float* wkv_a    = (const float*)d_in[6];
    const float* kv_a_ln  = (const float*)d_in[7];
    const float* wkv_b    = (const float*)d_in[8];
    const float* wo       = (const float*)d_in[9];
    float* out = (float*)d_out;

    float *qa, *qan, *ckv, *ckvn, *kpe, *q, *kv, *Qp, *Kp, *Vp, *attn;
    cudaGetSymbolAddress((void**)&qa,   g_qa);
    cudaGetSymbolAddress((void**)&qan,  g_qan);
    cudaGetSymbolAddress((void**)&ckv,  g_ckv);
    cudaGetSymbolAddress((void**)&ckvn, g_ckvn);
    cudaGetSymbolAddress((void**)&kpe,  g_kpe);
    cudaGetSymbolAddress((void**)&q,    g_q);
    cudaGetSymbolAddress((void**)&kv,   g_kv);
    cudaGetSymbolAddress((void**)&Qp,   g_Q);
    cudaGetSymbolAddress((void**)&Kp,   g_K);
    cudaGetSymbolAddress((void**)&Vp,   g_V);
    cudaGetSymbolAddress((void**)&attn, g_attn);

    cudaFuncSetAttribute(flash_kernel, cudaFuncAttributeMaxDynamicSharedMemorySize,
                         FLASH_SMEM_BYTES);
    cudaFuncSetAttribute(tgemm, cudaFuncAttributeMaxDynamicSharedMemorySize,
                         TG_SMEM_BYTES);

    dim3 blk(256);

    // 1) hidden @ wq_a -> qa (2048x768)
    tgemm<<<dim3((QA_DIM + TBN - 1) / TBN, SEQ / TBM), blk, TG_SMEM_BYTES>>>(
        hidden, wq_a, qa, SEQ, QA_DIM, HID);
    // 2) hidden @ wkv_a -> ckv (2048x288)
    tgemm<<<dim3((KVA_DIM + TBN - 1) / TBN, SEQ / TBM), blk, TG_SMEM_BYTES>>>(
        hidden, wkv_a, ckv, SEQ, KVA_DIM, HID);
    // 3) rmsnorm q
    rmsnorm_kernel<<<SEQ, 256>>>(qa, q_a_ln_w, qan, QA_DIM, QA_DIM, QA_DIM);
    // 4) rmsnorm ckv[:, :256]
    rmsnorm_kernel<<<SEQ, 256>>>(ckv, kv_a_ln, ckvn, CKV_DIM, KVA_DIM, CKV_DIM);
    // 5) rope on k_pe
    kpe_rope_kernel<<<SEQ, RD>>>(ckv, cosb, sinb, kpe);
    // 6) qan @ wq_b -> q (2048x3840)
    tgemm<<<dim3(QB_DIM / TBN, SEQ / TBM), blk, TG_SMEM_BYTES>>>(
        qan, wq_b, q, SEQ, QB_DIM, QA_DIM);
    // 7) ckvn @ wkv_b -> kv (2048x5120)
    tgemm<<<dim3(KVB_DIM / TBN, SEQ / TBM), blk, TG_SMEM_BYTES>>>(
        ckvn, wkv_b, kv, SEQ, KVB_DIM, CKV_DIM);
    // 8) assemble per-head Q (roped, scaled), K, V
    prep_kernel<<<dim3(SEQ, NH), DQK>>>(q, kv, kpe, cosb, sinb, Qp, Kp, Vp);
    // 9) causal flash attention
    flash_kernel<<<dim3(SEQ / FBM, NH), blk, FLASH_SMEM_BYTES>>>(Qp, Kp, Vp, attn);
    // 10) attn @ wo -> out (2048x2560)
    tgemm<<<dim3(OUT_DIM / TBN, SEQ / TBM), blk, TG_SMEM_BYTES>>>(
        attn, wo, out, SEQ, OUT_DIM, NH * DV);
}

// round 3
// speedup vs baseline: 3.3907x; 1.9040x over previous
#include <cuda_runtime.h>
#include <math.h>
#include <stdint.h>

// ---------------- problem constants ----------------
#define SEQ 2048
#define HID 2560
#define NH 40
#define DQK 96          // 64 nope + 32 rope
#define DV 64
#define RD 32           // rope dim
#define QA_DIM 768
#define KVA_DIM 288     // 256 ckv + 32 k_pe
#define CKV_DIM 256
#define QB_DIM (NH*DQK)         // 3840
#define KVB_DIM (NH*(64+DV))    // 5120
#define OUT_DIM 2560
#define EPSV 1e-6f
#define QSCALE 0.10206207261596577f   // 96^-0.5

// ---------------- scratch ----------------
__device__ float g_qa  [SEQ*QA_DIM];
__device__ float g_qan [SEQ*QA_DIM];
__device__ float g_ckv [SEQ*KVA_DIM];
__device__ float g_ckvn[SEQ*CKV_DIM];
__device__ float g_kpe [SEQ*RD];
__device__ float g_q   [SEQ*QB_DIM];
__device__ float g_kv  [SEQ*KVB_DIM];
__device__ float g_Q   [NH*SEQ*DQK];
__device__ float g_K   [NH*SEQ*DQK];
__device__ float g_V   [NH*SEQ*DV];
__device__ float g_attn[SEQ*NH*DV];

// ---------------- tf32 helpers ----------------
__device__ __forceinline__ uint32_t f2tf32(float f) {
    uint32_t u;
    asm("cvt.rna.tf32.f32 %0, %1;" : "=r"(u) : "f"(f));
    return u;
}
__device__ __forceinline__ float tf32r(float f) {
    uint32_t u;
    asm("cvt.rna.tf32.f32 %0, %1;" : "=r"(u) : "f"(f));
    return __uint_as_float(u);
}

__device__ __forceinline__ void cp16(uint32_t dst, const void* src, bool pred) {
    int sz = pred ? 16 : 0;
    asm volatile("cp.async.cg.shared.global [%0], [%1], 16, %2;\n"
                 :: "r"(dst), "l"(src), "r"(sz));
}
__device__ __forceinline__ void cp_commit() {
    asm volatile("cp.async.commit_group;\n");
}
template <int N>
__device__ __forceinline__ void cp_wait() {
    asm volatile("cp.async.wait_group %0;\n" :: "n"(N));
}

#define MMA_TF32(c, a, b) \
    asm volatile("mma.sync.aligned.m16n8k8.row.col.f32.tf32.tf32.f32 " \
                 "{%0,%1,%2,%3},{%4,%5,%6,%7},{%8,%9},{%0,%1,%2,%3};" \
                 : "+f"(c[0]), "+f"(c[1]), "+f"(c[2]), "+f"(c[3]) \
                 : "r"(a[0]), "r"(a[1]), "r"(a[2]), "r"(a[3]), \
                   "r"(b[0]), "r"(b[1]))

// ================= TF32 tensor-core GEMM (unchanged from R2) =================
#define TBM 128
#define TBN 128
#define TBK 32
#define ASTR 36
#define BSTR 136
#define ABUF (TBM*ASTR)
#define BBUF (TBK*BSTR)
#define TG_SMEM_BYTES ((2*ABUF + 2*BBUF) * 4)

__global__ __launch_bounds__(256) void tgemm(const float* __restrict__ A,
                                             const float* __restrict__ B,
                                             float* __restrict__ C,
                                             int M, int N, int K) {
    extern __shared__ float sm[];
    float* sA = sm;
    float* sB = sm + 2 * ABUF;
    uint32_t sA_u = (uint32_t)__cvta_generic_to_shared(sA);
    uint32_t sB_u = (uint32_t)__cvta_generic_to_shared(sB);

    int tid = threadIdx.x;
    int warp = tid >> 5, lane = tid & 31;
    int g = lane >> 2, t = lane & 3;
    int wrow = (warp >> 2) * 64;
    int wcol = (warp & 3) * 32;
    int row0 = blockIdx.y * TBM;
    int col0 = blockIdx.x * TBN;

    float c[4][4][4];
#pragma unroll
    for (int mi = 0; mi < 4; mi++)
#pragma unroll
        for (int ni = 0; ni < 4; ni++)
#pragma unroll
            for (int r = 0; r < 4; r++) c[mi][ni][r] = 0.f;

    int kt_total = K / TBK;
    {
        int k0 = 0;
#pragma unroll
        for (int i = 0; i < 4; i++) {
            int idx = tid + i * 256;
            int r = idx >> 3, c4 = idx & 7;
            cp16(sA_u + (uint32_t)((r * ASTR + c4 * 4) * 4),
                 A + (size_t)(row0 + r) * K + k0 + c4 * 4, true);
        }
#pragma unroll
        for (int i = 0; i < 4; i++) {
            int idx = tid + i * 256;
            int r = idx >> 5, c4 = idx & 31;
            int col = col0 + c4 * 4;
            bool p = col < N;
            const float* src = p ? (B + (size_t)(k0 + r) * N + col) : B;
            cp16(sB_u + (uint32_t)((r * BSTR + c4 * 4) * 4), src, p);
        }
        cp_commit();
    }

    for (int kt = 0; kt < kt_total; kt++) {
        int cur = kt & 1;
        if (kt + 1 < kt_total) {
            int k0 = (kt + 1) * TBK;
            int nb = cur ^ 1;
#pragma unroll
            for (int i = 0; i < 4; i++) {
                int idx = tid + i * 256;
                int r = idx >> 3, c4 = idx & 7;
                cp16(sA_u + (uint32_t)((nb * ABUF + r * ASTR + c4 * 4) * 4),
                     A + (size_t)(row0 + r) * K + k0 + c4 * 4, true);
            }
#pragma unroll
            for (int i = 0; i < 4; i++) {
                int idx = tid + i * 256;
                int r = idx >> 5, c4 = idx & 31;
                int col = col0 + c4 * 4;
                bool p = col < N;
                const float* src = p ? (B + (size_t)(k0 + r) * N + col) : B;
                cp16(sB_u + (uint32_t)((nb * BBUF + r * BSTR + c4 * 4) * 4), src, p);
            }
            cp_commit();
            cp_wait<1>();
        } else {
            cp_wait<0>();
        }
        __syncthreads();

        const float* As = sA + cur * ABUF;
        const float* Bs = sB + cur * BBUF;
#pragma unroll
        for (int k0 = 0; k0 < TBK; k0 += 8) {
            uint32_t a[4][4], b[4][2];
#pragma unroll
            for (int mi = 0; mi < 4; mi++) {
                int r0 = wrow + mi * 16 + g;
                a[mi][0] = f2tf32(As[r0 * ASTR + k0 + t]);
                a[mi][1] = f2tf32(As[(r0 + 8) * ASTR + k0 + t]);
                a[mi][2] = f2tf32(As[r0 * ASTR + k0 + t + 4]);
                a[mi][3] = f2tf32(As[(r0 + 8) * ASTR + k0 + t + 4]);
            }
#pragma unroll
            for (int ni = 0; ni < 4; ni++) {
                int cB = wcol + ni * 8 + g;
                b[ni][0] = f2tf32(Bs[(k0 + t) * BSTR + cB]);
                b[ni][1] = f2tf32(Bs[(k0 + t + 4) * BSTR + cB]);
            }
#pragma unroll
            for (int mi = 0; mi < 4; mi++)
#pragma unroll
                for (int ni = 0; ni < 4; ni++)
                    MMA_TF32(c[mi][ni], a[mi], b[ni]);
        }
        __syncthreads();
    }
#pragma unroll
    for (int mi = 0; mi < 4; mi++) {
#pragma unroll
        for (int ni = 0; ni < 4; ni++) {
            int row = row0 + wrow + mi * 16 + g;
            int col = col0 + wcol + ni * 8 + 2 * t;
            if (col < N) {
                float2 v0 = make_float2(c[mi][ni][0], c[mi][ni][1]);
                float2 v1 = make_float2(c[mi][ni][2], c[mi][ni][3]);
                *reinterpret_cast<float2*>(&C[(size_t)row * N + col]) = v0;
                *reinterpret_cast<float2*>(&C[(size_t)(row + 8) * N + col]) = v1;
            }
        }
    }
}

// ---------------- RMSNorm ----------------
__global__ __launch_bounds__(256) void rmsnorm_kernel(const float* __restrict__ x,
                                                      const float* __restrict__ w,
                                                      float* __restrict__ y,
                                                      int ncols, int xstride, int ystride) {
    int row = blockIdx.x;
    const float* xr = x + (size_t)row * xstride;
    float ss = 0.f;
    for (int c = threadIdx.x; c < ncols; c += blockDim.x) {
        float v = xr[c];
        ss += v * v;
    }
    __shared__ float warp_s[8];
    __shared__ float snorm;
    for (int off = 16; off > 0; off >>= 1) ss += __shfl_down_sync(0xffffffffu, ss, off);
    int lane = threadIdx.x & 31, wid = threadIdx.x >> 5;
    if (lane == 0) warp_s[wid] = ss;
    __syncthreads();
    if (threadIdx.x == 0) {
        float tt = 0.f;
        for (int i = 0; i < (int)(blockDim.x >> 5); i++) tt += warp_s[i];
        snorm = rsqrtf(tt / (float)ncols + EPSV);
    }
    __syncthreads();
    float r = snorm;
    for (int c = threadIdx.x; c < ncols; c += blockDim.x)
        y[(size_t)row * ystride + c] = xr[c] * r * w[c];
}

// ---------------- k_pe RoPE ----------------
__global__ void kpe_rope_kernel(const float* __restrict__ ckv,
                                const float* __restrict__ cosb,
                                const float* __restrict__ sinb,
                                float* __restrict__ kpe) {
    int s = blockIdx.x;
    int d = threadIdx.x;
    const float* base = ckv + (size_t)s * KVA_DIM + CKV_DIM;
    float x = base[d];
    float rot = (d < 16) ? -base[d + 16] : base[d - 16];
    kpe[(size_t)s * RD + d] = x * cosb[(size_t)s * RD + d] + rot * sinb[(size_t)s * RD + d];
}

// ---------------- build per-head Q,K,V (tf32 pre-rounded) ----------------
__global__ void prep_kernel(const float* __restrict__ q,
                            const float* __restrict__ kv,
                            const float* __restrict__ kpe,
                            const float* __restrict__ cosb,
                            const float* __restrict__ sinb,
                            float* __restrict__ Q, float* __restrict__ K,
                            float* __restrict__ V) {
    int s = blockIdx.x;
    int h = blockIdx.y;
    int d = threadIdx.x;
    size_t qbase = (size_t)s * QB_DIM + (size_t)h * DQK;
    size_t kvbase = (size_t)s * KVB_DIM + (size_t)h * 128;
    size_t hs = ((size_t)h * SEQ + s);

    float qv;
    if (d < 64) {
        qv = q[qbase + d];
    } else {
        int i = d - 64;
        float x = q[qbase + 64 + i];
        float rot = (i < 16) ? -q[qbase + 64 + i + 16] : q[qbase + 64 + i - 16];
        qv = x * cosb[(size_t)s * RD + i] + rot * sinb[(size_t)s * RD + i];
    }
    Q[hs * DQK + d] = tf32r(qv * QSCALE);

    float kvv = (d < 64) ? kv[kvbase + d] : kpe[(size_t)s * RD + (d - 64)];
    K[hs * DQK + d] = tf32r(kvv);

    if (d < DV) V[hs * DV + d] = tf32r(kv[kvbase + 64 + d]);
}

// ================= TF32 flash attention =================
// 128 q-rows x 64 keys per tile, 8 warps (4x2), warp tile 32x32.
// smem strides: Q/K 100 (banks 4g+t), V 104 (8t+g), P 68 (4g+t) — conflict-free.
#define FQSTR 100
#define FKSTR 100
#define FVSTR 104
#define FPSTR 68
#define FQS_F (128*FQSTR)          // 12800
#define FKS_F (64*FKSTR)           // 6400 per buffer
#define FVS_F (64*FVSTR)           // 6656 per buffer
#define FPS_F (128*FPSTR)          // 8704
#define FLASH2_SMEM_FLOATS (FQS_F + 2*FKS_F + 2*FVS_F + FPS_F + 256 + 3*128)
#define FLASH2_SMEM_BYTES (FLASH2_SMEM_FLOATS*4)   // 193024

__device__ __forceinline__ void flash_loadKV(const float* __restrict__ Kh,
                                             const float* __restrict__ Vh,
                                             int k0g, uint32_t ks_u, uint32_t vs_u,
                                             int tid) {
#pragma unroll
    for (int i = 0; i < 6; i++) {
        int idx = tid + i * 256;
        int r = idx / 24, c4 = idx % 24;
        cp16(ks_u + (uint32_t)((r * FKSTR + c4 * 4) * 4),
             Kh + (size_t)(k0g + r) * DQK + c4 * 4, true);
    }
#pragma unroll
    for (int i = 0; i < 4; i++) {
        int idx = tid + i * 256;
        int r = idx >> 4, c4 = idx & 15;
        cp16(vs_u + (uint32_t)((r * FVSTR + c4 * 4) * 4),
             Vh + (size_t)(k0g + r) * DV + c4 * 4, true);
    }
}

__global__ __launch_bounds__(256, 1) void flash2(const float* __restrict__ Q,
                                                 const float* __restrict__ K,
                                                 const float* __restrict__ V,
                                                 float* __restrict__ O) {
    extern __shared__ float smf[];
    float* Qs = smf;
    float* Ks = Qs + FQS_F;
    float* Vs = Ks + 2 * FKS_F;
    float* Ps = Vs + 2 * FVS_F;
    float* red = Ps + FPS_F;     // 128*2
    float* mrow = red + 256;
    float* lrow = mrow + 128;
    float* arow = lrow + 128;
    uint32_t ks_u = (uint32_t)__cvta_generic_to_shared(Ks);
    uint32_t vs_u = (uint32_t)__cvta_generic_to_shared(Vs);

    int h = blockIdx.y;
    int qt = (int)gridDim.x - 1 - (int)blockIdx.x;   // long blocks first
    int q0 = qt * 128;
    int tid = threadIdx.x, warp = tid >> 5, lane = tid & 31;
    int g = lane >> 2, t = lane & 3;
    int wrowS = (warp >> 1) * 32, wcol = (warp & 1) * 32, warpcol = warp & 1;
    const float* Qh = Q + (size_t)h * SEQ * DQK;
    const float* Kh = K + (size_t)h * SEQ * DQK;
    const float* Vh = V + (size_t)h * SEQ * DV;

    // load Q tile (128 x 96)
#pragma unroll
    for (int i = 0; i < 12; i++) {
        int idx = tid + i * 256;
        int r = idx / 24, c4 = idx % 24;
        float4 v = *reinterpret_cast<const float4*>(Qh + (size_t)(q0 + r) * DQK + c4 * 4);
        *reinterpret_cast<float4*>(Qs + r * FQSTR + c4 * 4) = v;
    }
    if (tid < 128) { mrow[tid] = -1e30f; lrow[tid] = 0.f; }

    float o[2][4][4];
#pragma unroll
    for (int mi = 0; mi < 2; mi++)
#pragma unroll
        for (int ni = 0; ni < 4; ni++)
#pragma unroll
            for (int r = 0; r < 4; r++) o[mi][ni][r] = 0.f;

    int nkt = 2 * qt + 2;
    flash_loadKV(Kh, Vh, 0, ks_u, vs_u, tid);
    cp_commit();

    for (int kt = 0; kt < nkt; kt++) {
        int cur = kt & 1;
        if (kt + 1 < nkt) {
            int nb = cur ^ 1;
            flash_loadKV(Kh, Vh, (kt + 1) * 64,
                         ks_u + (uint32_t)(nb * FKS_F * 4),
                         vs_u + (uint32_t)(nb * FVS_F * 4), tid);
            cp_commit();
            cp_wait<1>();
        } else {
            cp_wait<0>();
        }
        __syncthreads();

        const float* KsC = Ks + cur * FKS_F;
        const float* VsC = Vs + cur * FVS_F;

        // ---- S = Q K^T ----
        float s[2][4][4];
#pragma unroll
        for (int mi = 0; mi < 2; mi++)
#pragma unroll
            for (int ni = 0; ni < 4; ni++)
#pragma unroll
                for (int r = 0; r < 4; r++) s[mi][ni][r] = 0.f;

#pragma unroll
        for (int k0 = 0; k0 < DQK; k0 += 8) {
            uint32_t a[2][4];
#pragma unroll
            for (int mi = 0; mi < 2; mi++) {
                int r0 = wrowS + mi * 16 + g;
                a[mi][0] = __float_as_uint(Qs[r0 * FQSTR + k0 + t]);
                a[mi][1] = __float_as_uint(Qs[(r0 + 8) * FQSTR + k0 + t]);
                a[mi][2] = __float_as_uint(Qs[r0 * FQSTR + k0 + t + 4]);
                a[mi][3] = __float_as_uint(Qs[(r0 + 8) * FQSTR + k0 + t + 4]);
            }
#pragma unroll
            for (int ni = 0; ni < 4; ni++) {
                uint32_t b[2];
                int cb = wcol + ni * 8 + g;
                b[0] = __float_as_uint(KsC[cb * FKSTR + k0 + t]);
                b[1] = __float_as_uint(KsC[cb * FKSTR + k0 + t + 4]);
                MMA_TF32(s[0][ni], a[0], b);
                MMA_TF32(s[1][ni], a[1], b);
            }
        }

        // ---- causal mask (only on diagonal-overlapping tiles) ----
        int k0g = kt * 64;
        if (k0g + 63 > q0) {
#pragma unroll
            for (int mi = 0; mi < 2; mi++)
#pragma unroll
                for (int ni = 0; ni < 4; ni++) {
                    int col = k0g + wcol + ni * 8 + 2 * t;
                    int row = q0 + wrowS + mi * 16 + g;
                    if (col > row)         s[mi][ni][0] = -1e30f;
                    if (col + 1 > row)     s[mi][ni][1] = -1e30f;
                    if (col > row + 8)     s[mi][ni][2] = -1e30f;
                    if (col + 1 > row + 8) s[mi][ni][3] = -1e30f;
                }
        }

        // ---- row max ----
#pragma unroll
        for (int mi = 0; mi < 2; mi++)
#pragma unroll
            for (int rr = 0; rr < 2; rr++) {
                float v = -1e30f;
#pragma unroll
                for (int ni = 0; ni < 4; ni++)
                    v = fmaxf(v, fmaxf(s[mi][ni][2 * rr], s[mi][ni][2 * rr + 1]));
                v = fmaxf(v, __shfl_xor_sync(0xffffffffu, v, 1));
                v = fmaxf(v, __shfl_xor_sync(0xffffffffu, v, 2));
                if (t == 0)
                    red[(wrowS + mi * 16 + g + 8 * rr) * 2 + warpcol] = v;
            }
        __syncthreads();
        if (tid < 128) {
            float mt = fmaxf(red[2 * tid], red[2 * tid + 1]);
            float mo = mrow[tid];
            float mn = fmaxf(mo, mt);
            float al = __expf(mo - mn);
            mrow[tid] = mn; arow[tid] = al; lrow[tid] *= al;
        }
        __syncthreads();

        // ---- P = exp(S - m); write P^ (tf32) to smem; row sums; rescale O ----
#pragma unroll
        for (int mi = 0; mi < 2; mi++)
#pragma unroll
            for (int rr = 0; rr < 2; rr++) {
                int row = wrowS + mi * 16 + g + 8 * rr;
                float m = mrow[row];
                float al = arow[row];
                float sum = 0.f;
#pragma unroll
                for (int ni = 0; ni < 4; ni++) {
                    float p0 = __expf(s[mi][ni][2 * rr] - m);
                    float p1 = __expf(s[mi][ni][2 * rr + 1] - m);
                    sum += p0 + p1;
                    float2 pv = make_float2(tf32r(p0), tf32r(p1));
                    *reinterpret_cast<float2*>(Ps + row * FPSTR + wcol + ni * 8 + 2 * t) = pv;
                    o[mi][ni][2 * rr] *= al;
                    o[mi][ni][2 * rr + 1] *= al;
                }
                sum += __shfl_xor_sync(0xffffffffu, sum, 1);
                sum += __shfl_xor_sync(0xffffffffu, sum, 2);
                if (t == 0) red[row * 2 + warpcol] = sum;
            }
        __syncthreads();
        if (tid < 128) lrow[tid] += red[2 * tid] + red[2 * tid + 1];

        // ---- O += P V ----
#pragma unroll
        for (int k0 = 0; k0 < 64; k0 += 8) {
            uint32_t a[2][4];
#pragma unroll
            for (int mi = 0; mi < 2; mi++) {
                int r0 = wrowS + mi * 16 + g;
                a[mi][0] = __float_as_uint(Ps[r0 * FPSTR + k0 + t]);
                a[mi][1] = __float_as_uint(Ps[(r0 + 8) * FPSTR + k0 + t]);
                a[mi][2] = __float_as_uint(Ps[r0 * FPSTR + k0 + t + 4]);
                a[mi][3] = __float_as_uint(Ps[(r0 + 8) * FPSTR + k0 + t + 4]);
            }
#pragma unroll
            for (int ni = 0; ni < 4; ni++) {
                uint32_t b[2];
                int cb = wcol + ni * 8 + g;
                b[0] = __float_as_uint(VsC[(k0 + t) * FVSTR + cb]);
                b[1] = __float_as_uint(VsC[(k0 + t + 4) * FVSTR + cb]);
                MMA_TF32(o[0][ni], a[0], b);
                MMA_TF32(o[1][ni], a[1], b);
            }
        }
        __syncthreads();
    }

    // ---- epilogue ----
#pragma unroll
    for (int mi = 0; mi < 2; mi++) {
        int r0 = wrowS + mi * 16 + g;
        float inv0 = 1.f / lrow[r0];
        float inv1 = 1.f / lrow[r0 + 8];
        int gr0 = q0 + r0;
#pragma unroll
        for (int ni = 0; ni < 4; ni++) {
            int col = h * DV + wcol + ni * 8 + 2 * t;
            float2 v0 = make_float2(o[mi][ni][0] * inv0, o[mi][ni][1] * inv0);
            float2 v1 = make_float2(o[mi][ni][2] * inv1, o[mi][ni][3] * inv1);
            *reinterpret_cast<float2*>(O + (size_t)gr0 * (NH * DV) + col) = v0;
            *reinterpret_cast<float2*>(O + (size_t)(gr0 + 8) * (NH * DV) + col) = v1;
        }
    }
}

// ---------------- launch ----------------
extern "C" void kernel_launch(void* const* d_in, const int* in_sizes, int n_in,
                              void* d_out, int out_size) {
    const float* hidden   = (const float*)d_in[0];
    const float* cosb     = (const float*)d_in[1];
    const float* sinb     = (const float*)d_in[2];
    const float* wq_a     = (const float*)d_in[3];
    const float* q_a_ln_w = (const float*)d_in[4];
    const float* wq_b     = (const float*)d_in[5];
    const float* wkv_a    = (const float*)d_in[6];
    const float* kv_a_ln  = (const float*)d_in[7];
    const float* wkv_b    = (const float*)d_in[8];
    const float* wo       = (const float*)d_in[9];
    float* out = (float*)d_out;

    float *qa, *qan, *ckv, *ckvn, *kpe, *q, *kv, *Qp, *Kp, *Vp, *attn;
    cudaGetSymbolAddress((void**)&qa,   g_qa);
    cudaGetSymbolAddress((void**)&qan,  g_qan);
    cudaGetSymbolAddress((void**)&ckv,  g_ckv);
    cudaGetSymbolAddress((void**)&ckvn, g_ckvn);
    cudaGetSymbolAddress((void**)&kpe,  g_kpe);
    cudaGetSymbolAddress((void**)&q,    g_q);
    cudaGetSymbolAddress((void**)&kv,   g_kv);
    cudaGetSymbolAddress((void**)&Qp,   g_Q);
    cudaGetSymbolAddress((void**)&Kp,   g_K);
    cudaGetSymbolAddress((void**)&Vp,   g_V);
    cudaGetSymbolAddress((void**)&attn, g_attn);

    cudaFuncSetAttribute(tgemm, cudaFuncAttributeMaxDynamicSharedMemorySize,
                         TG_SMEM_BYTES);
    cudaFuncSetAttribute(flash2, cudaFuncAttributeMaxDynamicSharedMemorySize,
                         FLASH2_SMEM_BYTES);

    dim3 blk(256);

    tgemm<<<dim3((QA_DIM + TBN - 1) / TBN, SEQ / TBM), blk, TG_SMEM_BYTES>>>(
        hidden, wq_a, qa, SEQ, QA_DIM, HID);
    tgemm<<<dim3((KVA_DIM + TBN - 1) / TBN, SEQ / TBM), blk, TG_SMEM_BYTES>>>(
        hidden, wkv_a, ckv, SEQ, KVA_DIM, HID);
    rmsnorm_kernel<<<SEQ, 256>>>(qa, q_a_ln_w, qan, QA_DIM, QA_DIM, QA_DIM);
    rmsnorm_kernel<<<SEQ, 256>>>(ckv, kv_a_ln, ckvn, CKV_DIM, KVA_DIM, CKV_DIM);
    kpe_rope_kernel<<<SEQ, RD>>>(ckv, cosb, sinb, kpe);
    tgemm<<<dim3(QB_DIM / TBN, SEQ / TBM), blk, TG_SMEM_BYTES>>>(
        qan, wq_b, q, SEQ, QB_DIM, QA_DIM);
    tgemm<<<dim3(KVB_DIM / TBN, SEQ / TBM), blk, TG_SMEM_BYTES>>>(
        ckvn, wkv_b, kv, SEQ, KVB_DIM, CKV_DIM);
    prep_kernel<<<dim3(SEQ, NH), DQK>>>(q, kv, kpe, cosb, sinb, Qp, Kp, Vp);
    flash2<<<dim3(SEQ / 128, NH), blk, FLASH2_SMEM_BYTES>>>(Qp, Kp, Vp, attn);
    tgemm<<<dim3(OUT_DIM / TBN, SEQ / TBM), blk, TG_SMEM_BYTES>>>(
        attn, wo, out, SEQ, OUT_DIM, NH * DV);
}

// round 4
// speedup vs baseline: 4.0291x; 1.1883x over previous
#include <cuda_runtime.h>
#include <math.h>
#include <stdint.h>

// ---------------- problem constants ----------------
#define SEQ 2048
#define HID 2560
#define NH 40
#define DQK 96          // 64 nope + 32 rope
#define DV 64
#define RD 32           // rope dim
#define QA_DIM 768
#define KVA_DIM 288     // 256 ckv + 32 k_pe
#define CKV_DIM 256
#define QB_DIM (NH*DQK)         // 3840
#define KVB_DIM (NH*(64+DV))    // 5120
#define OUT_DIM 2560
#define EPSV 1e-6f
#define QSCALE 0.10206207261596577f   // 96^-0.5

// ---------------- scratch ----------------
__device__ float g_qa0 [SEQ*QA_DIM];
__device__ float g_qa1 [SEQ*QA_DIM];
__device__ float g_qan [SEQ*QA_DIM];
__device__ float g_ckv0[SEQ*KVA_DIM];
__device__ float g_ckv1[SEQ*KVA_DIM];
__device__ float g_ckvn[SEQ*CKV_DIM];
__device__ float g_kpe [SEQ*RD];
__device__ float g_q   [SEQ*QB_DIM];
__device__ float g_kv  [SEQ*KVB_DIM];
__device__ float g_Q   [NH*SEQ*DQK];
__device__ float g_K   [NH*SEQ*DQK];
__device__ float g_V   [NH*SEQ*DV];
__device__ float g_attn[SEQ*NH*DV];
__device__ float g_o1  [SEQ*OUT_DIM];

// ---------------- tf32 helpers ----------------
__device__ __forceinline__ uint32_t f2tf32(float f) {
    uint32_t u;
    asm("cvt.rna.tf32.f32 %0, %1;" : "=r"(u) : "f"(f));
    return u;
}
__device__ __forceinline__ float tf32r(float f) {
    uint32_t u;
    asm("cvt.rna.tf32.f32 %0, %1;" : "=r"(u) : "f"(f));
    return __uint_as_float(u);
}

__device__ __forceinline__ void cp16(uint32_t dst, const void* src, bool pred) {
    int sz = pred ? 16 : 0;
    asm volatile("cp.async.cg.shared.global [%0], [%1], 16, %2;\n"
                 :: "r"(dst), "l"(src), "r"(sz));
}
__device__ __forceinline__ void cp_commit() {
    asm volatile("cp.async.commit_group;\n");
}
template <int N>
__device__ __forceinline__ void cp_wait() {
    asm volatile("cp.async.wait_group %0;\n" :: "n"(N));
}

#define MMA_TF32(c, a, b) \
    asm volatile("mma.sync.aligned.m16n8k8.row.col.f32.tf32.tf32.f32 " \
                 "{%0,%1,%2,%3},{%4,%5,%6,%7},{%8,%9},{%0,%1,%2,%3};" \
                 : "+f"(c[0]), "+f"(c[1]), "+f"(c[2]), "+f"(c[3]) \
                 : "r"(a[0]), "r"(a[1]), "r"(a[2]), "r"(a[3]), \
                   "r"(b[0]), "r"(b[1]))

// ================= multi-problem TF32 GEMM =================
// up to 4 sub-problems in one launch; each C[M,N] = A[M,K]@B[K,N], M=2048.
#define TBM 128
#define TBN 128
#define TBK 32
#define ASTR 36
#define BSTR 136
#define ABUF (TBM*ASTR)
#define BBUF (TBK*BSTR)
#define TG_SMEM_BYTES ((2*ABUF + 2*BBUF) * 4)

struct GP4 {
    const float* A[4];
    const float* B[4];
    float*       C[4];
    int N[4], K[4], lda[4], nbx[4], bstart[4];
    int nprob;
};

__global__ __launch_bounds__(256, 2) void tgemm_multi(GP4 p) {
    extern __shared__ float sm[];
    float* sA = sm;
    float* sB = sm + 2 * ABUF;
    uint32_t sA_u = (uint32_t)__cvta_generic_to_shared(sA);
    uint32_t sB_u = (uint32_t)__cvta_generic_to_shared(sB);

    int bid = blockIdx.x;
    int pi = 0;
#pragma unroll
    for (int i = 1; i < 4; i++)
        if (i < p.nprob && bid >= p.bstart[i]) pi = i;
    const float* A = p.A[pi];
    const float* B = p.B[pi];
    float* C = p.C[pi];
    int N = p.N[pi], K = p.K[pi], lda = p.lda[pi];
    int l = bid - p.bstart[pi];
    int bx = l % p.nbx[pi];
    int by = l / p.nbx[pi];
    int row0 = by * TBM;
    int col0 = bx * TBN;

    int tid = threadIdx.x;
    int warp = tid >> 5, lane = tid & 31;
    int g = lane >> 2, t = lane & 3;
    int wrow = (warp >> 2) * 64;
    int wcol = (warp & 3) * 32;

    float c[4][4][4];
#pragma unroll
    for (int mi = 0; mi < 4; mi++)
#pragma unroll
        for (int ni = 0; ni < 4; ni++)
#pragma unroll
            for (int r = 0; r < 4; r++) c[mi][ni][r] = 0.f;

    int kt_total = K / TBK;
    {
#pragma unroll
        for (int i = 0; i < 4; i++) {
            int idx = tid + i * 256;
            int r = idx >> 3, c4 = idx & 7;
            cp16(sA_u + (uint32_t)((r * ASTR + c4 * 4) * 4),
                 A + (size_t)(row0 + r) * lda + c4 * 4, true);
        }
#pragma unroll
        for (int i = 0; i < 4; i++) {
            int idx = tid + i * 256;
            int r = idx >> 5, c4 = idx & 31;
            int col = col0 + c4 * 4;
            bool pr = col < N;
            const float* src = pr ? (B + (size_t)r * N + col) : B;
            cp16(sB_u + (uint32_t)((r * BSTR + c4 * 4) * 4), src, pr);
        }
        cp_commit();
    }

    for (int kt = 0; kt < kt_total; kt++) {
        int cur = kt & 1;
        if (kt + 1 < kt_total) {
            int k0 = (kt + 1) * TBK;
            int nb = cur ^ 1;
#pragma unroll
            for (int i = 0; i < 4; i++) {
                int idx = tid + i * 256;
                int r = idx >> 3, c4 = idx & 7;
                cp16(sA_u + (uint32_t)((nb * ABUF + r * ASTR + c4 * 4) * 4),
                     A + (size_t)(row0 + r) * lda + k0 + c4 * 4, true);
            }
#pragma unroll
            for (int i = 0; i < 4; i++) {
                int idx = tid + i * 256;
                int r = idx >> 5, c4 = idx & 31;
                int col = col0 + c4 * 4;
                bool pr = col < N;
                const float* src = pr ? (B + (size_t)(k0 + r) * N + col) : B;
                cp16(sB_u + (uint32_t)((nb * BBUF + r * BSTR + c4 * 4) * 4), src, pr);
            }
            cp_commit();
            cp_wait<1>();
        } else {
            cp_wait<0>();
        }
        __syncthreads();

        const float* As = sA + cur * ABUF;
        const float* Bs = sB + cur * BBUF;
#pragma unroll
        for (int k0 = 0; k0 < TBK; k0 += 8) {
            uint32_t a[4][4], b[4][2];
#pragma unroll
            for (int mi = 0; mi < 4; mi++) {
                int r0 = wrow + mi * 16 + g;
                a[mi][0] = f2tf32(As[r0 * ASTR + k0 + t]);
                a[mi][1] = f2tf32(As[(r0 + 8) * ASTR + k0 + t]);
                a[mi][2] = f2tf32(As[r0 * ASTR + k0 + t + 4]);
                a[mi][3] = f2tf32(As[(r0 + 8) * ASTR + k0 + t + 4]);
            }
#pragma unroll
            for (int ni = 0; ni < 4; ni++) {
                int cB = wcol + ni * 8 + g;
                b[ni][0] = f2tf32(Bs[(k0 + t) * BSTR + cB]);
                b[ni][1] = f2tf32(Bs[(k0 + t + 4) * BSTR + cB]);
            }
#pragma unroll
            for (int mi = 0; mi < 4; mi++)
#pragma unroll
                for (int ni = 0; ni < 4; ni++)
                    MMA_TF32(c[mi][ni], a[mi], b[ni]);
        }
        __syncthreads();
    }
#pragma unroll
    for (int mi = 0; mi < 4; mi++) {
#pragma unroll
        for (int ni = 0; ni < 4; ni++) {
            int row = row0 + wrow + mi * 16 + g;
            int col = col0 + wcol + ni * 8 + 2 * t;
            if (col < N) {
                float2 v0 = make_float2(c[mi][ni][0], c[mi][ni][1]);
                float2 v1 = make_float2(c[mi][ni][2], c[mi][ni][3]);
                *reinterpret_cast<float2*>(&C[(size_t)row * N + col]) = v0;
                *reinterpret_cast<float2*>(&C[(size_t)(row + 8) * N + col]) = v1;
            }
        }
    }
}

// ---------------- fused: add split-K halves + rmsnorm(q), rmsnorm(ckv), rope(k_pe) ----------------
__global__ __launch_bounds__(256) void norm_rope(
    const float* __restrict__ qa0, const float* __restrict__ qa1,
    const float* __restrict__ qw,
    const float* __restrict__ ckv0, const float* __restrict__ ckv1,
    const float* __restrict__ kvw,
    const float* __restrict__ cosb, const float* __restrict__ sinb,
    float* __restrict__ qan, float* __restrict__ ckvn, float* __restrict__ kpe) {
    int s = blockIdx.x;
    int tid = threadIdx.x;
    int lane = tid & 31, wid = tid >> 5;
    __shared__ float warp_s[8];
    __shared__ float snorm;

    // --- q rmsnorm over 768 cols ---
    float v[3];
    float ss = 0.f;
#pragma unroll
    for (int i = 0; i < 3; i++) {
        int c = tid + i * 256;
        v[i] = qa0[(size_t)s * QA_DIM + c] + qa1[(size_t)s * QA_DIM + c];
        ss += v[i] * v[i];
    }
    for (int off = 16; off > 0; off >>= 1) ss += __shfl_down_sync(0xffffffffu, ss, off);
    if (lane == 0) warp_s[wid] = ss;
    __syncthreads();
    if (tid == 0) {
        float tt = 0.f;
#pragma unroll
        for (int i = 0; i < 8; i++) tt += warp_s[i];
        snorm = rsqrtf(tt / (float)QA_DIM + EPSV);
    }
    __syncthreads();
    float r = snorm;
#pragma unroll
    for (int i = 0; i < 3; i++) {
        int c = tid + i * 256;
        qan[(size_t)s * QA_DIM + c] = v[i] * r * qw[c];
    }
    __syncthreads();

    // --- ckv rmsnorm over 256 cols ---
    float w = ckv0[(size_t)s * KVA_DIM + tid] + ckv1[(size_t)s * KVA_DIM + tid];
    float ss2 = w * w;
    for (int off = 16; off > 0; off >>= 1) ss2 += __shfl_down_sync(0xffffffffu, ss2, off);
    if (lane == 0) warp_s[wid] = ss2;
    __syncthreads();
    if (tid == 0) {
        float tt = 0.f;
#pragma unroll
        for (int i = 0; i < 8; i++) tt += warp_s[i];
        snorm = rsqrtf(tt / (float)CKV_DIM + EPSV);
    }
    __syncthreads();
    ckvn[(size_t)s * CKV_DIM + tid] = w * snorm * kvw[tid];

    // --- rope on k_pe (32 cols) ---
    if (tid < RD) {
        size_t base = (size_t)s * KVA_DIM + CKV_DIM;
        float x = ckv0[base + tid] + ckv1[base + tid];
        int pp = (tid < 16) ? tid + 16 : tid - 16;
        float xr = ckv0[base + pp] + ckv1[base + pp];
        float rot = (tid < 16) ? -xr : xr;
        kpe[(size_t)s * RD + tid] = x * cosb[(size_t)s * RD + tid]
                                  + rot * sinb[(size_t)s * RD + tid];
    }
}

// ---------------- build per-head Q,K,V (tf32 pre-rounded) ----------------
__global__ void prep_kernel(const float* __restrict__ q,
                            const float* __restrict__ kv,
                            const float* __restrict__ kpe,
                            const float* __restrict__ cosb,
                            const float* __restrict__ sinb,
                            float* __restrict__ Q, float* __restrict__ K,
                            float* __restrict__ V) {
    int s = blockIdx.x;
    int h = blockIdx.y;
    int d = threadIdx.x;
    size_t qbase = (size_t)s * QB_DIM + (size_t)h * DQK;
    size_t kvbase = (size_t)s * KVB_DIM + (size_t)h * 128;
    size_t hs = ((size_t)h * SEQ + s);

    float qv;
    if (d < 64) {
        qv = q[qbase + d];
    } else {
        int i = d - 64;
        float x = q[qbase + 64 + i];
        float rot = (i < 16) ? -q[qbase + 64 + i + 16] : q[qbase + 64 + i - 16];
        qv = x * cosb[(size_t)s * RD + i] + rot * sinb[(size_t)s * RD + i];
    }
    Q[hs * DQK + d] = tf32r(qv * QSCALE);

    float kvv = (d < 64) ? kv[kvbase + d] : kpe[(size_t)s * RD + (d - 64)];
    K[hs * DQK + d] = tf32r(kvv);

    if (d < DV) V[hs * DV + d] = tf32r(kv[kvbase + 64 + d]);
}

// ================= TF32 flash attention (warp-per-16-rows) =================
// 128 q-rows x 64 keys. 8 warps, warp w owns rows [16w,16w+16), full key span.
// Softmax stats in registers (quad shfl). One __syncthreads per K-tile.
#define FQSTR 100
#define FKSTR 100
#define FVSTR 104
#define FPSTR 68
#define FQS_F (128*FQSTR)
#define FKS_F (64*FKSTR)
#define FVS_F (64*FVSTR)
#define FPS_F (128*FPSTR)
#define FLASH3_SMEM_FLOATS (FQS_F + 2*FKS_F + 2*FVS_F + FPS_F)
#define FLASH3_SMEM_BYTES (FLASH3_SMEM_FLOATS*4)   // 190464

__device__ __forceinline__ void flash_loadKV(const float* __restrict__ Kh,
                                             const float* __restrict__ Vh,
                                             int k0g, uint32_t ks_u, uint32_t vs_u,
                                             int tid) {
#pragma unroll
    for (int i = 0; i < 6; i++) {
        int idx = tid + i * 256;
        int r = idx / 24, c4 = idx % 24;
        cp16(ks_u + (uint32_t)((r * FKSTR + c4 * 4) * 4),
             Kh + (size_t)(k0g + r) * DQK + c4 * 4, true);
    }
#pragma unroll
    for (int i = 0; i < 4; i++) {
        int idx = tid + i * 256;
        int r = idx >> 4, c4 = idx & 15;
        cp16(vs_u + (uint32_t)((r * FVSTR + c4 * 4) * 4),
             Vh + (size_t)(k0g + r) * DV + c4 * 4, true);
    }
}

__global__ __launch_bounds__(256, 1) void flash3(const float* __restrict__ Q,
                                                 const float* __restrict__ K,
                                                 const float* __restrict__ V,
                                                 float* __restrict__ O) {
    extern __shared__ float smf[];
    float* Qs = smf;
    float* Ks = Qs + FQS_F;
    float* Vs = Ks + 2 * FKS_F;
    float* Ps = Vs + 2 * FVS_F;
    uint32_t ks_u = (uint32_t)__cvta_generic_to_shared(Ks);
    uint32_t vs_u = (uint32_t)__cvta_generic_to_shared(Vs);

    int h = blockIdx.y;
    int qt = (int)gridDim.x - 1 - (int)blockIdx.x;   // long blocks first
    int q0 = qt * 128;
    int tid = threadIdx.x, warp = tid >> 5, lane = tid & 31;
    int g = lane >> 2, t = lane & 3;
    int r0 = warp * 16 + g;          // own rows r0, r0+8
    const float* Qh = Q + (size_t)h * SEQ * DQK;
    const float* Kh = K + (size_t)h * SEQ * DQK;
    const float* Vh = V + (size_t)h * SEQ * DV;

    // load Q tile (128 x 96)
#pragma unroll
    for (int i = 0; i < 12; i++) {
        int idx = tid + i * 256;
        int r = idx / 24, c4 = idx % 24;
        float4 v = *reinterpret_cast<const float4*>(Qh + (size_t)(q0 + r) * DQK + c4 * 4);
        *reinterpret_cast<float4*>(Qs + r * FQSTR + c4 * 4) = v;
    }

    float m0 = -1e30f, m1 = -1e30f, l0 = 0.f, l1 = 0.f;
    float o[8][4];
#pragma unroll
    for (int ni = 0; ni < 8; ni++)
#pragma unroll
        for (int r = 0; r < 4; r++) o[ni][r] = 0.f;

    int nkt = 2 * qt + 2;
    flash_loadKV(Kh, Vh, 0, ks_u, vs_u, tid);
    cp_commit();

    for (int kt = 0; kt < nkt; kt++) {
        int cur = kt & 1;
        if (kt + 1 < nkt) {
            int nb = cur ^ 1;
            flash_loadKV(Kh, Vh, (kt + 1) * 64,
                         ks_u + (uint32_t)(nb * FKS_F * 4),
                         vs_u + (uint32_t)(nb * FVS_F * 4), tid);
            cp_commit();
            cp_wait<1>();
        } else {
            cp_wait<0>();
        }
        __syncthreads();

        const float* KsC = Ks + cur * FKS_F;
        const float* VsC = Vs + cur * FVS_F;

        // ---- S = Q K^T ---- (16 rows x 64 cols per warp)
        float s[8][4];
#pragma unroll
        for (int ni = 0; ni < 8; ni++)
#pragma unroll
            for (int r = 0; r < 4; r++) s[ni][r] = 0.f;

#pragma unroll
        for (int k0 = 0; k0 < DQK; k0 += 8) {
            uint32_t a[4];
            a[0] = __float_as_uint(Qs[r0 * FQSTR + k0 + t]);
            a[1] = __float_as_uint(Qs[(r0 + 8) * FQSTR + k0 + t]);
            a[2] = __float_as_uint(Qs[r0 * FQSTR + k0 + t + 4]);
            a[3] = __float_as_uint(Qs[(r0 + 8) * FQSTR + k0 + t + 4]);
#pragma unroll
            for (int ni = 0; ni < 8; ni++) {
                uint32_t b[2];
                int cb = ni * 8 + g;
                b[0] = __float_as_uint(KsC[cb * FKSTR + k0 + t]);
                b[1] = __float_as_uint(KsC[cb * FKSTR + k0 + t + 4]);
                MMA_TF32(s[ni], a, b);
            }
        }

        // ---- causal mask ----
        int k0g = kt * 64;
        if (k0g + 63 > q0) {
            int rg = q0 + r0;
#pragma unroll
            for (int ni = 0; ni < 8; ni++) {
                int col = k0g + ni * 8 + 2 * t;
                if (col > rg)         s[ni][0] = -1e30f;
                if (col + 1 > rg)     s[ni][1] = -1e30f;
                if (col > rg + 8)     s[ni][2] = -1e30f;
                if (col + 1 > rg + 8) s[ni][3] = -1e30f;
            }
        }

        // ---- row max (quad-local) ----
        float mx0 = -1e30f, mx1 = -1e30f;
#pragma unroll
        for (int ni = 0; ni < 8; ni++) {
            mx0 = fmaxf(mx0, fmaxf(s[ni][0], s[ni][1]));
            mx1 = fmaxf(mx1, fmaxf(s[ni][2], s[ni][3]));
        }
        mx0 = fmaxf(mx0, __shfl_xor_sync(0xffffffffu, mx0, 1));
        mx0 = fmaxf(mx0, __shfl_xor_sync(0xffffffffu, mx0, 2));
        mx1 = fmaxf(mx1, __shfl_xor_sync(0xffffffffu, mx1, 1));
        mx1 = fmaxf(mx1, __shfl_xor_sync(0xffffffffu, mx1, 2));

        float mn0 = fmaxf(m0, mx0), mn1 = fmaxf(m1, mx1);
        float al0 = __expf(m0 - mn0), al1 = __expf(m1 - mn1);
        m0 = mn0; m1 = mn1;
        l0 *= al0; l1 *= al1;

        // ---- P = exp(S-m), write tf32 P to own rows; rescale O ----
        float sum0 = 0.f, sum1 = 0.f;
#pragma unroll
        for (int ni = 0; ni < 8; ni++) {
            float p0 = __expf(s[ni][0] - m0);
            float p1 = __expf(s[ni][1] - m0);
            float p2 = __expf(s[ni][2] - m1);
            float p3 = __expf(s[ni][3] - m1);
            sum0 += p0 + p1;
            sum1 += p2 + p3;
            *reinterpret_cast<float2*>(Ps + r0 * FPSTR + ni * 8 + 2 * t) =
                make_float2(tf32r(p0), tf32r(p1));
            *reinterpret_cast<float2*>(Ps + (r0 + 8) * FPSTR + ni * 8 + 2 * t) =
                make_float2(tf32r(p2), tf32r(p3));
            o[ni][0] *= al0; o[ni][1] *= al0;
            o[ni][2] *= al1; o[ni][3] *= al1;
        }
        sum0 += __shfl_xor_sync(0xffffffffu, sum0, 1);
        sum0 += __shfl_xor_sync(0xffffffffu, sum0, 2);
        sum1 += __shfl_xor_sync(0xffffffffu, sum1, 1);
        sum1 += __shfl_xor_sync(0xffffffffu, sum1, 2);
        l0 += sum0; l1 += sum1;

        // ---- O += P V (own rows only -> no barrier) ----
#pragma unroll
        for (int k0 = 0; k0 < 64; k0 += 8) {
            uint32_t a[4];
            a[0] = __float_as_uint(Ps[r0 * FPSTR + k0 + t]);
            a[1] = __float_as_uint(Ps[(r0 + 8) * FPSTR + k0 + t]);
            a[2] = __float_as_uint(Ps[r0 * FPSTR + k0 + t + 4]);
            a[3] = __float_as_uint(Ps[(r0 + 8) * FPSTR + k0 + t + 4]);
#pragma unroll
            for (int ni = 0; ni < 8; ni++) {
                uint32_t b[2];
                int cb = ni * 8 + g;
                b[0] = __float_as_uint(VsC[(k0 + t) * FVSTR + cb]);
                b[1] = __float_as_uint(VsC[(k0 + t + 4) * FVSTR + cb]);
                MMA_TF32(o[ni], a, b);
            }
        }
        __syncthreads();   // cur K/V consumed; next iter may overwrite it
    }

    // ---- epilogue ----
    float inv0 = 1.f / l0, inv1 = 1.f / l1;
    int gr = q0 + r0;
#pragma unroll
    for (int ni = 0; ni < 8; ni++) {
        int col = h * DV + ni * 8 + 2 * t;
        *reinterpret_cast<float2*>(O + (size_t)gr * (NH * DV) + col) =
            make_float2(o[ni][0] * inv0, o[ni][1] * inv0);
        *reinterpret_cast<float2*>(O + (size_t)(gr + 8) * (NH * DV) + col) =
            make_float2(o[ni][2] * inv1, o[ni][3] * inv1);
    }
}

// ---------------- split-K final add ----------------
__global__ __launch_bounds__(256) void add_kernel(float* __restrict__ out,
                                                  const float* __restrict__ o1) {
    int i = (blockIdx.x * 256 + threadIdx.x) * 4;
    float4 a = *reinterpret_cast<float4*>(out + i);
    float4 b = *reinterpret_cast<const float4*>(o1 + i);
    a.x += b.x; a.y += b.y; a.z += b.z; a.w += b.w;
    *reinterpret_cast<float4*>(out + i) = a;
}

// ---------------- launch ----------------
extern "C" void kernel_launch(void* const* d_in, const int* in_sizes, int n_in,
                              void* d_out, int out_size) {
    const float* hidden   = (const float*)d_in[0];
    const float* cosb     = (const float*)d_in[1];
    const float* sinb     = (const float*)d_in[2];
    const float* wq_a     = (const float*)d_in[3];
    const float* q_a_ln_w = (const float*)d_in[4];
    const float* wq_b     = (const float*)d_in[5];
    const float* wkv_a    = (const float*)d_in[6];
    const float* kv_a_ln  = (const float*)d_in[7];
    const float* wkv_b    = (const float*)d_in[8];
    const float* wo       = (const float*)d_in[9];
    float* out = (float*)d_out;

    float *qa0, *qa1, *qan, *ckv0, *ckv1, *ckvn, *kpe, *q, *kv, *Qp, *Kp, *Vp, *attn, *o1;
    cudaGetSymbolAddress((void**)&qa0,  g_qa0);
    cudaGetSymbolAddress((void**)&qa1,  g_qa1);
    cudaGetSymbolAddress((void**)&qan,  g_qan);
    cudaGetSymbolAddress((void**)&ckv0, g_ckv0);
    cudaGetSymbolAddress((void**)&ckv1, g_ckv1);
    cudaGetSymbolAddress((void**)&ckvn, g_ckvn);
    cudaGetSymbolAddress((void**)&kpe,  g_kpe);
    cudaGetSymbolAddress((void**)&q,    g_q);
    cudaGetSymbolAddress((void**)&kv,   g_kv);
    cudaGetSymbolAddress((void**)&Qp,   g_Q);
    cudaGetSymbolAddress((void**)&Kp,   g_K);
    cudaGetSymbolAddress((void**)&Vp,   g_V);
    cudaGetSymbolAddress((void**)&attn, g_attn);
    cudaGetSymbolAddress((void**)&o1,   g_o1);

    cudaFuncSetAttribute(tgemm_multi, cudaFuncAttributeMaxDynamicSharedMemorySize,
                         TG_SMEM_BYTES);
    cudaFuncSetAttribute(flash3, cudaFuncAttributeMaxDynamicSharedMemorySize,
                         FLASH3_SMEM_BYTES);

    dim3 blk(256);
    const int KH = HID / 2;   // 1280 split-K halves

    // 1) merged split-K GEMM: hidden@wq_a (2 halves) + hidden@wkv_a (2 halves)
    {
        GP4 p;
        p.nprob = 4;
        p.A[0] = hidden;      p.B[0] = wq_a;                    p.C[0] = qa0;
        p.N[0] = QA_DIM;  p.K[0] = KH; p.lda[0] = HID; p.nbx[0] = QA_DIM / TBN;
        p.A[1] = hidden + KH; p.B[1] = wq_a + (size_t)KH * QA_DIM; p.C[1] = qa1;
        p.N[1] = QA_DIM;  p.K[1] = KH; p.lda[1] = HID; p.nbx[1] = QA_DIM / TBN;
        p.A[2] = hidden;      p.B[2] = wkv_a;                   p.C[2] = ckv0;
        p.N[2] = KVA_DIM; p.K[2] = KH; p.lda[2] = HID; p.nbx[2] = (KVA_DIM + TBN - 1) / TBN;
        p.A[3] = hidden + KH; p.B[3] = wkv_a + (size_t)KH * KVA_DIM; p.C[3] = ckv1;
        p.N[3] = KVA_DIM; p.K[3] = KH; p.lda[3] = HID; p.nbx[3] = (KVA_DIM + TBN - 1) / TBN;
        int nb0 = p.nbx[0] * (SEQ / TBM);
        int nb2 = p.nbx[2] * (SEQ / TBM);
        p.bstart[0] = 0;
        p.bstart[1] = nb0;
        p.bstart[2] = 2 * nb0;
        p.bstart[3] = 2 * nb0 + nb2;
        int total = 2 * nb0 + 2 * nb2;
        tgemm_multi<<<total, blk, TG_SMEM_BYTES>>>(p);
    }
    // 2) fused norms + rope
    norm_rope<<<SEQ, 256>>>(qa0, qa1, q_a_ln_w, ckv0, ckv1, kv_a_ln,
                            cosb, sinb, qan, ckvn, kpe);
    // 3) merged up-projections: qan@wq_b + ckvn@wkv_b
    {
        GP4 p;
        p.nprob = 2;
        p.A[0] = qan;  p.B[0] = wq_b;  p.C[0] = q;
        p.N[0] = QB_DIM;  p.K[0] = QA_DIM; p.lda[0] = QA_DIM; p.nbx[0] = QB_DIM / TBN;
        p.A[1] = ckvn; p.B[1] = wkv_b; p.C[1] = kv;
        p.N[1] = KVB_DIM; p.K[1] = CKV_DIM; p.lda[1] = CKV_DIM; p.nbx[1] = KVB_DIM / TBN;
        p.A[2] = qan; p.B[2] = wq_b; p.C[2] = q;
        p.N[2] = QB_DIM; p.K[2] = QA_DIM; p.lda[2] = QA_DIM; p.nbx[2] = 1;
        p.A[3] = p.A[2]; p.B[3] = p.B[2]; p.C[3] = p.C[2];
        p.N[3] = p.N[2]; p.K[3] = p.K[2]; p.lda[3] = p.lda[2]; p.nbx[3] = 1;
        int nb0 = p.nbx[0] * (SEQ / TBM);
        int nb1 = p.nbx[1] * (SEQ / TBM);
        p.bstart[0] = 0;
        p.bstart[1] = nb0;
        p.bstart[2] = nb0 + nb1;
        p.bstart[3] = nb0 + nb1;
        tgemm_multi<<<nb0 + nb1, blk, TG_SMEM_BYTES>>>(p);
    }
    // 4) assemble per-head Q (roped, scaled), K, V
    prep_kernel<<<dim3(SEQ, NH), DQK>>>(q, kv, kpe, cosb, sinb, Qp, Kp, Vp);
    // 5) causal flash attention
    flash3<<<dim3(SEQ / 128, NH), blk, FLASH3_SMEM_BYTES>>>(Qp, Kp, Vp, attn);
    // 6) attn @ wo, split-K x2
    {
        const int KW = (NH * DV) / 2;    // 1280
        GP4 p;
        p.nprob = 2;
        p.A[0] = attn;      p.B[0] = wo;                        p.C[0] = out;
        p.N[0] = OUT_DIM; p.K[0] = KW; p.lda[0] = NH * DV; p.nbx[0] = OUT_DIM / TBN;
        p.A[1] = attn + KW; p.B[1] = wo + (size_t)KW * OUT_DIM; p.C[1] = o1;
        p.N[1] = OUT_DIM; p.K[1] = KW; p.lda[1] = NH * DV; p.nbx[1] = OUT_DIM / TBN;
        p.A[2] = p.A[0]; p.B[2] = p.B[0]; p.C[2] = p.C[0];
        p.N[2] = p.N[0]; p.K[2] = p.K[0]; p.lda[2] = p.lda[0]; p.nbx[2] = 1;
        p.A[3] = p.A[0]; p.B[3] = p.B[0]; p.C[3] = p.C[0];
        p.N[3] = p.N[0]; p.K[3] = p.K[0]; p.lda[3] = p.lda[0]; p.nbx[3] = 1;
        int nb = p.nbx[0] * (SEQ / TBM);
        p.bstart[0] = 0;
        p.bstart[1] = nb;
        p.bstart[2] = 2 * nb;
        p.bstart[3] = 2 * nb;
        tgemm_multi<<<2 * nb, blk, TG_SMEM_BYTES>>>(p);
    }
    // 7) out += o1
    add_kernel<<<(SEQ * OUT_DIM) / (256 * 4), blk>>>(out, o1);
}

// round 6
// speedup vs baseline: 6.7264x; 1.6695x over previous
#include <cuda_runtime.h>
#include <cuda_fp16.h>
#include <math.h>
#include <stdint.h>

// ---------------- problem constants ----------------
#define SEQ 2048
#define HID 2560
#define NH 40
#define DQK 96
#define DV 64
#define RD 32
#define QA_DIM 768
#define KVA_DIM 288
#define CKV_DIM 256
#define QB_DIM (NH*DQK)         // 3840
#define KVB_DIM (NH*(64+DV))    // 5120
#define OUT_DIM 2560
#define EPSV 1e-6f
// 96^-0.5 * log2(e)  (scores computed in log2 domain; softmax uses ex2)
#define QSCALE_L2E 0.14724602233502312f

// ---------------- scratch ----------------
__device__ float  g_qa0 [SEQ*QA_DIM];
__device__ float  g_qa1 [SEQ*QA_DIM];
__device__ float  g_ckv0[SEQ*KVA_DIM];
__device__ float  g_ckv1[SEQ*KVA_DIM];
__device__ float  g_kpe [SEQ*RD];
__device__ float  g_q   [SEQ*QB_DIM];
__device__ float  g_kv  [SEQ*KVB_DIM];
__device__ float  g_o1  [SEQ*OUT_DIM];
// half operands
__device__ __half g_hidh[SEQ*HID];
__device__ __half g_wqaT[QA_DIM*HID];      // [N][K]
__device__ __half g_wkvaT[KVA_DIM*HID];
__device__ __half g_wqbT[QB_DIM*QA_DIM];
__device__ __half g_wkvbT[KVB_DIM*CKV_DIM];
__device__ __half g_woT [OUT_DIM*(NH*DV)];
__device__ __half g_qan [SEQ*QA_DIM];
__device__ __half g_ckvn[SEQ*CKV_DIM];
__device__ __half g_Q   [NH*SEQ*DQK];
__device__ __half g_K   [NH*SEQ*DQK];
__device__ __half g_Vt  [NH*DV*SEQ];       // [h*64+d][s]
__device__ __half g_attn[SEQ*NH*DV];

// ---------------- helpers ----------------
__device__ __forceinline__ float ex2f(float x) {
    float r;
    asm("ex2.approx.ftz.f32 %0, %1;" : "=f"(r) : "f"(x));
    return r;
}
__device__ __forceinline__ void cp16(uint32_t dst, const void* src, bool pred) {
    int sz = pred ? 16 : 0;
    asm volatile("cp.async.cg.shared.global [%0], [%1], 16, %2;\n"
                 :: "r"(dst), "l"(src), "r"(sz));
}
__device__ __forceinline__ void cp_commit() {
    asm volatile("cp.async.commit_group;\n");
}
template <int N>
__device__ __forceinline__ void cp_wait() {
    asm volatile("cp.async.wait_group %0;\n" :: "n"(N));
}

#define MMA_F16(c, a, b) \
    asm volatile("mma.sync.aligned.m16n8k16.row.col.f32.f16.f16.f32 " \
                 "{%0,%1,%2,%3},{%4,%5,%6,%7},{%8,%9},{%0,%1,%2,%3};" \
                 : "+f"(c[0]), "+f"(c[1]), "+f"(c[2]), "+f"(c[3]) \
                 : "r"(a[0]), "r"(a[1]), "r"(a[2]), "r"(a[3]), \
                   "r"(b[0]), "r"(b[1]))

__device__ __forceinline__ uint32_t ldh2(const __half* p) {
    return *reinterpret_cast<const uint32_t*>(p);
}

// ================= convert / transpose pass =================
// Problems 0..4: src fp32 [K][N] -> dst half [N][K] (64x64 tiles via smem)
// Problem 5: straight fp32 -> half copy (hidden)
struct CV6 {
    const float* src[6];
    __half* dst[6];
    int K[6], N[6];     // straight: K*N total in [K], N unused
    int nbx[6];         // tiles along N (transpose) ; unused straight
    int bstart[7];
    int trans[6];
};
__global__ __launch_bounds__(256) void convtrans(CV6 p) {
    __shared__ __half sm[64 * 72];
    int bid = blockIdx.x;
    int pi = 0;
#pragma unroll
    for (int i = 1; i < 6; i++) if (bid >= p.bstart[i]) pi = i;
    int l = bid - p.bstart[pi];
    int tid = threadIdx.x;
    if (p.trans[pi]) {
        int K = p.K[pi], N = p.N[pi];
        int k0 = (l / p.nbx[pi]) * 64;
        int n0 = (l % p.nbx[pi]) * 64;
        const float* src = p.src[pi];
#pragma unroll
        for (int i = 0; i < 4; i++) {
            int idx = tid + i * 256;             // 0..1023
            int r = idx >> 4, c4 = idx & 15;     // row k, col-chunk
            int n = n0 + c4 * 4;
            if (n < N) {
                float4 v = *reinterpret_cast<const float4*>(
                    &src[(size_t)(k0 + r) * N + n]);
                sm[(c4 * 4 + 0) * 72 + r] = __float2half_rn(v.x);
                sm[(c4 * 4 + 1) * 72 + r] = __float2half_rn(v.y);
                sm[(c4 * 4 + 2) * 72 + r] = __float2half_rn(v.z);
                sm[(c4 * 4 + 3) * 72 + r] = __float2half_rn(v.w);
            }
        }
        __syncthreads();
        __half* dst = p.dst[pi];
#pragma unroll
        for (int i = 0; i < 2; i++) {
            int idx = tid + i * 256;             // 0..511
            int rr = idx >> 3, cc = idx & 7;
            if (n0 + rr < N) {
                uint4 v = *reinterpret_cast<const uint4*>(&sm[rr * 72 + cc * 8]);
                *reinterpret_cast<uint4*>(
                    &dst[(size_t)(n0 + rr) * K + k0 + cc * 8]) = v;
            }
        }
    } else {
        const float* src = p.src[pi];
        __half* dst = p.dst[pi];
        int base = l * 4096;
#pragma unroll
        for (int i = 0; i < 4; i++) {
            int e = base + (tid + i * 256) * 4;
            float4 v = *reinterpret_cast<const float4*>(&src[e]);
            __half2 h0 = __floats2half2_rn(v.x, v.y);
            __half2 h1 = __floats2half2_rn(v.z, v.w);
            *reinterpret_cast<__half2*>(&dst[e]) = h0;
            *reinterpret_cast<__half2*>(&dst[e + 2]) = h1;
        }
    }
}

// ================= multi-problem FP16 GEMM =================
// C[M,N] = A[M,K] @ B[K,N]; A half row-major (lda), B given TRANSPOSED half
// BT[N][K] (ldb). Tile 128x128x32, double-buffered cp.async, m16n8k16.
#define HSTR 40
#define HBUF (128*HSTR)              // halves per A or B buffer
#define HSTAGE (2*HBUF)              // halves per stage (A+B)
#define HG_SMEM_BYTES (2*HSTAGE*2)   // 40960

struct GP4 {
    const __half* A[4];
    const __half* B[4];   // BT
    float*        C[4];
    int N[4], K[4], lda[4], ldb[4], nbx[4], bstart[4];
    int nprob;
};

__global__ __launch_bounds__(256, 2) void hgemm_multi(GP4 p) {
    extern __shared__ __half hsm[];
    __half* sA = hsm;                  // 2 x [128][HSTR]
    __half* sB = hsm + 2 * HBUF;       // 2 x [128][HSTR]
    uint32_t sA_u = (uint32_t)__cvta_generic_to_shared(sA);
    uint32_t sB_u = (uint32_t)__cvta_generic_to_shared(sB);

    int bid = blockIdx.x;
    int pi = 0;
#pragma unroll
    for (int i = 1; i < 4; i++)
        if (i < p.nprob && bid >= p.bstart[i]) pi = i;
    const __half* A = p.A[pi];
    const __half* B = p.B[pi];
    float* C = p.C[pi];
    int N = p.N[pi], K = p.K[pi], lda = p.lda[pi], ldb = p.ldb[pi];
    int l = bid - p.bstart[pi];
    int row0 = (l / p.nbx[pi]) * 128;
    int col0 = (l % p.nbx[pi]) * 128;

    int tid = threadIdx.x;
    int warp = tid >> 5, lane = tid & 31;
    int g = lane >> 2, t = lane & 3;
    int wrow = (warp >> 2) * 64;
    int wcol = (warp & 3) * 32;

    float c[4][4][4];
#pragma unroll
    for (int mi = 0; mi < 4; mi++)
#pragma unroll
        for (int ni = 0; ni < 4; ni++)
#pragma unroll
            for (int r = 0; r < 4; r++) c[mi][ni][r] = 0.f;

    int kt_total = K / 32;

    auto load_tile = [&](int kt, int stg) {
        int k0 = kt * 32;
        uint32_t aD = sA_u + (uint32_t)(stg * HBUF * 2);
        uint32_t bD = sB_u + (uint32_t)(stg * HBUF * 2);
#pragma unroll
        for (int i = 0; i < 2; i++) {
            int idx = tid + i * 256;           // 0..511
            int r = idx >> 2, cc = (idx & 3) * 8;
            cp16(aD + (uint32_t)((r * HSTR + cc) * 2),
                 A + (size_t)(row0 + r) * lda + k0 + cc, true);
        }
#pragma unroll
        for (int i = 0; i < 2; i++) {
            int idx = tid + i * 256;
            int r = idx >> 2, cc = (idx & 3) * 8;
            bool pr = (col0 + r) < N;
            const __half* src = pr ? (B + (size_t)(col0 + r) * ldb + k0 + cc) : B;
            cp16(bD + (uint32_t)((r * HSTR + cc) * 2), src, pr);
        }
    };

    load_tile(0, 0);
    cp_commit();

    for (int kt = 0; kt < kt_total; kt++) {
        int cur = kt & 1;
        if (kt + 1 < kt_total) {
            load_tile(kt + 1, cur ^ 1);
            cp_commit();
            cp_wait<1>();
        } else {
            cp_wait<0>();
        }
        __syncthreads();

        const __half* As = sA + cur * HBUF;
        const __half* Bs = sB + cur * HBUF;
#pragma unroll
        for (int k0 = 0; k0 < 32; k0 += 16) {
            uint32_t a[4][4], b[4][2];
#pragma unroll
            for (int mi = 0; mi < 4; mi++) {
                int r0 = wrow + mi * 16 + g;
                a[mi][0] = ldh2(&As[r0 * HSTR + k0 + 2 * t]);
                a[mi][1] = ldh2(&As[(r0 + 8) * HSTR + k0 + 2 * t]);
                a[mi][2] = ldh2(&As[r0 * HSTR + k0 + 2 * t + 8]);
                a[mi][3] = ldh2(&As[(r0 + 8) * HSTR + k0 + 2 * t + 8]);
            }
#pragma unroll
            for (int ni = 0; ni < 4; ni++) {
                int cb = wcol + ni * 8 + g;
                b[ni][0] = ldh2(&Bs[cb * HSTR + k0 + 2 * t]);
                b[ni][1] = ldh2(&Bs[cb * HSTR + k0 + 2 * t + 8]);
            }
#pragma unroll
            for (int mi = 0; mi < 4; mi++)
#pragma unroll
                for (int ni = 0; ni < 4; ni++)
                    MMA_F16(c[mi][ni], a[mi], b[ni]);
        }
        __syncthreads();
    }

#pragma unroll
    for (int mi = 0; mi < 4; mi++) {
#pragma unroll
        for (int ni = 0; ni < 4; ni++) {
            int row = row0 + wrow + mi * 16 + g;
            int col = col0 + wcol + ni * 8 + 2 * t;
            if (col < N) {
                float2 v0 = make_float2(c[mi][ni][0], c[mi][ni][1]);
                float2 v1 = make_float2(c[mi][ni][2], c[mi][ni][3]);
                *reinterpret_cast<float2*>(&C[(size_t)row * N + col]) = v0;
                *reinterpret_cast<float2*>(&C[(size_t)(row + 8) * N + col]) = v1;
            }
        }
    }
}

// ---------------- fused norms + rope (half outputs) ----------------
__global__ __launch_bounds__(256) void norm_rope(
    const float* __restrict__ qa0, const float* __restrict__ qa1,
    const float* __restrict__ qw,
    const float* __restrict__ ckv0, const float* __restrict__ ckv1,
    const float* __restrict__ kvw,
    const float* __restrict__ cosb, const float* __restrict__ sinb,
    __half* __restrict__ qan, __half* __restrict__ ckvn,
    float* __restrict__ kpe) {
    int s = blockIdx.x;
    int tid = threadIdx.x;
    int lane = tid & 31, wid = tid >> 5;
    __shared__ float warp_s[8];
    __shared__ float snorm;

    float v[3];
    float ss = 0.f;
#pragma unroll
    for (int i = 0; i < 3; i++) {
        int c = tid + i * 256;
        v[i] = qa0[(size_t)s * QA_DIM + c] + qa1[(size_t)s * QA_DIM + c];
        ss += v[i] * v[i];
    }
    for (int off = 16; off > 0; off >>= 1) ss += __shfl_down_sync(0xffffffffu, ss, off);
    if (lane == 0) warp_s[wid] = ss;
    __syncthreads();
    if (tid == 0) {
        float tt = 0.f;
#pragma unroll
        for (int i = 0; i < 8; i++) tt += warp_s[i];
        snorm = rsqrtf(tt / (float)QA_DIM + EPSV);
    }
    __syncthreads();
    float rr = snorm;
#pragma unroll
    for (int i = 0; i < 3; i++) {
        int c = tid + i * 256;
        qan[(size_t)s * QA_DIM + c] = __float2half_rn(v[i] * rr * qw[c]);
    }
    __syncthreads();

    float w = ckv0[(size_t)s * KVA_DIM + tid] + ckv1[(size_t)s * KVA_DIM + tid];
    float ss2 = w * w;
    for (int off = 16; off > 0; off >>= 1) ss2 += __shfl_down_sync(0xffffffffu, ss2, off);
    if (lane == 0) warp_s[wid] = ss2;
    __syncthreads();
    if (tid == 0) {
        float tt = 0.f;
#pragma unroll
        for (int i = 0; i < 8; i++) tt += warp_s[i];
        snorm = rsqrtf(tt / (float)CKV_DIM + EPSV);
    }
    __syncthreads();
    ckvn[(size_t)s * CKV_DIM + tid] = __float2half_rn(w * snorm * kvw[tid]);

    if (tid < RD) {
        size_t base = (size_t)s * KVA_DIM + CKV_DIM;
        float x = ckv0[base + tid] + ckv1[base + tid];
        int pp = (tid < 16) ? tid + 16 : tid - 16;
        float xr = ckv0[base + pp] + ckv1[base + pp];
        float rot = (tid < 16) ? -xr : xr;
        kpe[(size_t)s * RD + tid] = x * cosb[(size_t)s * RD + tid]
                                  + rot * sinb[(size_t)s * RD + tid];
    }
}

// ---------------- prep: Q (roped+scaled, log2e), K, V-transposed ----------------
// grid (SEQ/64, NH), 256 threads
__global__ __launch_bounds__(256) void prep_kernel(
    const float* __restrict__ q, const float* __restrict__ kv,
    const float* __restrict__ kpe,
    const float* __restrict__ cosb, const float* __restrict__ sinb,
    __half* __restrict__ Q, __half* __restrict__ K, __half* __restrict__ Vt) {
    __shared__ __half smv[64 * 72];
    int s0 = blockIdx.x * 64;
    int h = blockIdx.y;
    int tid = threadIdx.x;

    // Q and K, 64 s-rows x 96 dims
#pragma unroll
    for (int i = 0; i < 24; i++) {
        int idx = tid + i * 256;
        int si = idx / DQK, d = idx % DQK;
        int s = s0 + si;
        size_t qbase = (size_t)s * QB_DIM + (size_t)h * DQK;
        float qv;
        if (d < 64) {
            qv = q[qbase + d];
        } else {
            int k = d - 64;
            float x = q[qbase + 64 + k];
            float rot = (k < 16) ? -q[qbase + 64 + k + 16] : q[qbase + 64 + k - 16];
            qv = x * cosb[(size_t)s * RD + k] + rot * sinb[(size_t)s * RD + k];
        }
        size_t hs = (size_t)h * SEQ + s;
        Q[hs * DQK + d] = __float2half_rn(qv * QSCALE_L2E);
        float kvv = (d < 64) ? kv[(size_t)s * KVB_DIM + (size_t)h * 128 + d]
                             : kpe[(size_t)s * RD + (d - 64)];
        K[hs * DQK + d] = __float2half_rn(kvv);
    }

    // V transpose: read [64 s][64 d] -> smem [d][s] -> write Vt rows
#pragma unroll
    for (int i = 0; i < 4; i++) {
        int idx = tid + i * 256;              // 0..1023
        int si = idx >> 4, c4 = (idx & 15) * 4;
        float4 v = *reinterpret_cast<const float4*>(
            &kv[(size_t)(s0 + si) * KVB_DIM + (size_t)h * 128 + 64 + c4]);
        smv[(c4 + 0) * 72 + si] = __float2half_rn(v.x);
        smv[(c4 + 1) * 72 + si] = __float2half_rn(v.y);
        smv[(c4 + 2) * 72 + si] = __float2half_rn(v.z);
        smv[(c4 + 3) * 72 + si] = __float2half_rn(v.w);
    }
    __syncthreads();
#pragma unroll
    for (int i = 0; i < 2; i++) {
        int idx = tid + i * 256;              // 0..511
        int d = idx >> 3, cc = idx & 7;
        uint4 v = *reinterpret_cast<const uint4*>(&smv[d * 72 + cc * 8]);
        *reinterpret_cast<uint4*>(
            &Vt[((size_t)h * DV + d) * SEQ + s0 + cc * 8]) = v;
    }
}

// ================= FP16 flash attention =================
// 128 q x 64 keys/tile; 8 warps, warp w owns rows [16w,16w+16).
// Q/K smem [rows][104]h, P/Vt smem [rows][72]h. One sync per K-tile.
#define FQS 104
#define FPS 72
#define FQS_H (128*FQS)        // Q
#define FKS_H (64*FQS)         // K per buffer
#define FVS_H (64*FPS)         // Vt per buffer
#define FPS_H (128*FPS)        // P
#define FLASH4_SMEM_BYTES ((FQS_H + 2*FKS_H + 2*FVS_H + FPS_H) * 2)   // 90112

__device__ __forceinline__ void flash_loadKV(const __half* __restrict__ Kh,
                                             const __half* __restrict__ Vth,
                                             int k0g, uint32_t ks_u, uint32_t vs_u,
                                             int tid) {
#pragma unroll
    for (int i = 0; i < 3; i++) {
        int idx = tid + i * 256;               // 0..767
        int r = idx / 12, cc = (idx % 12) * 8;
        cp16(ks_u + (uint32_t)((r * FQS + cc) * 2),
             Kh + (size_t)(k0g + r) * DQK + cc, true);
    }
#pragma unroll
    for (int i = 0; i < 2; i++) {
        int idx = tid + i * 256;               // 0..511
        int r = idx >> 3, cc = (idx & 7) * 8;
        cp16(vs_u + (uint32_t)((r * FPS + cc) * 2),
             Vth + (size_t)r * SEQ + k0g + cc, true);
    }
}

__global__ __launch_bounds__(256, 1) void flash4(const __half* __restrict__ Q,
                                                 const __half* __restrict__ K,
                                                 const __half* __restrict__ Vt,
                                                 __half* __restrict__ O) {
    extern __shared__ __half smh[];
    __half* Qs = smh;
    __half* Ks = Qs + FQS_H;
    __half* Vs = Ks + 2 * FKS_H;
    __half* Ps = Vs + 2 * FVS_H;
    uint32_t ks_u = (uint32_t)__cvta_generic_to_shared(Ks);
    uint32_t vs_u = (uint32_t)__cvta_generic_to_shared(Vs);
    uint32_t qs_u = (uint32_t)__cvta_generic_to_shared(Qs);

    int h = blockIdx.y;
    int qt = (int)gridDim.x - 1 - (int)blockIdx.x;   // long blocks first
    int q0 = qt * 128;
    int tid = threadIdx.x, warp = tid >> 5, lane = tid & 31;
    int g = lane >> 2, t = lane & 3;
    int r0 = warp * 16 + g;
    const __half* Qh = Q + (size_t)h * SEQ * DQK;
    const __half* Kh = K + (size_t)h * SEQ * DQK;
    const __half* Vth = Vt + (size_t)h * DV * SEQ;

    // Q tile via cp.async (128 x 96 halves)
#pragma unroll
    for (int i = 0; i < 6; i++) {
        int idx = tid + i * 256;               // 0..1535
        int r = idx / 12, cc = (idx % 12) * 8;
        cp16(qs_u + (uint32_t)((r * FQS + cc) * 2),
             Qh + (size_t)(q0 + r) * DQK + cc, true);
    }

    float m0 = -1e30f, m1 = -1e30f, l0 = 0.f, l1 = 0.f;
    float o[8][4];
#pragma unroll
    for (int ni = 0; ni < 8; ni++)
#pragma unroll
        for (int r = 0; r < 4; r++) o[ni][r] = 0.f;

    int nkt = 2 * qt + 2;
    flash_loadKV(Kh, Vth, 0, ks_u, vs_u, tid);
    cp_commit();

    for (int kt = 0; kt < nkt; kt++) {
        int cur = kt & 1;
        if (kt + 1 < nkt) {
            int nb = cur ^ 1;
            flash_loadKV(Kh, Vth, (kt + 1) * 64,
                         ks_u + (uint32_t)(nb * FKS_H * 2),
                         vs_u + (uint32_t)(nb * FVS_H * 2), tid);
            cp_commit();
            cp_wait<1>();
        } else {
            cp_wait<0>();
        }
        __syncthreads();

        const __half* KsC = Ks + cur * FKS_H;
        const __half* VsC = Vs + cur * FVS_H;

        // ---- S = Q K^T (scores already in log2 domain via QSCALE_L2E) ----
        float s[8][4];
#pragma unroll
        for (int ni = 0; ni < 8; ni++)
#pragma unroll
            for (int r = 0; r < 4; r++) s[ni][r] = 0.f;

#pragma unroll
        for (int k0 = 0; k0 < DQK; k0 += 16) {
            uint32_t a[4];
            a[0] = ldh2(&Qs[r0 * FQS + k0 + 2 * t]);
            a[1] = ldh2(&Qs[(r0 + 8) * FQS + k0 + 2 * t]);
            a[2] = ldh2(&Qs[r0 * FQS + k0 + 2 * t + 8]);
            a[3] = ldh2(&Qs[(r0 + 8) * FQS + k0 + 2 * t + 8]);
#pragma unroll
            for (int ni = 0; ni < 8; ni++) {
                uint32_t b[2];
                int cb = ni * 8 + g;
                b[0] = ldh2(&KsC[cb * FQS + k0 + 2 * t]);
                b[1] = ldh2(&KsC[cb * FQS + k0 + 2 * t + 8]);
                MMA_F16(s[ni], a, b);
            }
        }

        // ---- causal mask ----
        int k0g = kt * 64;
        if (k0g + 63 > q0) {
            int rg = q0 + r0;
#pragma unroll
            for (int ni = 0; ni < 8; ni++) {
                int col = k0g + ni * 8 + 2 * t;
                if (col > rg)         s[ni][0] = -1e30f;
                if (col + 1 > rg)     s[ni][1] = -1e30f;
                if (col > rg + 8)     s[ni][2] = -1e30f;
                if (col + 1 > rg + 8) s[ni][3] = -1e30f;
            }
        }

        // ---- online softmax (log2 domain, quad-local) ----
        float mx0 = -1e30f, mx1 = -1e30f;
#pragma unroll
        for (int ni = 0; ni < 8; ni++) {
            mx0 = fmaxf(mx0, fmaxf(s[ni][0], s[ni][1]));
            mx1 = fmaxf(mx1, fmaxf(s[ni][2], s[ni][3]));
        }
        mx0 = fmaxf(mx0, __shfl_xor_sync(0xffffffffu, mx0, 1));
        mx0 = fmaxf(mx0, __shfl_xor_sync(0xffffffffu, mx0, 2));
        mx1 = fmaxf(mx1, __shfl_xor_sync(0xffffffffu, mx1, 1));
        mx1 = fmaxf(mx1, __shfl_xor_sync(0xffffffffu, mx1, 2));

        float mn0 = fmaxf(m0, mx0), mn1 = fmaxf(m1, mx1);
        float al0 = ex2f(m0 - mn0), al1 = ex2f(m1 - mn1);
        m0 = mn0; m1 = mn1;
        l0 *= al0; l1 *= al1;

        float sum0 = 0.f, sum1 = 0.f;
#pragma unroll
        for (int ni = 0; ni < 8; ni++) {
            float p0 = ex2f(s[ni][0] - m0);
            float p1 = ex2f(s[ni][1] - m0);
            float p2 = ex2f(s[ni][2] - m1);
            float p3 = ex2f(s[ni][3] - m1);
            sum0 += p0 + p1;
            sum1 += p2 + p3;
            *reinterpret_cast<__half2*>(&Ps[r0 * FPS + ni * 8 + 2 * t]) =
                __floats2half2_rn(p0, p1);
            *reinterpret_cast<__half2*>(&Ps[(r0 + 8) * FPS + ni * 8 + 2 * t]) =
                __floats2half2_rn(p2, p3);
            o[ni][0] *= al0; o[ni][1] *= al0;
            o[ni][2] *= al1; o[ni][3] *= al1;
        }
        sum0 += __shfl_xor_sync(0xffffffffu, sum0, 1);
        sum0 += __shfl_xor_sync(0xffffffffu, sum0, 2);
        sum1 += __shfl_xor_sync(0xffffffffu, sum1, 1);
        sum1 += __shfl_xor_sync(0xffffffffu, sum1, 2);
        l0 += sum0; l1 += sum1;

        // ---- O += P V (own rows only, no barrier) ----
#pragma unroll
        for (int k0 = 0; k0 < 64; k0 += 16) {
            uint32_t a[4];
            a[0] = ldh2(&Ps[r0 * FPS + k0 + 2 * t]);
            a[1] = ldh2(&Ps[(r0 + 8) * FPS + k0 + 2 * t]);
            a[2] = ldh2(&Ps[r0 * FPS + k0 + 2 * t + 8]);
            a[3] = ldh2(&Ps[(r0 + 8) * FPS + k0 + 2 * t + 8]);
#pragma unroll
            for (int ni = 0; ni < 8; ni++) {
                uint32_t b[2];
                int cb = ni * 8 + g;
                b[0] = ldh2(&VsC[cb * FPS + k0 + 2 * t]);
                b[1] = ldh2(&VsC[cb * FPS + k0 + 2 * t + 8]);
                MMA_F16(o[ni], a, b);
            }
        }
        __syncthreads();
    }

    // ---- epilogue (half attn) ----
    float inv0 = 1.f / l0, inv1 = 1.f / l1;
    int gr = q0 + r0;
#pragma unroll
    for (int ni = 0; ni < 8; ni++) {
        int col = h * DV + ni * 8 + 2 * t;
        *reinterpret_cast<__half2*>(&O[(size_t)gr * (NH * DV) + col]) =
            __floats2half2_rn(o[ni][0] * inv0, o[ni][1] * inv0);
        *reinterpret_cast<__half2*>(&O[(size_t)(gr + 8) * (NH * DV) + col]) =
            __floats2half2_rn(o[ni][2] * inv1, o[ni][3] * inv1);
    }
}

// ---------------- split-K final add ----------------
__global__ __launch_bounds__(256) void add_kernel(float* __restrict__ out,
                                                  const float* __restrict__ o1) {
    int i = (blockIdx.x * 256 + threadIdx.x) * 4;
    float4 a = *reinterpret_cast<float4*>(out + i);
    float4 b = *reinterpret_cast<const float4*>(o1 + i);
    a.x += b.x; a.y += b.y; a.z += b.z; a.w += b.w;
    *reinterpret_cast<float4*>(out + i) = a;
}

// ---------------- launch ----------------
extern "C" void kernel_launch(void* const* d_in, const int* in_sizes, int n_in,
                              void* d_out, int out_size) {
    const float* hidden   = (const float*)d_in[0];
    const float* cosb     = (const float*)d_in[1];
    const float* sinb     = (const float*)d_in[2];
    const float* wq_a     = (const float*)d_in[3];
    const float* q_a_ln_w = (const float*)d_in[4];
    const float* wq_b     = (const float*)d_in[5];
    const float* wkv_a    = (const float*)d_in[6];
    const float* kv_a_ln  = (const float*)d_in[7];
    const float* wkv_b    = (const float*)d_in[8];
    const float* wo       = (const float*)d_in[9];
    float* out = (float*)d_out;

    float *qa0, *qa1, *ckv0, *ckv1, *kpe, *q, *kv, *o1;
    __half *hidh, *wqaT, *wkvaT, *wqbT, *wkvbT, *woT, *qan, *ckvn, *Qp, *Kp, *Vt, *attn;
    cudaGetSymbolAddress((void**)&qa0,  g_qa0);
    cudaGetSymbolAddress((void**)&qa1,  g_qa1);
    cudaGetSymbolAddress((void**)&ckv0, g_ckv0);
    cudaGetSymbolAddress((void**)&ckv1, g_ckv1);
    cudaGetSymbolAddress((void**)&kpe,  g_kpe);
    cudaGetSymbolAddress((void**)&q,    g_q);
    cudaGetSymbolAddress((void**)&kv,   g_kv);
    cudaGetSymbolAddress((void**)&o1,   g_o1);
    cudaGetSymbolAddress((void**)&hidh, g_hidh);
    cudaGetSymbolAddress((void**)&wqaT, g_wqaT);
    cudaGetSymbolAddress((void**)&wkvaT,g_wkvaT);
    cudaGetSymbolAddress((void**)&wqbT, g_wqbT);
    cudaGetSymbolAddress((void**)&wkvbT,g_wkvbT);
    cudaGetSymbolAddress((void**)&woT,  g_woT);
    cudaGetSymbolAddress((void**)&qan,  g_qan);
    cudaGetSymbolAddress((void**)&ckvn, g_ckvn);
    cudaGetSymbolAddress((void**)&Qp,   g_Q);
    cudaGetSymbolAddress((void**)&Kp,   g_K);
    cudaGetSymbolAddress((void**)&Vt,   g_Vt);
    cudaGetSymbolAddress((void**)&attn, g_attn);

    cudaFuncSetAttribute(hgemm_multi, cudaFuncAttributeMaxDynamicSharedMemorySize,
                         HG_SMEM_BYTES);
    cudaFuncSetAttribute(flash4, cudaFuncAttributeMaxDynamicSharedMemorySize,
                         FLASH4_SMEM_BYTES);

    dim3 blk(256);
    const int KH = HID / 2;   // 1280

    // 1) convert: 5 weights transposed->half, hidden straight->half
    {
        CV6 cp;
        const float* srcs[6] = { wq_a, wkv_a, wq_b, wkv_b, wo, hidden };
        __half* dsts[6] = { wqaT, wkvaT, wqbT, wkvbT, woT, hidh };
        int Ks[6] = { HID, HID, QA_DIM, CKV_DIM, NH*DV, SEQ*HID };
        int Ns[6] = { QA_DIM, KVA_DIM, QB_DIM, KVB_DIM, OUT_DIM, 0 };
        int acc = 0;
        for (int i = 0; i < 6; i++) {
            cp.src[i] = srcs[i]; cp.dst[i] = dsts[i];
            cp.K[i] = Ks[i]; cp.N[i] = Ns[i];
            cp.bstart[i] = acc;
            if (i < 5) {
                cp.trans[i] = 1;
                cp.nbx[i] = (Ns[i] + 63) / 64;
                acc += (Ks[i] / 64) * cp.nbx[i];
            } else {
                cp.trans[i] = 0;
                cp.nbx[i] = 1;
                acc += Ks[i] / 4096;
            }
        }
        cp.bstart[6] = acc;
        convtrans<<<acc, blk>>>(cp);
    }

    // 2) merged split-K: hidh@wqa (2 halves) + hidh@wkva (2 halves)
    {
        GP4 p;
        p.nprob = 4;
        p.A[0] = hidh;      p.B[0] = wqaT;       p.C[0] = qa0;
        p.N[0] = QA_DIM;  p.K[0] = KH; p.lda[0] = HID; p.ldb[0] = HID;
        p.nbx[0] = QA_DIM / 128;
        p.A[1] = hidh + KH; p.B[1] = wqaT + KH;  p.C[1] = qa1;
        p.N[1] = QA_DIM;  p.K[1] = KH; p.lda[1] = HID; p.ldb[1] = HID;
        p.nbx[1] = QA_DIM / 128;
        p.A[2] = hidh;      p.B[2] = wkvaT;      p.C[2] = ckv0;
        p.N[2] = KVA_DIM; p.K[2] = KH; p.lda[2] = HID; p.ldb[2] = HID;
        p.nbx[2] = (KVA_DIM + 127) / 128;
        p.A[3] = hidh + KH; p.B[3] = wkvaT + KH; p.C[3] = ckv1;
        p.N[3] = KVA_DIM; p.K[3] = KH; p.lda[3] = HID; p.ldb[3] = HID;
        p.nbx[3] = (KVA_DIM + 127) / 128;
        int nb0 = p.nbx[0] * (SEQ / 128);
        int nb2 = p.nbx[2] * (SEQ / 128);
        p.bstart[0] = 0; p.bstart[1] = nb0;
        p.bstart[2] = 2 * nb0; p.bstart[3] = 2 * nb0 + nb2;
        hgemm_multi<<<2 * nb0 + 2 * nb2, blk, HG_SMEM_BYTES>>>(p);
    }
    // 3) fused norms + rope
    norm_rope<<<SEQ, 256>>>(qa0, qa1, q_a_ln_w, ckv0, ckv1, kv_a_ln,
                            cosb, sinb, qan, ckvn, kpe);
    // 4) merged up-projections
    {
        GP4 p;
        p.nprob = 2;
        p.A[0] = qan;  p.B[0] = wqbT;  p.C[0] = q;
        p.N[0] = QB_DIM;  p.K[0] = QA_DIM; p.lda[0] = QA_DIM; p.ldb[0] = QA_DIM;
        p.nbx[0] = QB_DIM / 128;
        p.A[1] = ckvn; p.B[1] = wkvbT; p.C[1] = kv;
        p.N[1] = KVB_DIM; p.K[1] = CKV_DIM; p.lda[1] = CKV_DIM; p.ldb[1] = CKV_DIM;
        p.nbx[1] = KVB_DIM / 128;
        p.A[2] = p.A[0]; p.B[2] = p.B[0]; p.C[2] = p.C[0];
        p.N[2] = p.N[0]; p.K[2] = p.K[0]; p.lda[2] = p.lda[0]; p.ldb[2] = p.ldb[0];
        p.nbx[2] = 1;
        p.A[3] = p.A[0]; p.B[3] = p.B[0]; p.C[3] = p.C[0];
        p.N[3] = p.N[0]; p.K[3] = p.K[0]; p.lda[3] = p.lda[0]; p.ldb[3] = p.ldb[0];
        p.nbx[3] = 1;
        int nb0 = p.nbx[0] * (SEQ / 128);
        int nb1 = p.nbx[1] * (SEQ / 128);
        p.bstart[0] = 0; p.bstart[1] = nb0;
        p.bstart[2] = nb0 + nb1; p.bstart[3] = nb0 + nb1;
        hgemm_multi<<<nb0 + nb1, blk, HG_SMEM_BYTES>>>(p);
    }
    // 5) prep: Q/K (half) + V transpose
    prep_kernel<<<dim3(SEQ / 64, NH), blk>>>(q, kv, kpe, cosb, sinb, Qp, Kp, Vt);
    // 6) flash attention (6th launch: ncu -s 5 captures this)
    flash4<<<dim3(SEQ / 128, NH), blk, FLASH4_SMEM_BYTES>>>(Qp, Kp, Vt, attn);
    // 7) attn @ wo, split-K x2
    {
        const int KW = (NH * DV) / 2;   // 1280
        GP4 p;
        p.nprob = 2;
        p.A[0] = attn;      p.B[0] = woT;       p.C[0] = out;
        p.N[0] = OUT_DIM; p.K[0] = KW; p.lda[0] = NH * DV; p.ldb[0] = NH * DV;
        p.nbx[0] = OUT_DIM / 128;
        p.A[1] = attn + KW; p.B[1] = woT + KW;  p.C[1] = o1;
        p.N[1] = OUT_DIM; p.K[1] = KW; p.lda[1] = NH * DV; p.ldb[1] = NH * DV;
        p.nbx[1] = OUT_DIM / 128;
        p.A[2] = p.A[0]; p.B[2] = p.B[0]; p.C[2] = p.C[0];
        p.N[2] = p.N[0]; p.K[2] = p.K[0]; p.lda[2] = p.lda[0]; p.ldb[2] = p.ldb[0];
        p.nbx[2] = 1;
        p.A[3] = p.A[0]; p.B[3] = p.B[0]; p.C[3] = p.C[0];
        p.N[3] = p.N[0]; p.K[3] = p.K[0]; p.lda[3] = p.lda[0]; p.ldb[3] = p.ldb[0];
        p.nbx[3] = 1;
        int nb = p.nbx[0] * (SEQ / 128);
        p.bstart[0] = 0; p.bstart[1] = nb;
        p.bstart[2] = 2 * nb; p.bstart[3] = 2 * nb;
        hgemm_multi<<<2 * nb, blk, HG_SMEM_BYTES>>>(p);
    }
    // 8) out += o1
    add_kernel<<<(SEQ * OUT_DIM) / (256 * 4), blk>>>(out, o1);
}

// round 7
// speedup vs baseline: 7.0733x; 1.0516x over previous
#include <cuda_runtime.h>
#include <cuda_fp16.h>
#include <math.h>
#include <stdint.h>

// ---------------- problem constants ----------------
#define SEQ 2048
#define HID 2560
#define NH 40
#define DQK 96
#define DV 64
#define RD 32
#define QA_DIM 768
#define KVA_DIM 288
#define CKV_DIM 256
#define QB_DIM (NH*DQK)         // 3840
#define KVB_DIM (NH*(64+DV))    // 5120
#define OUT_DIM 2560
#define EPSV 1e-6f
// 96^-0.5 * log2(e)
#define QSCALE_L2E 0.14724602233502312f

// ---------------- scratch ----------------
__device__ float  g_qa0 [SEQ*QA_DIM];
__device__ float  g_qa1 [SEQ*QA_DIM];
__device__ float  g_ckv0[SEQ*KVA_DIM];
__device__ float  g_ckv1[SEQ*KVA_DIM];
__device__ float  g_kpe [SEQ*RD];
__device__ float  g_q   [SEQ*QB_DIM];
__device__ float  g_kv  [SEQ*KVB_DIM];
__device__ float  g_o1  [SEQ*OUT_DIM];
__device__ __half g_hidh[SEQ*HID];
__device__ __half g_wqaT[QA_DIM*HID];
__device__ __half g_wkvaT[KVA_DIM*HID];
__device__ __half g_wqbT[QB_DIM*QA_DIM];
__device__ __half g_wkvbT[KVB_DIM*CKV_DIM];
__device__ __half g_woT [OUT_DIM*(NH*DV)];
__device__ __half g_qan [SEQ*QA_DIM];
__device__ __half g_ckvn[SEQ*CKV_DIM];
__device__ __half g_Q   [NH*SEQ*DQK];
__device__ __half g_K   [NH*SEQ*DQK];
__device__ __half g_Vt  [NH*DV*SEQ];
__device__ __half g_attn[SEQ*NH*DV];

// ---------------- helpers ----------------
__device__ __forceinline__ float ex2f(float x) {
    float r;
    asm("ex2.approx.ftz.f32 %0, %1;" : "=f"(r) : "f"(x));
    return r;
}
__device__ __forceinline__ void cp16(uint32_t dst, const void* src, bool pred) {
    int sz = pred ? 16 : 0;
    asm volatile("cp.async.cg.shared.global [%0], [%1], 16, %2;\n"
                 :: "r"(dst), "l"(src), "r"(sz));
}
__device__ __forceinline__ void cp_commit() {
    asm volatile("cp.async.commit_group;\n");
}
template <int N>
__device__ __forceinline__ void cp_wait() {
    asm volatile("cp.async.wait_group %0;\n" :: "n"(N));
}

#define MMA_F16(c, a, b) \
    asm volatile("mma.sync.aligned.m16n8k16.row.col.f32.f16.f16.f32 " \
                 "{%0,%1,%2,%3},{%4,%5,%6,%7},{%8,%9},{%0,%1,%2,%3};" \
                 : "+f"(c[0]), "+f"(c[1]), "+f"(c[2]), "+f"(c[3]) \
                 : "r"(a[0]), "r"(a[1]), "r"(a[2]), "r"(a[3]), \
                   "r"(b[0]), "r"(b[1]))

__device__ __forceinline__ uint32_t ldh2(const __half* p) {
    return *reinterpret_cast<const uint32_t*>(p);
}

// ================= convert / transpose pass (unchanged) =================
struct CV6 {
    const float* src[6];
    __half* dst[6];
    int K[6], N[6];
    int nbx[6];
    int bstart[7];
    int trans[6];
};
__global__ __launch_bounds__(256) void convtrans(CV6 p) {
    __shared__ __half sm[64 * 72];
    int bid = blockIdx.x;
    int pi = 0;
#pragma unroll
    for (int i = 1; i < 6; i++) if (bid >= p.bstart[i]) pi = i;
    int l = bid - p.bstart[pi];
    int tid = threadIdx.x;
    if (p.trans[pi]) {
        int K = p.K[pi], N = p.N[pi];
        int k0 = (l / p.nbx[pi]) * 64;
        int n0 = (l % p.nbx[pi]) * 64;
        const float* src = p.src[pi];
#pragma unroll
        for (int i = 0; i < 4; i++) {
            int idx = tid + i * 256;
            int r = idx >> 4, c4 = idx & 15;
            int n = n0 + c4 * 4;
            if (n < N) {
                float4 v = *reinterpret_cast<const float4*>(
                    &src[(size_t)(k0 + r) * N + n]);
                sm[(c4 * 4 + 0) * 72 + r] = __float2half_rn(v.x);
                sm[(c4 * 4 + 1) * 72 + r] = __float2half_rn(v.y);
                sm[(c4 * 4 + 2) * 72 + r] = __float2half_rn(v.z);
                sm[(c4 * 4 + 3) * 72 + r] = __float2half_rn(v.w);
            }
        }
        __syncthreads();
        __half* dst = p.dst[pi];
#pragma unroll
        for (int i = 0; i < 2; i++) {
            int idx = tid + i * 256;
            int rr = idx >> 3, cc = idx & 7;
            if (n0 + rr < N) {
                uint4 v = *reinterpret_cast<const uint4*>(&sm[rr * 72 + cc * 8]);
                *reinterpret_cast<uint4*>(
                    &dst[(size_t)(n0 + rr) * K + k0 + cc * 8]) = v;
            }
        }
    } else {
        const float* src = p.src[pi];
        __half* dst = p.dst[pi];
        int base = l * 4096;
#pragma unroll
        for (int i = 0; i < 4; i++) {
            int e = base + (tid + i * 256) * 4;
            float4 v = *reinterpret_cast<const float4*>(&src[e]);
            __half2 h0 = __floats2half2_rn(v.x, v.y);
            __half2 h1 = __floats2half2_rn(v.z, v.w);
            *reinterpret_cast<__half2*>(&dst[e]) = h0;
            *reinterpret_cast<__half2*>(&dst[e + 2]) = h1;
        }
    }
}

// ================= multi-problem FP16 GEMM (BK=64) =================
#define HSTR 72
#define HBUF (128*HSTR)
#define HG_SMEM_BYTES (4*HBUF*2)     // 73728

struct GP4 {
    const __half* A[4];
    const __half* B[4];   // BT [N][K]
    float*        C[4];
    int N[4], K[4], lda[4], ldb[4], nbx[4], bstart[4];
    int nprob;
};

__global__ __launch_bounds__(256, 2) void hgemm_multi(GP4 p) {
    extern __shared__ __half hsm[];
    __half* sA = hsm;                  // 2 x [128][72]
    __half* sB = hsm + 2 * HBUF;
    uint32_t sA_u = (uint32_t)__cvta_generic_to_shared(sA);
    uint32_t sB_u = (uint32_t)__cvta_generic_to_shared(sB);

    int bid = blockIdx.x;
    int pi = 0;
#pragma unroll
    for (int i = 1; i < 4; i++)
        if (i < p.nprob && bid >= p.bstart[i]) pi = i;
    const __half* A = p.A[pi];
    const __half* B = p.B[pi];
    float* C = p.C[pi];
    int N = p.N[pi], K = p.K[pi], lda = p.lda[pi], ldb = p.ldb[pi];
    int l = bid - p.bstart[pi];
    int row0 = (l / p.nbx[pi]) * 128;
    int col0 = (l % p.nbx[pi]) * 128;

    int tid = threadIdx.x;
    int warp = tid >> 5, lane = tid & 31;
    int g = lane >> 2, t = lane & 3;
    int wrow = (warp >> 2) * 64;
    int wcol = (warp & 3) * 32;

    float c[4][4][4];
#pragma unroll
    for (int mi = 0; mi < 4; mi++)
#pragma unroll
        for (int ni = 0; ni < 4; ni++)
#pragma unroll
            for (int r = 0; r < 4; r++) c[mi][ni][r] = 0.f;

    int kt_total = K / 64;

    auto load_tile = [&](int kt, int stg) {
        int k0 = kt * 64;
        uint32_t aD = sA_u + (uint32_t)(stg * HBUF * 2);
        uint32_t bD = sB_u + (uint32_t)(stg * HBUF * 2);
#pragma unroll
        for (int i = 0; i < 4; i++) {
            int idx = tid + i * 256;           // 0..1023
            int r = idx >> 3, cc = (idx & 7) * 8;
            cp16(aD + (uint32_t)((r * HSTR + cc) * 2),
                 A + (size_t)(row0 + r) * lda + k0 + cc, true);
        }
#pragma unroll
        for (int i = 0; i < 4; i++) {
            int idx = tid + i * 256;
            int r = idx >> 3, cc = (idx & 7) * 8;
            bool pr = (col0 + r) < N;
            const __half* src = pr ? (B + (size_t)(col0 + r) * ldb + k0 + cc) : B;
            cp16(bD + (uint32_t)((r * HSTR + cc) * 2), src, pr);
        }
    };

    load_tile(0, 0);
    cp_commit();

    for (int kt = 0; kt < kt_total; kt++) {
        int cur = kt & 1;
        if (kt + 1 < kt_total) {
            load_tile(kt + 1, cur ^ 1);
            cp_commit();
            cp_wait<1>();
        } else {
            cp_wait<0>();
        }
        __syncthreads();

        const __half* As = sA + cur * HBUF;
        const __half* Bs = sB + cur * HBUF;
#pragma unroll
        for (int k0 = 0; k0 < 64; k0 += 16) {
            uint32_t a[4][4], b[4][2];
#pragma unroll
            for (int mi = 0; mi < 4; mi++) {
                int r0 = wrow + mi * 16 + g;
                a[mi][0] = ldh2(&As[r0 * HSTR + k0 + 2 * t]);
                a[mi][1] = ldh2(&As[(r0 + 8) * HSTR + k0 + 2 * t]);
                a[mi][2] = ldh2(&As[r0 * HSTR + k0 + 2 * t + 8]);
                a[mi][3] = ldh2(&As[(r0 + 8) * HSTR + k0 + 2 * t + 8]);
            }
#pragma unroll
            for (int ni = 0; ni < 4; ni++) {
                int cb = wcol + ni * 8 + g;
                b[ni][0] = ldh2(&Bs[cb * HSTR + k0 + 2 * t]);
                b[ni][1] = ldh2(&Bs[cb * HSTR + k0 + 2 * t + 8]);
            }
#pragma unroll
            for (int mi = 0; mi < 4; mi++)
#pragma unroll
                for (int ni = 0; ni < 4; ni++)
                    MMA_F16(c[mi][ni], a[mi], b[ni]);
        }
        __syncthreads();
    }

#pragma unroll
    for (int mi = 0; mi < 4; mi++) {
#pragma unroll
        for (int ni = 0; ni < 4; ni++) {
            int row = row0 + wrow + mi * 16 + g;
            int col = col0 + wcol + ni * 8 + 2 * t;
            if (col < N) {
                float2 v0 = make_float2(c[mi][ni][0], c[mi][ni][1]);
                float2 v1 = make_float2(c[mi][ni][2], c[mi][ni][3]);
                *reinterpret_cast<float2*>(&C[(size_t)row * N + col]) = v0;
                *reinterpret_cast<float2*>(&C[(size_t)(row + 8) * N + col]) = v1;
            }
        }
    }
}

// ---------------- fused norms + rope (unchanged) ----------------
__global__ __launch_bounds__(256) void norm_rope(
    const float* __restrict__ qa0, const float* __restrict__ qa1,
    const float* __restrict__ qw,
    const float* __restrict__ ckv0, const float* __restrict__ ckv1,
    const float* __restrict__ kvw,
    const float* __restrict__ cosb, const float* __restrict__ sinb,
    __half* __restrict__ qan, __half* __restrict__ ckvn,
    float* __restrict__ kpe) {
    int s = blockIdx.x;
    int tid = threadIdx.x;
    int lane = tid & 31, wid = tid >> 5;
    __shared__ float warp_s[8];
    __shared__ float snorm;

    float v[3];
    float ss = 0.f;
#pragma unroll
    for (int i = 0; i < 3; i++) {
        int c = tid + i * 256;
        v[i] = qa0[(size_t)s * QA_DIM + c] + qa1[(size_t)s * QA_DIM + c];
        ss += v[i] * v[i];
    }
    for (int off = 16; off > 0; off >>= 1) ss += __shfl_down_sync(0xffffffffu, ss, off);
    if (lane == 0) warp_s[wid] = ss;
    __syncthreads();
    if (tid == 0) {
        float tt = 0.f;
#pragma unroll
        for (int i = 0; i < 8; i++) tt += warp_s[i];
        snorm = rsqrtf(tt / (float)QA_DIM + EPSV);
    }
    __syncthreads();
    float rr = snorm;
#pragma unroll
    for (int i = 0; i < 3; i++) {
        int c = tid + i * 256;
        qan[(size_t)s * QA_DIM + c] = __float2half_rn(v[i] * rr * qw[c]);
    }
    __syncthreads();

    float w = ckv0[(size_t)s * KVA_DIM + tid] + ckv1[(size_t)s * KVA_DIM + tid];
    float ss2 = w * w;
    for (int off = 16; off > 0; off >>= 1) ss2 += __shfl_down_sync(0xffffffffu, ss2, off);
    if (lane == 0) warp_s[wid] = ss2;
    __syncthreads();
    if (tid == 0) {
        float tt = 0.f;
#pragma unroll
        for (int i = 0; i < 8; i++) tt += warp_s[i];
        snorm = rsqrtf(tt / (float)CKV_DIM + EPSV);
    }
    __syncthreads();
    ckvn[(size_t)s * CKV_DIM + tid] = __float2half_rn(w * snorm * kvw[tid]);

    if (tid < RD) {
        size_t base = (size_t)s * KVA_DIM + CKV_DIM;
        float x = ckv0[base + tid] + ckv1[base + tid];
        int pp = (tid < 16) ? tid + 16 : tid - 16;
        float xr = ckv0[base + pp] + ckv1[base + pp];
        float rot = (tid < 16) ? -xr : xr;
        kpe[(size_t)s * RD + tid] = x * cosb[(size_t)s * RD + tid]
                                  + rot * sinb[(size_t)s * RD + tid];
    }
}

// ---------------- prep (unchanged) ----------------
__global__ __launch_bounds__(256) void prep_kernel(
    const float* __restrict__ q, const float* __restrict__ kv,
    const float* __restrict__ kpe,
    const float* __restrict__ cosb, const float* __restrict__ sinb,
    __half* __restrict__ Q, __half* __restrict__ K, __half* __restrict__ Vt) {
    __shared__ __half smv[64 * 72];
    int s0 = blockIdx.x * 64;
    int h = blockIdx.y;
    int tid = threadIdx.x;

#pragma unroll
    for (int i = 0; i < 24; i++) {
        int idx = tid + i * 256;
        int si = idx / DQK, d = idx % DQK;
        int s = s0 + si;
        size_t qbase = (size_t)s * QB_DIM + (size_t)h * DQK;
        float qv;
        if (d < 64) {
            qv = q[qbase + d];
        } else {
            int k = d - 64;
            float x = q[qbase + 64 + k];
            float rot = (k < 16) ? -q[qbase + 64 + k + 16] : q[qbase + 64 + k - 16];
            qv = x * cosb[(size_t)s * RD + k] + rot * sinb[(size_t)s * RD + k];
        }
        size_t hs = (size_t)h * SEQ + s;
        Q[hs * DQK + d] = __float2half_rn(qv * QSCALE_L2E);
        float kvv = (d < 64) ? kv[(size_t)s * KVB_DIM + (size_t)h * 128 + d]
                             : kpe[(size_t)s * RD + (d - 64)];
        K[hs * DQK + d] = __float2half_rn(kvv);
    }

#pragma unroll
    for (int i = 0; i < 4; i++) {
        int idx = tid + i * 256;
        int si = idx >> 4, c4 = (idx & 15) * 4;
        float4 v = *reinterpret_cast<const float4*>(
            &kv[(size_t)(s0 + si) * KVB_DIM + (size_t)h * 128 + 64 + c4]);
        smv[(c4 + 0) * 72 + si] = __float2half_rn(v.x);
        smv[(c4 + 1) * 72 + si] = __float2half_rn(v.y);
        smv[(c4 + 2) * 72 + si] = __float2half_rn(v.z);
        smv[(c4 + 3) * 72 + si] = __float2half_rn(v.w);
    }
    __syncthreads();
#pragma unroll
    for (int i = 0; i < 2; i++) {
        int idx = tid + i * 256;
        int d = idx >> 3, cc = idx & 7;
        uint4 v = *reinterpret_cast<const uint4*>(&smv[d * 72 + cc * 8]);
        *reinterpret_cast<uint4*>(
            &Vt[((size_t)h * DV + d) * SEQ + s0 + cc * 8]) = v;
    }
}

// ================= FP16 flash attention: 256 q-rows x 64 keys =================
// 8 warps; warp w owns 32 rows [32w, 32w+32) as two 16-row mma tiles.
#define FQS 104
#define FPS 72
#define FQS_H (256*FQS)
#define FKS_H (64*FQS)
#define FVS_H (64*FPS)
#define FPS_H (256*FPS)
#define FLASH5_SMEM_BYTES ((FQS_H + 2*FKS_H + 2*FVS_H + FPS_H) * 2)   // 135168

__device__ __forceinline__ void flash_loadKV(const __half* __restrict__ Kh,
                                             const __half* __restrict__ Vth,
                                             int k0g, uint32_t ks_u, uint32_t vs_u,
                                             int tid) {
#pragma unroll
    for (int i = 0; i < 3; i++) {
        int idx = tid + i * 256;
        int r = idx / 12, cc = (idx % 12) * 8;
        cp16(ks_u + (uint32_t)((r * FQS + cc) * 2),
             Kh + (size_t)(k0g + r) * DQK + cc, true);
    }
#pragma unroll
    for (int i = 0; i < 2; i++) {
        int idx = tid + i * 256;
        int r = idx >> 3, cc = (idx & 7) * 8;
        cp16(vs_u + (uint32_t)((r * FPS + cc) * 2),
             Vth + (size_t)r * SEQ + k0g + cc, true);
    }
}

__global__ __launch_bounds__(256, 1) void flash5(const __half* __restrict__ Q,
                                                 const __half* __restrict__ K,
                                                 const __half* __restrict__ Vt,
                                                 __half* __restrict__ O) {
    extern __shared__ __half smh[];
    __half* Qs = smh;
    __half* Ks = Qs + FQS_H;
    __half* Vs = Ks + 2 * FKS_H;
    __half* Ps = Vs + 2 * FVS_H;
    uint32_t ks_u = (uint32_t)__cvta_generic_to_shared(Ks);
    uint32_t vs_u = (uint32_t)__cvta_generic_to_shared(Vs);
    uint32_t qs_u = (uint32_t)__cvta_generic_to_shared(Qs);

    int h = blockIdx.y;
    int qt = (int)gridDim.x - 1 - (int)blockIdx.x;   // long blocks first
    int q0 = qt * 256;
    int tid = threadIdx.x, warp = tid >> 5, lane = tid & 31;
    int g = lane >> 2, t = lane & 3;
    int wr = warp * 32 + g;                 // rows wr+16*mi, wr+16*mi+8
    const __half* Qh = Q + (size_t)h * SEQ * DQK;
    const __half* Kh = K + (size_t)h * SEQ * DQK;
    const __half* Vth = Vt + (size_t)h * DV * SEQ;

    // Q tile (256 x 96 halves) via cp.async
#pragma unroll
    for (int i = 0; i < 12; i++) {
        int idx = tid + i * 256;
        int r = idx / 12, cc = (idx % 12) * 8;
        cp16(qs_u + (uint32_t)((r * FQS + cc) * 2),
             Qh + (size_t)(q0 + r) * DQK + cc, true);
    }

    float m0[2], m1[2], l0[2], l1[2];
#pragma unroll
    for (int mi = 0; mi < 2; mi++) {
        m0[mi] = -1e30f; m1[mi] = -1e30f; l0[mi] = 0.f; l1[mi] = 0.f;
    }
    float o[2][8][4];
#pragma unroll
    for (int mi = 0; mi < 2; mi++)
#pragma unroll
        for (int ni = 0; ni < 8; ni++)
#pragma unroll
            for (int r = 0; r < 4; r++) o[mi][ni][r] = 0.f;

    int nkt = 4 * qt + 4;
    flash_loadKV(Kh, Vth, 0, ks_u, vs_u, tid);
    cp_commit();

    for (int kt = 0; kt < nkt; kt++) {
        int cur = kt & 1;
        if (kt + 1 < nkt) {
            int nb = cur ^ 1;
            flash_loadKV(Kh, Vth, (kt + 1) * 64,
                         ks_u + (uint32_t)(nb * FKS_H * 2),
                         vs_u + (uint32_t)(nb * FVS_H * 2), tid);
            cp_commit();
            cp_wait<1>();
        } else {
            cp_wait<0>();
        }
        __syncthreads();

        const __half* KsC = Ks + cur * FKS_H;
        const __half* VsC = Vs + cur * FVS_H;

        // ---- S = Q K^T for both 16-row tiles (K fragments shared) ----
        float s[2][8][4];
#pragma unroll
        for (int mi = 0; mi < 2; mi++)
#pragma unroll
            for (int ni = 0; ni < 8; ni++)
#pragma unroll
                for (int r = 0; r < 4; r++) s[mi][ni][r] = 0.f;

#pragma unroll
        for (int k0 = 0; k0 < DQK; k0 += 16) {
            uint32_t a[2][4];
#pragma unroll
            for (int mi = 0; mi < 2; mi++) {
                int r0 = wr + mi * 16;
                a[mi][0] = ldh2(&Qs[r0 * FQS + k0 + 2 * t]);
                a[mi][1] = ldh2(&Qs[(r0 + 8) * FQS + k0 + 2 * t]);
                a[mi][2] = ldh2(&Qs[r0 * FQS + k0 + 2 * t + 8]);
                a[mi][3] = ldh2(&Qs[(r0 + 8) * FQS + k0 + 2 * t + 8]);
            }
#pragma unroll
            for (int ni = 0; ni < 8; ni++) {
                uint32_t b[2];
                int cb = ni * 8 + g;
                b[0] = ldh2(&KsC[cb * FQS + k0 + 2 * t]);
                b[1] = ldh2(&KsC[cb * FQS + k0 + 2 * t + 8]);
                MMA_F16(s[0][ni], a[0], b);
                MMA_F16(s[1][ni], a[1], b);
            }
        }

        // ---- causal mask ----
        int k0g = kt * 64;
        if (k0g + 63 > q0) {
#pragma unroll
            for (int mi = 0; mi < 2; mi++) {
                int rg = q0 + wr + mi * 16;
#pragma unroll
                for (int ni = 0; ni < 8; ni++) {
                    int col = k0g + ni * 8 + 2 * t;
                    if (col > rg)         s[mi][ni][0] = -1e30f;
                    if (col + 1 > rg)     s[mi][ni][1] = -1e30f;
                    if (col > rg + 8)     s[mi][ni][2] = -1e30f;
                    if (col + 1 > rg + 8) s[mi][ni][3] = -1e30f;
                }
            }
        }

        // ---- online softmax (log2 domain) + P store + O rescale ----
#pragma unroll
        for (int mi = 0; mi < 2; mi++) {
            float mx0 = -1e30f, mx1 = -1e30f;
#pragma unroll
            for (int ni = 0; ni < 8; ni++) {
                mx0 = fmaxf(mx0, fmaxf(s[mi][ni][0], s[mi][ni][1]));
                mx1 = fmaxf(mx1, fmaxf(s[mi][ni][2], s[mi][ni][3]));
            }
            mx0 = fmaxf(mx0, __shfl_xor_sync(0xffffffffu, mx0, 1));
            mx0 = fmaxf(mx0, __shfl_xor_sync(0xffffffffu, mx0, 2));
            mx1 = fmaxf(mx1, __shfl_xor_sync(0xffffffffu, mx1, 1));
            mx1 = fmaxf(mx1, __shfl_xor_sync(0xffffffffu, mx1, 2));

            float mn0 = fmaxf(m0[mi], mx0), mn1 = fmaxf(m1[mi], mx1);
            float al0 = ex2f(m0[mi] - mn0), al1 = ex2f(m1[mi] - mn1);
            m0[mi] = mn0; m1[mi] = mn1;
            l0[mi] *= al0; l1[mi] *= al1;

            int r0 = wr + mi * 16;
            float sum0 = 0.f, sum1 = 0.f;
#pragma unroll
            for (int ni = 0; ni < 8; ni++) {
                float p0 = ex2f(s[mi][ni][0] - mn0);
                float p1 = ex2f(s[mi][ni][1] - mn0);
                float p2 = ex2f(s[mi][ni][2] - mn1);
                float p3 = ex2f(s[mi][ni][3] - mn1);
                sum0 += p0 + p1;
                sum1 += p2 + p3;
                *reinterpret_cast<__half2*>(&Ps[r0 * FPS + ni * 8 + 2 * t]) =
                    __floats2half2_rn(p0, p1);
                *reinterpret_cast<__half2*>(&Ps[(r0 + 8) * FPS + ni * 8 + 2 * t]) =
                    __floats2half2_rn(p2, p3);
                o[mi][ni][0] *= al0; o[mi][ni][1] *= al0;
                o[mi][ni][2] *= al1; o[mi][ni][3] *= al1;
            }
            sum0 += __shfl_xor_sync(0xffffffffu, sum0, 1);
            sum0 += __shfl_xor_sync(0xffffffffu, sum0, 2);
            sum1 += __shfl_xor_sync(0xffffffffu, sum1, 1);
            sum1 += __shfl_xor_sync(0xffffffffu, sum1, 2);
            l0[mi] += sum0; l1[mi] += sum1;
        }

        // ---- O += P V (V fragments shared across the two row tiles) ----
#pragma unroll
        for (int k0 = 0; k0 < 64; k0 += 16) {
            uint32_t a[2][4];
#pragma unroll
            for (int mi = 0; mi < 2; mi++) {
                int r0 = wr + mi * 16;
                a[mi][0] = ldh2(&Ps[r0 * FPS + k0 + 2 * t]);
                a[mi][1] = ldh2(&Ps[(r0 + 8) * FPS + k0 + 2 * t]);
                a[mi][2] = ldh2(&Ps[r0 * FPS + k0 + 2 * t + 8]);
                a[mi][3] = ldh2(&Ps[(r0 + 8) * FPS + k0 + 2 * t + 8]);
            }
#pragma unroll
            for (int ni = 0; ni < 8; ni++) {
                uint32_t b[2];
                int cb = ni * 8 + g;
                b[0] = ldh2(&VsC[cb * FPS + k0 + 2 * t]);
                b[1] = ldh2(&VsC[cb * FPS + k0 + 2 * t + 8]);
                MMA_F16(o[0][ni], a[0], b);
                MMA_F16(o[1][ni], a[1], b);
            }
        }
        __syncthreads();
    }

    // ---- epilogue ----
#pragma unroll
    for (int mi = 0; mi < 2; mi++) {
        float inv0 = 1.f / l0[mi], inv1 = 1.f / l1[mi];
        int gr = q0 + wr + mi * 16;
#pragma unroll
        for (int ni = 0; ni < 8; ni++) {
            int col = h * DV + ni * 8 + 2 * t;
            *reinterpret_cast<__half2*>(&O[(size_t)gr * (NH * DV) + col]) =
                __floats2half2_rn(o[mi][ni][0] * inv0, o[mi][ni][1] * inv0);
            *reinterpret_cast<__half2*>(&O[(size_t)(gr + 8) * (NH * DV) + col]) =
                __floats2half2_rn(o[mi][ni][2] * inv1, o[mi][ni][3] * inv1);
        }
    }
}

// ---------------- split-K final add ----------------
__global__ __launch_bounds__(256) void add_kernel(float* __restrict__ out,
                                                  const float* __restrict__ o1) {
    int i = (blockIdx.x * 256 + threadIdx.x) * 4;
    float4 a = *reinterpret_cast<float4*>(out + i);
    float4 b = *reinterpret_cast<const float4*>(o1 + i);
    a.x += b.x; a.y += b.y; a.z += b.z; a.w += b.w;
    *reinterpret_cast<float4*>(out + i) = a;
}

// ---------------- launch ----------------
extern "C" void kernel_launch(void* const* d_in, const int* in_sizes, int n_in,
                              void* d_out, int out_size) {
    const float* hidden   = (const float*)d_in[0];
    const float* cosb     = (const float*)d_in[1];
    const float* sinb     = (const float*)d_in[2];
    const float* wq_a     = (const float*)d_in[3];
    const float* q_a_ln_w = (const float*)d_in[4];
    const float* wq_b     = (const float*)d_in[5];
    const float* wkv_a    = (const float*)d_in[6];
    const float* kv_a_ln  = (const float*)d_in[7];
    const float* wkv_b    = (const float*)d_in[8];
    const float* wo       = (const float*)d_in[9];
    float* out = (float*)d_out;

    float *qa0, *qa1, *ckv0, *ckv1, *kpe, *q, *kv, *o1;
    __half *hidh, *wqaT, *wkvaT, *wqbT, *wkvbT, *woT, *qan, *ckvn, *Qp, *Kp, *Vt, *attn;
    cudaGetSymbolAddress((void**)&qa0,  g_qa0);
    cudaGetSymbolAddress((void**)&qa1,  g_qa1);
    cudaGetSymbolAddress((void**)&ckv0, g_ckv0);
    cudaGetSymbolAddress((void**)&ckv1, g_ckv1);
    cudaGetSymbolAddress((void**)&kpe,  g_kpe);
    cudaGetSymbolAddress((void**)&q,    g_q);
    cudaGetSymbolAddress((void**)&kv,   g_kv);
    cudaGetSymbolAddress((void**)&o1,   g_o1);
    cudaGetSymbolAddress((void**)&hidh, g_hidh);
    cudaGetSymbolAddress((void**)&wqaT, g_wqaT);
    cudaGetSymbolAddress((void**)&wkvaT,g_wkvaT);
    cudaGetSymbolAddress((void**)&wqbT, g_wqbT);
    cudaGetSymbolAddress((void**)&wkvbT,g_wkvbT);
    cudaGetSymbolAddress((void**)&woT,  g_woT);
    cudaGetSymbolAddress((void**)&qan,  g_qan);
    cudaGetSymbolAddress((void**)&ckvn, g_ckvn);
    cudaGetSymbolAddress((void**)&Qp,   g_Q);
    cudaGetSymbolAddress((void**)&Kp,   g_K);
    cudaGetSymbolAddress((void**)&Vt,   g_Vt);
    cudaGetSymbolAddress((void**)&attn, g_attn);

    cudaFuncSetAttribute(hgemm_multi, cudaFuncAttributeMaxDynamicSharedMemorySize,
                         HG_SMEM_BYTES);
    cudaFuncSetAttribute(flash5, cudaFuncAttributeMaxDynamicSharedMemorySize,
                         FLASH5_SMEM_BYTES);

    dim3 blk(256);
    const int KH = HID / 2;   // 1280

    // 1) convert
    {
        CV6 cp;
        const float* srcs[6] = { wq_a, wkv_a, wq_b, wkv_b, wo, hidden };
        __half* dsts[6] = { wqaT, wkvaT, wqbT, wkvbT, woT, hidh };
        int Ks[6] = { HID, HID, QA_DIM, CKV_DIM, NH*DV, SEQ*HID };
        int Ns[6] = { QA_DIM, KVA_DIM, QB_DIM, KVB_DIM, OUT_DIM, 0 };
        int acc = 0;
        for (int i = 0; i < 6; i++) {
            cp.src[i] = srcs[i]; cp.dst[i] = dsts[i];
            cp.K[i] = Ks[i]; cp.N[i] = Ns[i];
            cp.bstart[i] = acc;
            if (i < 5) {
                cp.trans[i] = 1;
                cp.nbx[i] = (Ns[i] + 63) / 64;
                acc += (Ks[i] / 64) * cp.nbx[i];
            } else {
                cp.trans[i] = 0;
                cp.nbx[i] = 1;
                acc += Ks[i] / 4096;
            }
        }
        cp.bstart[6] = acc;
        convtrans<<<acc, blk>>>(cp);
    }

    // 2) merged split-K down-projections
    {
        GP4 p;
        p.nprob = 4;
        p.A[0] = hidh;      p.B[0] = wqaT;       p.C[0] = qa0;
        p.N[0] = QA_DIM;  p.K[0] = KH; p.lda[0] = HID; p.ldb[0] = HID;
        p.nbx[0] = QA_DIM / 128;
        p.A[1] = hidh + KH; p.B[1] = wqaT + KH;  p.C[1] = qa1;
        p.N[1] = QA_DIM;  p.K[1] = KH; p.lda[1] = HID; p.ldb[1] = HID;
        p.nbx[1] = QA_DIM / 128;
        p.A[2] = hidh;      p.B[2] = wkvaT;      p.C[2] = ckv0;
        p.N[2] = KVA_DIM; p.K[2] = KH; p.lda[2] = HID; p.ldb[2] = HID;
        p.nbx[2] = (KVA_DIM + 127) / 128;
        p.A[3] = hidh + KH; p.B[3] = wkvaT + KH; p.C[3] = ckv1;
        p.N[3] = KVA_DIM; p.K[3] = KH; p.lda[3] = HID; p.ldb[3] = HID;
        p.nbx[3] = (KVA_DIM + 127) / 128;
        int nb0 = p.nbx[0] * (SEQ / 128);
        int nb2 = p.nbx[2] * (SEQ / 128);
        p.bstart[0] = 0; p.bstart[1] = nb0;
        p.bstart[2] = 2 * nb0; p.bstart[3] = 2 * nb0 + nb2;
        hgemm_multi<<<2 * nb0 + 2 * nb2, blk, HG_SMEM_BYTES>>>(p);
    }
    // 3) fused norms + rope
    norm_rope<<<SEQ, 256>>>(qa0, qa1, q_a_ln_w, ckv0, ckv1, kv_a_ln,
                            cosb, sinb, qan, ckvn, kpe);
    // 4) merged up-projections
    {
        GP4 p;
        p.nprob = 2;
        p.A[0] = qan;  p.B[0] = wqbT;  p.C[0] = q;
        p.N[0] = QB_DIM;  p.K[0] = QA_DIM; p.lda[0] = QA_DIM; p.ldb[0] = QA_DIM;
        p.nbx[0] = QB_DIM / 128;
        p.A[1] = ckvn; p.B[1] = wkvbT; p.C[1] = kv;
        p.N[1] = KVB_DIM; p.K[1] = CKV_DIM; p.lda[1] = CKV_DIM; p.ldb[1] = CKV_DIM;
        p.nbx[1] = KVB_DIM / 128;
        p.A[2] = p.A[0]; p.B[2] = p.B[0]; p.C[2] = p.C[0];
        p.N[2] = p.N[0]; p.K[2] = p.K[0]; p.lda[2] = p.lda[0]; p.ldb[2] = p.ldb[0];
        p.nbx[2] = 1;
        p.A[3] = p.A[0]; p.B[3] = p.B[0]; p.C[3] = p.C[0];
        p.N[3] = p.N[0]; p.K[3] = p.K[0]; p.lda[3] = p.lda[0]; p.ldb[3] = p.ldb[0];
        p.nbx[3] = 1;
        int nb0 = p.nbx[0] * (SEQ / 128);
        int nb1 = p.nbx[1] * (SEQ / 128);
        p.bstart[0] = 0; p.bstart[1] = nb0;
        p.bstart[2] = nb0 + nb1; p.bstart[3] = nb0 + nb1;
        hgemm_multi<<<nb0 + nb1, blk, HG_SMEM_BYTES>>>(p);
    }
    // 5) prep
    prep_kernel<<<dim3(SEQ / 64, NH), blk>>>(q, kv, kpe, cosb, sinb, Qp, Kp, Vt);
    // 6) flash attention (256-row tiles)
    flash5<<<dim3(SEQ / 256, NH), blk, FLASH5_SMEM_BYTES>>>(Qp, Kp, Vt, attn);
    // 7) attn @ wo, split-K x2
    {
        const int KW = (NH * DV) / 2;   // 1280
        GP4 p;
        p.nprob = 2;
        p.A[0] = attn;      p.B[0] = woT;       p.C[0] = out;
        p.N[0] = OUT_DIM; p.K[0] = KW; p.lda[0] = NH * DV; p.ldb[0] = NH * DV;
        p.nbx[0] = OUT_DIM / 128;
        p.A[1] = attn + KW; p.B[1] = woT + KW;  p.C[1] = o1;
        p.N[1] = OUT_DIM; p.K[1] = KW; p.lda[1] = NH * DV; p.ldb[1] = NH * DV;
        p.nbx[1] = OUT_DIM / 128;
        p.A[2] = p.A[0]; p.B[2] = p.B[0]; p.C[2] = p.C[0];
        p.N[2] = p.N[0]; p.K[2] = p.K[0]; p.lda[2] = p.lda[0]; p.ldb[2] = p.ldb[0];
        p.nbx[2] = 1;
        p.A[3] = p.A[0]; p.B[3] = p.B[0]; p.C[3] = p.C[0];
        p.N[3] = p.N[0]; p.K[3] = p.K[0]; p.lda[3] = p.lda[0]; p.ldb[3] = p.ldb[0];
        p.nbx[3] = 1;
        int nb = p.nbx[0] * (SEQ / 128);
        p.bstart[0] = 0; p.bstart[1] = nb;
        p.bstart[2] = 2 * nb; p.bstart[3] = 2 * nb;
        hgemm_multi<<<2 * nb, blk, HG_SMEM_BYTES>>>(p);
    }
    // 8) out += o1
    add_kernel<<<(SEQ * OUT_DIM) / (256 * 4), blk>>>(out, o1);
}

// round 8
// speedup vs baseline: 7.5354x; 1.0653x over previous
#include <cuda_runtime.h>
#include <cuda_fp16.h>
#include <math.h>
#include <stdint.h>

// ---------------- problem constants ----------------
#define SEQ 2048
#define HID 2560
#define NH 40
#define DQK 96
#define DV 64
#define RD 32
#define QA_DIM 768
#define KVA_DIM 288
#define CKV_DIM 256
#define QB_DIM (NH*DQK)         // 3840
#define KVB_DIM (NH*(64+DV))    // 5120
#define OUT_DIM 2560
#define EPSV 1e-6f
#define QSCALE_L2E 0.14724602233502312f   // 96^-0.5 * log2(e)

// ---------------- scratch ----------------
__device__ float  g_qa0 [SEQ*QA_DIM];
__device__ float  g_qa1 [SEQ*QA_DIM];
__device__ float  g_ckv0[SEQ*KVA_DIM];
__device__ float  g_ckv1[SEQ*KVA_DIM];
__device__ float  g_kpe [SEQ*RD];
__device__ float  g_q   [SEQ*QB_DIM];
__device__ float  g_kv  [SEQ*KVB_DIM];
__device__ float  g_o1  [SEQ*OUT_DIM];
__device__ __half g_hidh[SEQ*HID];
__device__ __half g_wqaT[QA_DIM*HID];
__device__ __half g_wkvaT[KVA_DIM*HID];
__device__ __half g_wqbT[QB_DIM*QA_DIM];
__device__ __half g_wkvbT[KVB_DIM*CKV_DIM];
__device__ __half g_woT [OUT_DIM*(NH*DV)];
__device__ __half g_qan [SEQ*QA_DIM];
__device__ __half g_ckvn[SEQ*CKV_DIM];
__device__ __half g_Q   [NH*SEQ*DQK];
__device__ __half g_K   [NH*SEQ*DQK];
__device__ __half g_Vt  [NH*DV*SEQ];
__device__ __half g_attn[SEQ*NH*DV];

// ---------------- helpers ----------------
__device__ __forceinline__ float ex2f(float x) {
    float r;
    asm("ex2.approx.ftz.f32 %0, %1;" : "=f"(r) : "f"(x));
    return r;
}
__device__ __forceinline__ void cp16(uint32_t dst, const void* src, bool pred) {
    int sz = pred ? 16 : 0;
    asm volatile("cp.async.cg.shared.global [%0], [%1], 16, %2;\n"
                 :: "r"(dst), "l"(src), "r"(sz));
}
__device__ __forceinline__ void cp_commit() {
    asm volatile("cp.async.commit_group;\n");
}
template <int N>
__device__ __forceinline__ void cp_wait() {
    asm volatile("cp.async.wait_group %0;\n" :: "n"(N));
}

#define MMA_F16(c, a, b) \
    asm volatile("mma.sync.aligned.m16n8k16.row.col.f32.f16.f16.f32 " \
                 "{%0,%1,%2,%3},{%4,%5,%6,%7},{%8,%9},{%0,%1,%2,%3};" \
                 : "+f"(c[0]), "+f"(c[1]), "+f"(c[2]), "+f"(c[3]) \
                 : "r"(a[0]), "r"(a[1]), "r"(a[2]), "r"(a[3]), \
                   "r"(b[0]), "r"(b[1]))

#define LDSM4(r, addr) \
    asm volatile("ldmatrix.sync.aligned.m8n8.x4.shared.b16 {%0,%1,%2,%3}, [%4];" \
                 : "=r"((r)[0]), "=r"((r)[1]), "=r"((r)[2]), "=r"((r)[3]) \
                 : "r"(addr))

// ================= convert / transpose pass (unchanged) =================
struct CV6 {
    const float* src[6];
    __half* dst[6];
    int K[6], N[6];
    int nbx[6];
    int bstart[7];
    int trans[6];
};
__global__ __launch_bounds__(256) void convtrans(CV6 p) {
    __shared__ __half sm[64 * 72];
    int bid = blockIdx.x;
    int pi = 0;
#pragma unroll
    for (int i = 1; i < 6; i++) if (bid >= p.bstart[i]) pi = i;
    int l = bid - p.bstart[pi];
    int tid = threadIdx.x;
    if (p.trans[pi]) {
        int K = p.K[pi], N = p.N[pi];
        int k0 = (l / p.nbx[pi]) * 64;
        int n0 = (l % p.nbx[pi]) * 64;
        const float* src = p.src[pi];
#pragma unroll
        for (int i = 0; i < 4; i++) {
            int idx = tid + i * 256;
            int r = idx >> 4, c4 = idx & 15;
            int n = n0 + c4 * 4;
            if (n < N) {
                float4 v = *reinterpret_cast<const float4*>(
                    &src[(size_t)(k0 + r) * N + n]);
                sm[(c4 * 4 + 0) * 72 + r] = __float2half_rn(v.x);
                sm[(c4 * 4 + 1) * 72 + r] = __float2half_rn(v.y);
                sm[(c4 * 4 + 2) * 72 + r] = __float2half_rn(v.z);
                sm[(c4 * 4 + 3) * 72 + r] = __float2half_rn(v.w);
            }
        }
        __syncthreads();
        __half* dst = p.dst[pi];
#pragma unroll
        for (int i = 0; i < 2; i++) {
            int idx = tid + i * 256;
            int rr = idx >> 3, cc = idx & 7;
            if (n0 + rr < N) {
                uint4 v = *reinterpret_cast<const uint4*>(&sm[rr * 72 + cc * 8]);
                *reinterpret_cast<uint4*>(
                    &dst[(size_t)(n0 + rr) * K + k0 + cc * 8]) = v;
            }
        }
    } else {
        const float* src = p.src[pi];
        __half* dst = p.dst[pi];
        int base = l * 4096;
#pragma unroll
        for (int i = 0; i < 4; i++) {
            int e = base + (tid + i * 256) * 4;
            float4 v = *reinterpret_cast<const float4*>(&src[e]);
            __half2 h0 = __floats2half2_rn(v.x, v.y);
            __half2 h1 = __floats2half2_rn(v.z, v.w);
            *reinterpret_cast<__half2*>(&dst[e]) = h0;
            *reinterpret_cast<__half2*>(&dst[e + 2]) = h1;
        }
    }
}

// ================= multi-problem FP16 GEMM (BK=64, ldmatrix) =================
#define HSTR 72
#define HBUF (128*HSTR)
#define HG_SMEM_BYTES (4*HBUF*2)     // 73728

struct GP4 {
    const __half* A[4];
    const __half* B[4];   // BT [N][K]
    float*        C[4];
    int N[4], K[4], lda[4], ldb[4], nbx[4], bstart[4];
    int nprob;
};

__global__ __launch_bounds__(256, 2) void hgemm_multi(GP4 p) {
    extern __shared__ __half hsm[];
    __half* sA = hsm;
    __half* sB = hsm + 2 * HBUF;
    uint32_t sA_u = (uint32_t)__cvta_generic_to_shared(sA);
    uint32_t sB_u = (uint32_t)__cvta_generic_to_shared(sB);

    int bid = blockIdx.x;
    int pi = 0;
#pragma unroll
    for (int i = 1; i < 4; i++)
        if (i < p.nprob && bid >= p.bstart[i]) pi = i;
    const __half* A = p.A[pi];
    const __half* B = p.B[pi];
    float* C = p.C[pi];
    int N = p.N[pi], K = p.K[pi], lda = p.lda[pi], ldb = p.ldb[pi];
    int l = bid - p.bstart[pi];
    int row0 = (l / p.nbx[pi]) * 128;
    int col0 = (l % p.nbx[pi]) * 128;

    int tid = threadIdx.x;
    int warp = tid >> 5, lane = tid & 31;
    int g = lane >> 2, t = lane & 3;
    int wrow = (warp >> 2) * 64;
    int wcol = (warp & 3) * 32;
    // ldmatrix lane->addr components
    int arow = lane & 15;                 // A/P pattern row offset
    int acol = (lane >> 4) * 8;           // A/P pattern col offset
    int brow = ((lane >> 4) & 1) * 8 + (lane & 7);   // B pair pattern
    int bcol = ((lane >> 3) & 1) * 8;

    float c[4][4][4];
#pragma unroll
    for (int mi = 0; mi < 4; mi++)
#pragma unroll
        for (int ni = 0; ni < 4; ni++)
#pragma unroll
            for (int r = 0; r < 4; r++) c[mi][ni][r] = 0.f;

    int kt_total = K / 64;

    auto load_tile = [&](int kt, int stg) {
        int k0 = kt * 64;
        uint32_t aD = sA_u + (uint32_t)(stg * HBUF * 2);
        uint32_t bD = sB_u + (uint32_t)(stg * HBUF * 2);
#pragma unroll
        for (int i = 0; i < 4; i++) {
            int idx = tid + i * 256;
            int r = idx >> 3, cc = (idx & 7) * 8;
            cp16(aD + (uint32_t)((r * HSTR + cc) * 2),
                 A + (size_t)(row0 + r) * lda + k0 + cc, true);
        }
#pragma unroll
        for (int i = 0; i < 4; i++) {
            int idx = tid + i * 256;
            int r = idx >> 3, cc = (idx & 7) * 8;
            bool pr = (col0 + r) < N;
            const __half* src = pr ? (B + (size_t)(col0 + r) * ldb + k0 + cc) : B;
            cp16(bD + (uint32_t)((r * HSTR + cc) * 2), src, pr);
        }
    };

    load_tile(0, 0);
    cp_commit();

    for (int kt = 0; kt < kt_total; kt++) {
        int cur = kt & 1;
        if (kt + 1 < kt_total) {
            load_tile(kt + 1, cur ^ 1);
            cp_commit();
            cp_wait<1>();
        } else {
            cp_wait<0>();
        }
        __syncthreads();

        uint32_t aBase = sA_u + (uint32_t)(cur * HBUF * 2);
        uint32_t bBase = sB_u + (uint32_t)(cur * HBUF * 2);
#pragma unroll
        for (int k0 = 0; k0 < 64; k0 += 16) {
            uint32_t a[4][4], bb[2][4];
#pragma unroll
            for (int mi = 0; mi < 4; mi++)
                LDSM4(a[mi], aBase + (uint32_t)(((wrow + mi * 16 + arow) * HSTR
                                                 + k0 + acol) * 2));
#pragma unroll
            for (int nip = 0; nip < 2; nip++)
                LDSM4(bb[nip], bBase + (uint32_t)(((wcol + nip * 16 + brow) * HSTR
                                                   + k0 + bcol) * 2));
#pragma unroll
            for (int mi = 0; mi < 4; mi++)
#pragma unroll
                for (int ni = 0; ni < 4; ni++)
                    MMA_F16(c[mi][ni], a[mi], (&bb[ni >> 1][2 * (ni & 1)]));
        }
        __syncthreads();
    }

#pragma unroll
    for (int mi = 0; mi < 4; mi++) {
#pragma unroll
        for (int ni = 0; ni < 4; ni++) {
            int row = row0 + wrow + mi * 16 + g;
            int col = col0 + wcol + ni * 8 + 2 * t;
            if (col < N) {
                float2 v0 = make_float2(c[mi][ni][0], c[mi][ni][1]);
                float2 v1 = make_float2(c[mi][ni][2], c[mi][ni][3]);
                *reinterpret_cast<float2*>(&C[(size_t)row * N + col]) = v0;
                *reinterpret_cast<float2*>(&C[(size_t)(row + 8) * N + col]) = v1;
            }
        }
    }
}

// ---------------- fused norms + rope (unchanged) ----------------
__global__ __launch_bounds__(256) void norm_rope(
    const float* __restrict__ qa0, const float* __restrict__ qa1,
    const float* __restrict__ qw,
    const float* __restrict__ ckv0, const float* __restrict__ ckv1,
    const float* __restrict__ kvw,
    const float* __restrict__ cosb, const float* __restrict__ sinb,
    __half* __restrict__ qan, __half* __restrict__ ckvn,
    float* __restrict__ kpe) {
    int s = blockIdx.x;
    int tid = threadIdx.x;
    int lane = tid & 31, wid = tid >> 5;
    __shared__ float warp_s[8];
    __shared__ float snorm;

    float v[3];
    float ss = 0.f;
#pragma unroll
    for (int i = 0; i < 3; i++) {
        int c = tid + i * 256;
        v[i] = qa0[(size_t)s * QA_DIM + c] + qa1[(size_t)s * QA_DIM + c];
        ss += v[i] * v[i];
    }
    for (int off = 16; off > 0; off >>= 1) ss += __shfl_down_sync(0xffffffffu, ss, off);
    if (lane == 0) warp_s[wid] = ss;
    __syncthreads();
    if (tid == 0) {
        float tt = 0.f;
#pragma unroll
        for (int i = 0; i < 8; i++) tt += warp_s[i];
        snorm = rsqrtf(tt / (float)QA_DIM + EPSV);
    }
    __syncthreads();
    float rr = snorm;
#pragma unroll
    for (int i = 0; i < 3; i++) {
        int c = tid + i * 256;
        qan[(size_t)s * QA_DIM + c] = __float2half_rn(v[i] * rr * qw[c]);
    }
    __syncthreads();

    float w = ckv0[(size_t)s * KVA_DIM + tid] + ckv1[(size_t)s * KVA_DIM + tid];
    float ss2 = w * w;
    for (int off = 16; off > 0; off >>= 1) ss2 += __shfl_down_sync(0xffffffffu, ss2, off);
    if (lane == 0) warp_s[wid] = ss2;
    __syncthreads();
    if (tid == 0) {
        float tt = 0.f;
#pragma unroll
        for (int i = 0; i < 8; i++) tt += warp_s[i];
        snorm = rsqrtf(tt / (float)CKV_DIM + EPSV);
    }
    __syncthreads();
    ckvn[(size_t)s * CKV_DIM + tid] = __float2half_rn(w * snorm * kvw[tid]);

    if (tid < RD) {
        size_t base = (size_t)s * KVA_DIM + CKV_DIM;
        float x = ckv0[base + tid] + ckv1[base + tid];
        int pp = (tid < 16) ? tid + 16 : tid - 16;
        float xr = ckv0[base + pp] + ckv1[base + pp];
        float rot = (tid < 16) ? -xr : xr;
        kpe[(size_t)s * RD + tid] = x * cosb[(size_t)s * RD + tid]
                                  + rot * sinb[(size_t)s * RD + tid];
    }
}

// ---------------- prep (unchanged) ----------------
__global__ __launch_bounds__(256) void prep_kernel(
    const float* __restrict__ q, const float* __restrict__ kv,
    const float* __restrict__ kpe,
    const float* __restrict__ cosb, const float* __restrict__ sinb,
    __half* __restrict__ Q, __half* __restrict__ K, __half* __restrict__ Vt) {
    __shared__ __half smv[64 * 72];
    int s0 = blockIdx.x * 64;
    int h = blockIdx.y;
    int tid = threadIdx.x;

#pragma unroll
    for (int i = 0; i < 24; i++) {
        int idx = tid + i * 256;
        int si = idx / DQK, d = idx % DQK;
        int s = s0 + si;
        size_t qbase = (size_t)s * QB_DIM + (size_t)h * DQK;
        float qv;
        if (d < 64) {
            qv = q[qbase + d];
        } else {
            int k = d - 64;
            float x = q[qbase + 64 + k];
            float rot = (k < 16) ? -q[qbase + 64 + k + 16] : q[qbase + 64 + k - 16];
            qv = x * cosb[(size_t)s * RD + k] + rot * sinb[(size_t)s * RD + k];
        }
        size_t hs = (size_t)h * SEQ + s;
        Q[hs * DQK + d] = __float2half_rn(qv * QSCALE_L2E);
        float kvv = (d < 64) ? kv[(size_t)s * KVB_DIM + (size_t)h * 128 + d]
                             : kpe[(size_t)s * RD + (d - 64)];
        K[hs * DQK + d] = __float2half_rn(kvv);
    }

#pragma unroll
    for (int i = 0; i < 4; i++) {
        int idx = tid + i * 256;
        int si = idx >> 4, c4 = (idx & 15) * 4;
        float4 v = *reinterpret_cast<const float4*>(
            &kv[(size_t)(s0 + si) * KVB_DIM + (size_t)h * 128 + 64 + c4]);
        smv[(c4 + 0) * 72 + si] = __float2half_rn(v.x);
        smv[(c4 + 1) * 72 + si] = __float2half_rn(v.y);
        smv[(c4 + 2) * 72 + si] = __float2half_rn(v.z);
        smv[(c4 + 3) * 72 + si] = __float2half_rn(v.w);
    }
    __syncthreads();
#pragma unroll
    for (int i = 0; i < 2; i++) {
        int idx = tid + i * 256;
        int d = idx >> 3, cc = idx & 7;
        uint4 v = *reinterpret_cast<const uint4*>(&smv[d * 72 + cc * 8]);
        *reinterpret_cast<uint4*>(
            &Vt[((size_t)h * DV + d) * SEQ + s0 + cc * 8]) = v;
    }
}

// ================= FP16 flash attention (256x64, ldmatrix) =================
#define FQS 104
#define FPS 72
#define FQS_H (256*FQS)
#define FKS_H (64*FQS)
#define FVS_H (64*FPS)
#define FPS_H (256*FPS)
#define FLASH5_SMEM_BYTES ((FQS_H + 2*FKS_H + 2*FVS_H + FPS_H) * 2)   // 135168

__device__ __forceinline__ void flash_loadKV(const __half* __restrict__ Kh,
                                             const __half* __restrict__ Vth,
                                             int k0g, uint32_t ks_u, uint32_t vs_u,
                                             int tid) {
#pragma unroll
    for (int i = 0; i < 3; i++) {
        int idx = tid + i * 256;
        int r = idx / 12, cc = (idx % 12) * 8;
        cp16(ks_u + (uint32_t)((r * FQS + cc) * 2),
             Kh + (size_t)(k0g + r) * DQK + cc, true);
    }
#pragma unroll
    for (int i = 0; i < 2; i++) {
        int idx = tid + i * 256;
        int r = idx >> 3, cc = (idx & 7) * 8;
        cp16(vs_u + (uint32_t)((r * FPS + cc) * 2),
             Vth + (size_t)r * SEQ + k0g + cc, true);
    }
}

__global__ __launch_bounds__(256, 1) void flash5(const __half* __restrict__ Q,
                                                 const __half* __restrict__ K,
                                                 const __half* __restrict__ Vt,
                                                 __half* __restrict__ O) {
    extern __shared__ __half smh[];
    __half* Qs = smh;
    __half* Ks = Qs + FQS_H;
    __half* Vs = Ks + 2 * FKS_H;
    __half* Ps = Vs + 2 * FVS_H;
    uint32_t ks_u = (uint32_t)__cvta_generic_to_shared(Ks);
    uint32_t vs_u = (uint32_t)__cvta_generic_to_shared(Vs);
    uint32_t qs_u = (uint32_t)__cvta_generic_to_shared(Qs);
    uint32_t ps_u = (uint32_t)__cvta_generic_to_shared(Ps);

    int h = blockIdx.y;
    int qt = (int)gridDim.x - 1 - (int)blockIdx.x;
    int q0 = qt * 256;
    int tid = threadIdx.x, warp = tid >> 5, lane = tid & 31;
    int g = lane >> 2, t = lane & 3;
    int wrb = warp * 32;                   // warp row block
    int wr = wrb + g;
    int arow = lane & 15;                  // ldmatrix A pattern
    int acol = (lane >> 4) * 8;
    int brow = ((lane >> 4) & 1) * 8 + (lane & 7);   // ldmatrix B pair pattern
    int bcol = ((lane >> 3) & 1) * 8;
    const __half* Qh = Q + (size_t)h * SEQ * DQK;
    const __half* Kh = K + (size_t)h * SEQ * DQK;
    const __half* Vth = Vt + (size_t)h * DV * SEQ;

#pragma unroll
    for (int i = 0; i < 12; i++) {
        int idx = tid + i * 256;
        int r = idx / 12, cc = (idx % 12) * 8;
        cp16(qs_u + (uint32_t)((r * FQS + cc) * 2),
             Qh + (size_t)(q0 + r) * DQK + cc, true);
    }

    float m0[2], m1[2], l0[2], l1[2];
#pragma unroll
    for (int mi = 0; mi < 2; mi++) {
        m0[mi] = -1e30f; m1[mi] = -1e30f; l0[mi] = 0.f; l1[mi] = 0.f;
    }
    float o[2][8][4];
#pragma unroll
    for (int mi = 0; mi < 2; mi++)
#pragma unroll
        for (int ni = 0; ni < 8; ni++)
#pragma unroll
            for (int r = 0; r < 4; r++) o[mi][ni][r] = 0.f;

    int nkt = 4 * qt + 4;
    flash_loadKV(Kh, Vth, 0, ks_u, vs_u, tid);
    cp_commit();

    for (int kt = 0; kt < nkt; kt++) {
        int cur = kt & 1;
        if (kt + 1 < nkt) {
            int nb = cur ^ 1;
            flash_loadKV(Kh, Vth, (kt + 1) * 64,
                         ks_u + (uint32_t)(nb * FKS_H * 2),
                         vs_u + (uint32_t)(nb * FVS_H * 2), tid);
            cp_commit();
            cp_wait<1>();
        } else {
            cp_wait<0>();
        }
        __syncthreads();

        uint32_t kBase = ks_u + (uint32_t)(cur * FKS_H * 2);
        uint32_t vBase = vs_u + (uint32_t)(cur * FVS_H * 2);

        // ---- S = Q K^T ----
        float s[2][8][4];
#pragma unroll
        for (int mi = 0; mi < 2; mi++)
#pragma unroll
            for (int ni = 0; ni < 8; ni++)
#pragma unroll
                for (int r = 0; r < 4; r++) s[mi][ni][r] = 0.f;

#pragma unroll
        for (int k0 = 0; k0 < DQK; k0 += 16) {
            uint32_t a[2][4], kb[4][4];
#pragma unroll
            for (int mi = 0; mi < 2; mi++)
                LDSM4(a[mi], qs_u + (uint32_t)(((wrb + mi * 16 + arow) * FQS
                                                + k0 + acol) * 2));
#pragma unroll
            for (int nip = 0; nip < 4; nip++)
                LDSM4(kb[nip], kBase + (uint32_t)(((nip * 16 + brow) * FQS
                                                   + k0 + bcol) * 2));
#pragma unroll
            for (int ni = 0; ni < 8; ni++) {
                MMA_F16(s[0][ni], a[0], (&kb[ni >> 1][2 * (ni & 1)]));
                MMA_F16(s[1][ni], a[1], (&kb[ni >> 1][2 * (ni & 1)]));
            }
        }

        // ---- causal mask ----
        int k0g = kt * 64;
        if (k0g + 63 > q0) {
#pragma unroll
            for (int mi = 0; mi < 2; mi++) {
                int rg = q0 + wr + mi * 16;
#pragma unroll
                for (int ni = 0; ni < 8; ni++) {
                    int col = k0g + ni * 8 + 2 * t;
                    if (col > rg)         s[mi][ni][0] = -1e30f;
                    if (col + 1 > rg)     s[mi][ni][1] = -1e30f;
                    if (col > rg + 8)     s[mi][ni][2] = -1e30f;
                    if (col + 1 > rg + 8) s[mi][ni][3] = -1e30f;
                }
            }
        }

        // ---- online softmax (log2 domain) + P store + O rescale ----
#pragma unroll
        for (int mi = 0; mi < 2; mi++) {
            float mx0 = -1e30f, mx1 = -1e30f;
#pragma unroll
            for (int ni = 0; ni < 8; ni++) {
                mx0 = fmaxf(mx0, fmaxf(s[mi][ni][0], s[mi][ni][1]));
                mx1 = fmaxf(mx1, fmaxf(s[mi][ni][2], s[mi][ni][3]));
            }
            mx0 = fmaxf(mx0, __shfl_xor_sync(0xffffffffu, mx0, 1));
            mx0 = fmaxf(mx0, __shfl_xor_sync(0xffffffffu, mx0, 2));
            mx1 = fmaxf(mx1, __shfl_xor_sync(0xffffffffu, mx1, 1));
            mx1 = fmaxf(mx1, __shfl_xor_sync(0xffffffffu, mx1, 2));

            float mn0 = fmaxf(m0[mi], mx0), mn1 = fmaxf(m1[mi], mx1);
            float al0 = ex2f(m0[mi] - mn0), al1 = ex2f(m1[mi] - mn1);
            m0[mi] = mn0; m1[mi] = mn1;
            l0[mi] *= al0; l1[mi] *= al1;

            int r0 = wr + mi * 16;
            float sum0 = 0.f, sum1 = 0.f;
#pragma unroll
            for (int ni = 0; ni < 8; ni++) {
                float p0 = ex2f(s[mi][ni][0] - mn0);
                float p1 = ex2f(s[mi][ni][1] - mn0);
                float p2 = ex2f(s[mi][ni][2] - mn1);
                float p3 = ex2f(s[mi][ni][3] - mn1);
                sum0 += p0 + p1;
                sum1 += p2 + p3;
                *reinterpret_cast<__half2*>(&Ps[r0 * FPS + ni * 8 + 2 * t]) =
                    __floats2half2_rn(p0, p1);
                *reinterpret_cast<__half2*>(&Ps[(r0 + 8) * FPS + ni * 8 + 2 * t]) =
                    __floats2half2_rn(p2, p3);
                o[mi][ni][0] *= al0; o[mi][ni][1] *= al0;
                o[mi][ni][2] *= al1; o[mi][ni][3] *= al1;
            }
            sum0 += __shfl_xor_sync(0xffffffffu, sum0, 1);
            sum0 += __shfl_xor_sync(0xffffffffu, sum0, 2);
            sum1 += __shfl_xor_sync(0xffffffffu, sum1, 1);
            sum1 += __shfl_xor_sync(0xffffffffu, sum1, 2);
            l0[mi] += sum0; l1[mi] += sum1;
        }

        // ---- O += P V ----
#pragma unroll
        for (int k0 = 0; k0 < 64; k0 += 16) {
            uint32_t a[2][4], vb[4][4];
#pragma unroll
            for (int mi = 0; mi < 2; mi++)
                LDSM4(a[mi], ps_u + (uint32_t)(((wrb + mi * 16 + arow) * FPS
                                                + k0 + acol) * 2));
#pragma unroll
            for (int nip = 0; nip < 4; nip++)
                LDSM4(vb[nip], vBase + (uint32_t)(((nip * 16 + brow) * FPS
                                                   + k0 + bcol) * 2));
#pragma unroll
            for (int ni = 0; ni < 8; ni++) {
                MMA_F16(o[0][ni], a[0], (&vb[ni >> 1][2 * (ni & 1)]));
                MMA_F16(o[1][ni], a[1], (&vb[ni >> 1][2 * (ni & 1)]));
            }
        }
        __syncthreads();
    }

    // ---- epilogue ----
#pragma unroll
    for (int mi = 0; mi < 2; mi++) {
        float inv0 = 1.f / l0[mi], inv1 = 1.f / l1[mi];
        int gr = q0 + wr + mi * 16;
#pragma unroll
        for (int ni = 0; ni < 8; ni++) {
            int col = h * DV + ni * 8 + 2 * t;
            *reinterpret_cast<__half2*>(&O[(size_t)gr * (NH * DV) + col]) =
                __floats2half2_rn(o[mi][ni][0] * inv0, o[mi][ni][1] * inv0);
            *reinterpret_cast<__half2*>(&O[(size_t)(gr + 8) * (NH * DV) + col]) =
                __floats2half2_rn(o[mi][ni][2] * inv1, o[mi][ni][3] * inv1);
        }
    }
}

// ---------------- split-K final add ----------------
__global__ __launch_bounds__(256) void add_kernel(float* __restrict__ out,
                                                  const float* __restrict__ o1) {
    int i = (blockIdx.x * 256 + threadIdx.x) * 4;
    float4 a = *reinterpret_cast<float4*>(out + i);
    float4 b = *reinterpret_cast<const float4*>(o1 + i);
    a.x += b.x; a.y += b.y; a.z += b.z; a.w += b.w;
    *reinterpret_cast<float4*>(out + i) = a;
}

// ---------------- launch ----------------
extern "C" void kernel_launch(void* const* d_in, const int* in_sizes, int n_in,
                              void* d_out, int out_size) {
    const float* hidden   = (const float*)d_in[0];
    const float* cosb     = (const float*)d_in[1];
    const float* sinb     = (const float*)d_in[2];
    const float* wq_a     = (const float*)d_in[3];
    const float* q_a_ln_w = (const float*)d_in[4];
    const float* wq_b     = (const float*)d_in[5];
    const float* wkv_a    = (const float*)d_in[6];
    const float* kv_a_ln  = (const float*)d_in[7];
    const float* wkv_b    = (const float*)d_in[8];
    const float* wo       = (const float*)d_in[9];
    float* out = (float*)d_out;

    float *qa0, *qa1, *ckv0, *ckv1, *kpe, *q, *kv, *o1;
    __half *hidh, *wqaT, *wkvaT, *wqbT, *wkvbT, *woT, *qan, *ckvn, *Qp, *Kp, *Vt, *attn;
    cudaGetSymbolAddress((void**)&qa0,  g_qa0);
    cudaGetSymbolAddress((void**)&qa1,  g_qa1);
    cudaGetSymbolAddress((void**)&ckv0, g_ckv0);
    cudaGetSymbolAddress((void**)&ckv1, g_ckv1);
    cudaGetSymbolAddress((void**)&kpe,  g_kpe);
    cudaGetSymbolAddress((void**)&q,    g_q);
    cudaGetSymbolAddress((void**)&kv,   g_kv);
    cudaGetSymbolAddress((void**)&o1,   g_o1);
    cudaGetSymbolAddress((void**)&hidh, g_hidh);
    cudaGetSymbolAddress((void**)&wqaT, g_wqaT);
    cudaGetSymbolAddress((void**)&wkvaT,g_wkvaT);
    cudaGetSymbolAddress((void**)&wqbT, g_wqbT);
    cudaGetSymbolAddress((void**)&wkvbT,g_wkvbT);
    cudaGetSymbolAddress((void**)&woT,  g_woT);
    cudaGetSymbolAddress((void**)&qan,  g_qan);
    cudaGetSymbolAddress((void**)&ckvn, g_ckvn);
    cudaGetSymbolAddress((void**)&Qp,   g_Q);
    cudaGetSymbolAddress((void**)&Kp,   g_K);
    cudaGetSymbolAddress((void**)&Vt,   g_Vt);
    cudaGetSymbolAddress((void**)&attn, g_attn);

    cudaFuncSetAttribute(hgemm_multi, cudaFuncAttributeMaxDynamicSharedMemorySize,
                         HG_SMEM_BYTES);
    cudaFuncSetAttribute(flash5, cudaFuncAttributeMaxDynamicSharedMemorySize,
                         FLASH5_SMEM_BYTES);

    dim3 blk(256);
    const int KH = HID / 2;   // 1280

    // 1) convert
    {
        CV6 cp;
        const float* srcs[6] = { wq_a, wkv_a, wq_b, wkv_b, wo, hidden };
        __half* dsts[6] = { wqaT, wkvaT, wqbT, wkvbT, woT, hidh };
        int Ks[6] = { HID, HID, QA_DIM, CKV_DIM, NH*DV, SEQ*HID };
        int Ns[6] = { QA_DIM, KVA_DIM, QB_DIM, KVB_DIM, OUT_DIM, 0 };
        int acc = 0;
        for (int i = 0; i < 6; i++) {
            cp.src[i] = srcs[i]; cp.dst[i] = dsts[i];
            cp.K[i] = Ks[i]; cp.N[i] = Ns[i];
            cp.bstart[i] = acc;
            if (i < 5) {
                cp.trans[i] = 1;
                cp.nbx[i] = (Ns[i] + 63) / 64;
                acc += (Ks[i] / 64) * cp.nbx[i];
            } else {
                cp.trans[i] = 0;
                cp.nbx[i] = 1;
                acc += Ks[i] / 4096;
            }
        }
        cp.bstart[6] = acc;
        convtrans<<<acc, blk>>>(cp);
    }

    // 2) merged split-K down-projections
    {
        GP4 p;
        p.nprob = 4;
        p.A[0] = hidh;      p.B[0] = wqaT;       p.C[0] = qa0;
        p.N[0] = QA_DIM;  p.K[0] = KH; p.lda[0] = HID; p.ldb[0] = HID;
        p.nbx[0] = QA_DIM / 128;
        p.A[1] = hidh + KH; p.B[1] = wqaT + KH;  p.C[1] = qa1;
        p.N[1] = QA_DIM;  p.K[1] = KH; p.lda[1] = HID; p.ldb[1] = HID;
        p.nbx[1] = QA_DIM / 128;
        p.A[2] = hidh;      p.B[2] = wkvaT;      p.C[2] = ckv0;
        p.N[2] = KVA_DIM; p.K[2] = KH; p.lda[2] = HID; p.ldb[2] = HID;
        p.nbx[2] = (KVA_DIM + 127) / 128;
        p.A[3] = hidh + KH; p.B[3] = wkvaT + KH; p.C[3] = ckv1;
        p.N[3] = KVA_DIM; p.K[3] = KH; p.lda[3] = HID; p.ldb[3] = HID;
        p.nbx[3] = (KVA_DIM + 127) / 128;
        int nb0 = p.nbx[0] * (SEQ / 128);
        int nb2 = p.nbx[2] * (SEQ / 128);
        p.bstart[0] = 0; p.bstart[1] = nb0;
        p.bstart[2] = 2 * nb0; p.bstart[3] = 2 * nb0 + nb2;
        hgemm_multi<<<2 * nb0 + 2 * nb2, blk, HG_SMEM_BYTES>>>(p);
    }
    // 3) fused norms + rope
    norm_rope<<<SEQ, 256>>>(qa0, qa1, q_a_ln_w, ckv0, ckv1, kv_a_ln,
                            cosb, sinb, qan, ckvn, kpe);
    // 4) merged up-projections
    {
        GP4 p;
        p.nprob = 2;
        p.A[0] = qan;  p.B[0] = wqbT;  p.C[0] = q;
        p.N[0] = QB_DIM;  p.K[0] = QA_DIM; p.lda[0] = QA_DIM; p.ldb[0] = QA_DIM;
        p.nbx[0] = QB_DIM / 128;
        p.A[1] = ckvn; p.B[1] = wkvbT; p.C[1] = kv;
        p.N[1] = KVB_DIM; p.K[1] = CKV_DIM; p.lda[1] = CKV_DIM; p.ldb[1] = CKV_DIM;
        p.nbx[1] = KVB_DIM / 128;
        p.A[2] = p.A[0]; p.B[2] = p.B[0]; p.C[2] = p.C[0];
        p.N[2] = p.N[0]; p.K[2] = p.K[0]; p.lda[2] = p.lda[0]; p.ldb[2] = p.ldb[0];
        p.nbx[2] = 1;
        p.A[3] = p.A[0]; p.B[3] = p.B[0]; p.C[3] = p.C[0];
        p.N[3] = p.N[0]; p.K[3] = p.K[0]; p.lda[3] = p.lda[0]; p.ldb[3] = p.ldb[0];
        p.nbx[3] = 1;
        int nb0 = p.nbx[0] * (SEQ / 128);
        int nb1 = p.nbx[1] * (SEQ / 128);
        p.bstart[0] = 0; p.bstart[1] = nb0;
        p.bstart[2] = nb0 + nb1; p.bstart[3] = nb0 + nb1;
        hgemm_multi<<<nb0 + nb1, blk, HG_SMEM_BYTES>>>(p);
    }
    // 5) prep
    prep_kernel<<<dim3(SEQ / 64, NH), blk>>>(q, kv, kpe, cosb, sinb, Qp, Kp, Vt);
    // 6) flash attention
    flash5<<<dim3(SEQ / 256, NH), blk, FLASH5_SMEM_BYTES>>>(Qp, Kp, Vt, attn);
    // 7) attn @ wo, split-K x2
    {
        const int KW = (NH * DV) / 2;   // 1280
        GP4 p;
        p.nprob = 2;
        p.A[0] = attn;      p.B[0] = woT;       p.C[0] = out;
        p.N[0] = OUT_DIM; p.K[0] = KW; p.lda[0] = NH * DV; p.ldb[0] = NH * DV;
        p.nbx[0] = OUT_DIM / 128;
        p.A[1] = attn + KW; p.B[1] = woT + KW;  p.C[1] = o1;
        p.N[1] = OUT_DIM; p.K[1] = KW; p.lda[1] = NH * DV; p.ldb[1] = NH * DV;
        p.nbx[1] = OUT_DIM / 128;
        p.A[2] = p.A[0]; p.B[2] = p.B[0]; p.C[2] = p.C[0];
        p.N[2] = p.N[0]; p.K[2] = p.K[0]; p.lda[2] = p.lda[0]; p.ldb[2] = p.ldb[0];
        p.nbx[2] = 1;
        p.A[3] = p.A[0]; p.B[3] = p.B[0]; p.C[3] = p.C[0];
        p.N[3] = p.N[0]; p.K[3] = p.K[0]; p.lda[3] = p.lda[0]; p.ldb[3] = p.ldb[0];
        p.nbx[3] = 1;
        int nb = p.nbx[0] * (SEQ / 128);
        p.bstart[0] = 0; p.bstart[1] = nb;
        p.bstart[2] = 2 * nb; p.bstart[3] = 2 * nb;
        hgemm_multi<<<2 * nb, blk, HG_SMEM_BYTES>>>(p);
    }
    // 8) out += o1
    add_kernel<<<(SEQ * OUT_DIM) / (256 * 4), blk>>>(out, o1);
}

// round 9
// speedup vs baseline: 7.8267x; 1.0387x over previous
#include <cuda_runtime.h>
#include <cuda_fp16.h>
#include <math.h>
#include <stdint.h>

// ---------------- problem constants ----------------
#define SEQ 2048
#define HID 2560
#define NH 40
#define DQK 96
#define DV 64
#define RD 32
#define QA_DIM 768
#define KVA_DIM 288
#define CKV_DIM 256
#define QB_DIM (NH*DQK)         // 3840
#define KVB_DIM (NH*(64+DV))    // 5120
#define OUT_DIM 2560
#define EPSV 1e-6f
#define QSCALE_L2E 0.14724602233502312f   // 96^-0.5 * log2(e)

// ---------------- scratch ----------------
__device__ float  g_qa0 [SEQ*QA_DIM];
__device__ float  g_qa1 [SEQ*QA_DIM];
__device__ float  g_ckv0[SEQ*KVA_DIM];
__device__ float  g_ckv1[SEQ*KVA_DIM];
__device__ float  g_kpe [SEQ*RD];
__device__ float  g_q   [SEQ*QB_DIM];
__device__ float  g_kv  [SEQ*KVB_DIM];
__device__ float  g_o1  [SEQ*OUT_DIM];
__device__ __half g_hidh[SEQ*HID];
__device__ __half g_wqaT[QA_DIM*HID];
__device__ __half g_wkvaT[KVA_DIM*HID];
__device__ __half g_wqbT[QB_DIM*QA_DIM];
__device__ __half g_wkvbT[KVB_DIM*CKV_DIM];
__device__ __half g_woT [OUT_DIM*(NH*DV)];
__device__ __half g_qan [SEQ*QA_DIM];
__device__ __half g_ckvn[SEQ*CKV_DIM];
__device__ __half g_Q   [NH*SEQ*DQK];
__device__ __half g_K   [NH*SEQ*DQK];
__device__ __half g_Vt  [NH*DV*SEQ];
__device__ __half g_attn[SEQ*NH*DV];

// ---------------- helpers ----------------
__device__ __forceinline__ float ex2f(float x) {
    float r;
    asm("ex2.approx.ftz.f32 %0, %1;" : "=f"(r) : "f"(x));
    return r;
}
__device__ __forceinline__ void cp16(uint32_t dst, const void* src, bool pred) {
    int sz = pred ? 16 : 0;
    asm volatile("cp.async.cg.shared.global [%0], [%1], 16, %2;\n"
                 :: "r"(dst), "l"(src), "r"(sz));
}
__device__ __forceinline__ void cp_commit() {
    asm volatile("cp.async.commit_group;\n");
}
template <int N>
__device__ __forceinline__ void cp_wait() {
    asm volatile("cp.async.wait_group %0;\n" :: "n"(N));
}

#define MMA_F16(c, a, b) \
    asm volatile("mma.sync.aligned.m16n8k16.row.col.f32.f16.f16.f32 " \
                 "{%0,%1,%2,%3},{%4,%5,%6,%7},{%8,%9},{%0,%1,%2,%3};" \
                 : "+f"(c[0]), "+f"(c[1]), "+f"(c[2]), "+f"(c[3]) \
                 : "r"(a[0]), "r"(a[1]), "r"(a[2]), "r"(a[3]), \
                   "r"(b[0]), "r"(b[1]))

#define LDSM4(r, addr) \
    asm volatile("ldmatrix.sync.aligned.m8n8.x4.shared.b16 {%0,%1,%2,%3}, [%4];" \
                 : "=r"((r)[0]), "=r"((r)[1]), "=r"((r)[2]), "=r"((r)[3]) \
                 : "r"(addr))

// ================= convert / transpose pass (unchanged) =================
struct CV6 {
    const float* src[6];
    __half* dst[6];
    int K[6], N[6];
    int nbx[6];
    int bstart[7];
    int trans[6];
};
__global__ __launch_bounds__(256) void convtrans(CV6 p) {
    __shared__ __half sm[64 * 72];
    int bid = blockIdx.x;
    int pi = 0;
#pragma unroll
    for (int i = 1; i < 6; i++) if (bid >= p.bstart[i]) pi = i;
    int l = bid - p.bstart[pi];
    int tid = threadIdx.x;
    if (p.trans[pi]) {
        int K = p.K[pi], N = p.N[pi];
        int k0 = (l / p.nbx[pi]) * 64;
        int n0 = (l % p.nbx[pi]) * 64;
        const float* src = p.src[pi];
#pragma unroll
        for (int i = 0; i < 4; i++) {
            int idx = tid + i * 256;
            int r = idx >> 4, c4 = idx & 15;
            int n = n0 + c4 * 4;
            if (n < N) {
                float4 v = *reinterpret_cast<const float4*>(
                    &src[(size_t)(k0 + r) * N + n]);
                sm[(c4 * 4 + 0) * 72 + r] = __float2half_rn(v.x);
                sm[(c4 * 4 + 1) * 72 + r] = __float2half_rn(v.y);
                sm[(c4 * 4 + 2) * 72 + r] = __float2half_rn(v.z);
                sm[(c4 * 4 + 3) * 72 + r] = __float2half_rn(v.w);
            }
        }
        __syncthreads();
        __half* dst = p.dst[pi];
#pragma unroll
        for (int i = 0; i < 2; i++) {
            int idx = tid + i * 256;
            int rr = idx >> 3, cc = idx & 7;
            if (n0 + rr < N) {
                uint4 v = *reinterpret_cast<const uint4*>(&sm[rr * 72 + cc * 8]);
                *reinterpret_cast<uint4*>(
                    &dst[(size_t)(n0 + rr) * K + k0 + cc * 8]) = v;
            }
        }
    } else {
        const float* src = p.src[pi];
        __half* dst = p.dst[pi];
        int base = l * 4096;
#pragma unroll
        for (int i = 0; i < 4; i++) {
            int e = base + (tid + i * 256) * 4;
            float4 v = *reinterpret_cast<const float4*>(&src[e]);
            __half2 h0 = __floats2half2_rn(v.x, v.y);
            __half2 h1 = __floats2half2_rn(v.z, v.w);
            *reinterpret_cast<__half2*>(&dst[e]) = h0;
            *reinterpret_cast<__half2*>(&dst[e + 2]) = h1;
        }
    }
}

// ================= multi-problem FP16 GEMM (BK=64, 3-stage, ldmatrix) ======
#define HSTR 72
#define HBUF (128*HSTR)                 // halves per A or B buffer per stage
#define HG_SMEM_BYTES (3*2*HBUF*2)      // 110592

struct GP4 {
    const __half* A[4];
    const __half* B[4];   // BT [N][K]
    float*        C[4];
    int N[4], K[4], lda[4], ldb[4], nbx[4], bstart[4];
    int nprob;
};

__global__ __launch_bounds__(256, 2) void hgemm_multi(GP4 p) {
    extern __shared__ __half hsm[];
    // layout: stage s at hsm + s*2*HBUF (A), + HBUF (B)
    uint32_t sm_u = (uint32_t)__cvta_generic_to_shared(hsm);

    int bid = blockIdx.x;
    int pi = 0;
#pragma unroll
    for (int i = 1; i < 4; i++)
        if (i < p.nprob && bid >= p.bstart[i]) pi = i;
    const __half* A = p.A[pi];
    const __half* B = p.B[pi];
    float* C = p.C[pi];
    int N = p.N[pi], K = p.K[pi], lda = p.lda[pi], ldb = p.ldb[pi];
    int l = bid - p.bstart[pi];
    int row0 = (l / p.nbx[pi]) * 128;
    int col0 = (l % p.nbx[pi]) * 128;

    int tid = threadIdx.x;
    int warp = tid >> 5, lane = tid & 31;
    int g = lane >> 2, t = lane & 3;
    int wrow = (warp >> 2) * 64;
    int wcol = (warp & 3) * 32;
    int arow = lane & 15;
    int acol = (lane >> 4) * 8;
    int brow = ((lane >> 4) & 1) * 8 + (lane & 7);
    int bcol = ((lane >> 3) & 1) * 8;

    float c[4][4][4];
#pragma unroll
    for (int mi = 0; mi < 4; mi++)
#pragma unroll
        for (int ni = 0; ni < 4; ni++)
#pragma unroll
            for (int r = 0; r < 4; r++) c[mi][ni][r] = 0.f;

    int kt_total = K / 64;

    auto load_tile = [&](int kt, int stg) {
        int k0 = kt * 64;
        uint32_t aD = sm_u + (uint32_t)(stg * 2 * HBUF * 2);
        uint32_t bD = aD + (uint32_t)(HBUF * 2);
#pragma unroll
        for (int i = 0; i < 4; i++) {
            int idx = tid + i * 256;
            int r = idx >> 3, cc = (idx & 7) * 8;
            cp16(aD + (uint32_t)((r * HSTR + cc) * 2),
                 A + (size_t)(row0 + r) * lda + k0 + cc, true);
        }
#pragma unroll
        for (int i = 0; i < 4; i++) {
            int idx = tid + i * 256;
            int r = idx >> 3, cc = (idx & 7) * 8;
            bool pr = (col0 + r) < N;
            const __half* src = pr ? (B + (size_t)(col0 + r) * ldb + k0 + cc) : B;
            cp16(bD + (uint32_t)((r * HSTR + cc) * 2), src, pr);
        }
    };

    load_tile(0, 0); cp_commit();
    load_tile(1, 1); cp_commit();

    int s_cur = 0, s_next = 2;
    for (int kt = 0; kt < kt_total; kt++) {
        cp_wait<1>();
        __syncthreads();
        if (kt + 2 < kt_total) load_tile(kt + 2, s_next);
        cp_commit();

        uint32_t aBase = sm_u + (uint32_t)(s_cur * 2 * HBUF * 2);
        uint32_t bBase = aBase + (uint32_t)(HBUF * 2);
#pragma unroll
        for (int k0 = 0; k0 < 64; k0 += 16) {
            uint32_t a[4][4], bb[2][4];
#pragma unroll
            for (int mi = 0; mi < 4; mi++)
                LDSM4(a[mi], aBase + (uint32_t)(((wrow + mi * 16 + arow) * HSTR
                                                 + k0 + acol) * 2));
#pragma unroll
            for (int nip = 0; nip < 2; nip++)
                LDSM4(bb[nip], bBase + (uint32_t)(((wcol + nip * 16 + brow) * HSTR
                                                   + k0 + bcol) * 2));
#pragma unroll
            for (int mi = 0; mi < 4; mi++)
#pragma unroll
                for (int ni = 0; ni < 4; ni++)
                    MMA_F16(c[mi][ni], a[mi], (&bb[ni >> 1][2 * (ni & 1)]));
        }
        s_cur = (s_cur == 2) ? 0 : s_cur + 1;
        s_next = (s_next == 2) ? 0 : s_next + 1;
    }

#pragma unroll
    for (int mi = 0; mi < 4; mi++) {
#pragma unroll
        for (int ni = 0; ni < 4; ni++) {
            int row = row0 + wrow + mi * 16 + g;
            int col = col0 + wcol + ni * 8 + 2 * t;
            if (col < N) {
                float2 v0 = make_float2(c[mi][ni][0], c[mi][ni][1]);
                float2 v1 = make_float2(c[mi][ni][2], c[mi][ni][3]);
                *reinterpret_cast<float2*>(&C[(size_t)row * N + col]) = v0;
                *reinterpret_cast<float2*>(&C[(size_t)(row + 8) * N + col]) = v1;
            }
        }
    }
}

// ---------------- fused norms + rope (unchanged) ----------------
__global__ __launch_bounds__(256) void norm_rope(
    const float* __restrict__ qa0, const float* __restrict__ qa1,
    const float* __restrict__ qw,
    const float* __restrict__ ckv0, const float* __restrict__ ckv1,
    const float* __restrict__ kvw,
    const float* __restrict__ cosb, const float* __restrict__ sinb,
    __half* __restrict__ qan, __half* __restrict__ ckvn,
    float* __restrict__ kpe) {
    int s = blockIdx.x;
    int tid = threadIdx.x;
    int lane = tid & 31, wid = tid >> 5;
    __shared__ float warp_s[8];
    __shared__ float snorm;

    float v[3];
    float ss = 0.f;
#pragma unroll
    for (int i = 0; i < 3; i++) {
        int c = tid + i * 256;
        v[i] = qa0[(size_t)s * QA_DIM + c] + qa1[(size_t)s * QA_DIM + c];
        ss += v[i] * v[i];
    }
    for (int off = 16; off > 0; off >>= 1) ss += __shfl_down_sync(0xffffffffu, ss, off);
    if (lane == 0) warp_s[wid] = ss;
    __syncthreads();
    if (tid == 0) {
        float tt = 0.f;
#pragma unroll
        for (int i = 0; i < 8; i++) tt += warp_s[i];
        snorm = rsqrtf(tt / (float)QA_DIM + EPSV);
    }
    __syncthreads();
    float rr = snorm;
#pragma unroll
    for (int i = 0; i < 3; i++) {
        int c = tid + i * 256;
        qan[(size_t)s * QA_DIM + c] = __float2half_rn(v[i] * rr * qw[c]);
    }
    __syncthreads();

    float w = ckv0[(size_t)s * KVA_DIM + tid] + ckv1[(size_t)s * KVA_DIM + tid];
    float ss2 = w * w;
    for (int off = 16; off > 0; off >>= 1) ss2 += __shfl_down_sync(0xffffffffu, ss2, off);
    if (lane == 0) warp_s[wid] = ss2;
    __syncthreads();
    if (tid == 0) {
        float tt = 0.f;
#pragma unroll
        for (int i = 0; i < 8; i++) tt += warp_s[i];
        snorm = rsqrtf(tt / (float)CKV_DIM + EPSV);
    }
    __syncthreads();
    ckvn[(size_t)s * CKV_DIM + tid] = __float2half_rn(w * snorm * kvw[tid]);

    if (tid < RD) {
        size_t base = (size_t)s * KVA_DIM + CKV_DIM;
        float x = ckv0[base + tid] + ckv1[base + tid];
        int pp = (tid < 16) ? tid + 16 : tid - 16;
        float xr = ckv0[base + pp] + ckv1[base + pp];
        float rot = (tid < 16) ? -xr : xr;
        kpe[(size_t)s * RD + tid] = x * cosb[(size_t)s * RD + tid]
                                  + rot * sinb[(size_t)s * RD + tid];
    }
}

// ---------------- prep (unchanged) ----------------
__global__ __launch_bounds__(256) void prep_kernel(
    const float* __restrict__ q, const float* __restrict__ kv,
    const float* __restrict__ kpe,
    const float* __restrict__ cosb, const float* __restrict__ sinb,
    __half* __restrict__ Q, __half* __restrict__ K, __half* __restrict__ Vt) {
    __shared__ __half smv[64 * 72];
    int s0 = blockIdx.x * 64;
    int h = blockIdx.y;
    int tid = threadIdx.x;

#pragma unroll
    for (int i = 0; i < 24; i++) {
        int idx = tid + i * 256;
        int si = idx / DQK, d = idx % DQK;
        int s = s0 + si;
        size_t qbase = (size_t)s * QB_DIM + (size_t)h * DQK;
        float qv;
        if (d < 64) {
            qv = q[qbase + d];
        } else {
            int k = d - 64;
            float x = q[qbase + 64 + k];
            float rot = (k < 16) ? -q[qbase + 64 + k + 16] : q[qbase + 64 + k - 16];
            qv = x * cosb[(size_t)s * RD + k] + rot * sinb[(size_t)s * RD + k];
        }
        size_t hs = (size_t)h * SEQ + s;
        Q[hs * DQK + d] = __float2half_rn(qv * QSCALE_L2E);
        float kvv = (d < 64) ? kv[(size_t)s * KVB_DIM + (size_t)h * 128 + d]
                             : kpe[(size_t)s * RD + (d - 64)];
        K[hs * DQK + d] = __float2half_rn(kvv);
    }

#pragma unroll
    for (int i = 0; i < 4; i++) {
        int idx = tid + i * 256;
        int si = idx >> 4, c4 = (idx & 15) * 4;
        float4 v = *reinterpret_cast<const float4*>(
            &kv[(size_t)(s0 + si) * KVB_DIM + (size_t)h * 128 + 64 + c4]);
        smv[(c4 + 0) * 72 + si] = __float2half_rn(v.x);
        smv[(c4 + 1) * 72 + si] = __float2half_rn(v.y);
        smv[(c4 + 2) * 72 + si] = __float2half_rn(v.z);
        smv[(c4 + 3) * 72 + si] = __float2half_rn(v.w);
    }
    __syncthreads();
#pragma unroll
    for (int i = 0; i < 2; i++) {
        int idx = tid + i * 256;
        int d = idx >> 3, cc = idx & 7;
        uint4 v = *reinterpret_cast<const uint4*>(&smv[d * 72 + cc * 8]);
        *reinterpret_cast<uint4*>(
            &Vt[((size_t)h * DV + d) * SEQ + s0 + cc * 8]) = v;
    }
}

// ================= FP16 flash attention (256x64, 3-stage, ldmatrix) ========
#define FQS 104
#define FPS 72
#define FQS_H (256*FQS)
#define FKS_H (64*FQS)
#define FVS_H (64*FPS)
#define FPS_H (256*FPS)
#define FLASH5_SMEM_BYTES ((FQS_H + 3*FKS_H + 3*FVS_H + FPS_H) * 2)   // 157696

__device__ __forceinline__ void flash_loadKV(const __half* __restrict__ Kh,
                                             const __half* __restrict__ Vth,
                                             int k0g, uint32_t ks_u, uint32_t vs_u,
                                             int tid) {
#pragma unroll
    for (int i = 0; i < 3; i++) {
        int idx = tid + i * 256;
        int r = idx / 12, cc = (idx % 12) * 8;
        cp16(ks_u + (uint32_t)((r * FQS + cc) * 2),
             Kh + (size_t)(k0g + r) * DQK + cc, true);
    }
#pragma unroll
    for (int i = 0; i < 2; i++) {
        int idx = tid + i * 256;
        int r = idx >> 3, cc = (idx & 7) * 8;
        cp16(vs_u + (uint32_t)((r * FPS + cc) * 2),
             Vth + (size_t)r * SEQ + k0g + cc, true);
    }
}

__global__ __launch_bounds__(256, 1) void flash5(const __half* __restrict__ Q,
                                                 const __half* __restrict__ K,
                                                 const __half* __restrict__ Vt,
                                                 __half* __restrict__ O) {
    extern __shared__ __half smh[];
    __half* Qs = smh;
    __half* Ks = Qs + FQS_H;            // 3 buffers
    __half* Vs = Ks + 3 * FKS_H;        // 3 buffers
    __half* Ps = Vs + 3 * FVS_H;
    uint32_t ks_u = (uint32_t)__cvta_generic_to_shared(Ks);
    uint32_t vs_u = (uint32_t)__cvta_generic_to_shared(Vs);
    uint32_t qs_u = (uint32_t)__cvta_generic_to_shared(Qs);
    uint32_t ps_u = (uint32_t)__cvta_generic_to_shared(Ps);

    int h = blockIdx.y;
    int qt = (int)gridDim.x - 1 - (int)blockIdx.x;
    int q0 = qt * 256;
    int tid = threadIdx.x, warp = tid >> 5, lane = tid & 31;
    int g = lane >> 2, t = lane & 3;
    int wrb = warp * 32;
    int wr = wrb + g;
    int arow = lane & 15;
    int acol = (lane >> 4) * 8;
    int brow = ((lane >> 4) & 1) * 8 + (lane & 7);
    int bcol = ((lane >> 3) & 1) * 8;
    const __half* Qh = Q + (size_t)h * SEQ * DQK;
    const __half* Kh = K + (size_t)h * SEQ * DQK;
    const __half* Vth = Vt + (size_t)h * DV * SEQ;

    // Q tile (in group 0 together with KV(0))
#pragma unroll
    for (int i = 0; i < 12; i++) {
        int idx = tid + i * 256;
        int r = idx / 12, cc = (idx % 12) * 8;
        cp16(qs_u + (uint32_t)((r * FQS + cc) * 2),
             Qh + (size_t)(q0 + r) * DQK + cc, true);
    }

    float m0[2], m1[2], l0[2], l1[2];
#pragma unroll
    for (int mi = 0; mi < 2; mi++) {
        m0[mi] = -1e30f; m1[mi] = -1e30f; l0[mi] = 0.f; l1[mi] = 0.f;
    }
    float o[2][8][4];
#pragma unroll
    for (int mi = 0; mi < 2; mi++)
#pragma unroll
        for (int ni = 0; ni < 8; ni++)
#pragma unroll
            for (int r = 0; r < 4; r++) o[mi][ni][r] = 0.f;

    int nkt = 4 * qt + 4;
    flash_loadKV(Kh, Vth, 0, ks_u, vs_u, tid);
    cp_commit();
    if (1 < nkt) flash_loadKV(Kh, Vth, 64, ks_u + (uint32_t)(FKS_H * 2),
                              vs_u + (uint32_t)(FVS_H * 2), tid);
    cp_commit();

    int s_cur = 0, s_next = 2;
    for (int kt = 0; kt < nkt; kt++) {
        cp_wait<1>();
        __syncthreads();
        if (kt + 2 < nkt)
            flash_loadKV(Kh, Vth, (kt + 2) * 64,
                         ks_u + (uint32_t)(s_next * FKS_H * 2),
                         vs_u + (uint32_t)(s_next * FVS_H * 2), tid);
        cp_commit();

        uint32_t kBase = ks_u + (uint32_t)(s_cur * FKS_H * 2);
        uint32_t vBase = vs_u + (uint32_t)(s_cur * FVS_H * 2);

        // ---- S = Q K^T ----
        float s[2][8][4];
#pragma unroll
        for (int mi = 0; mi < 2; mi++)
#pragma unroll
            for (int ni = 0; ni < 8; ni++)
#pragma unroll
                for (int r = 0; r < 4; r++) s[mi][ni][r] = 0.f;

#pragma unroll
        for (int k0 = 0; k0 < DQK; k0 += 16) {
            uint32_t a[2][4], kb[4][4];
#pragma unroll
            for (int mi = 0; mi < 2; mi++)
                LDSM4(a[mi], qs_u + (uint32_t)(((wrb + mi * 16 + arow) * FQS
                                                + k0 + acol) * 2));
#pragma unroll
            for (int nip = 0; nip < 4; nip++)
                LDSM4(kb[nip], kBase + (uint32_t)(((nip * 16 + brow) * FQS
                                                   + k0 + bcol) * 2));
#pragma unroll
            for (int ni = 0; ni < 8; ni++) {
                MMA_F16(s[0][ni], a[0], (&kb[ni >> 1][2 * (ni & 1)]));
                MMA_F16(s[1][ni], a[1], (&kb[ni >> 1][2 * (ni & 1)]));
            }
        }

        // ---- causal mask ----
        int k0g = kt * 64;
        if (k0g + 63 > q0) {
#pragma unroll
            for (int mi = 0; mi < 2; mi++) {
                int rg = q0 + wr + mi * 16;
#pragma unroll
                for (int ni = 0; ni < 8; ni++) {
                    int col = k0g + ni * 8 + 2 * t;
                    if (col > rg)         s[mi][ni][0] = -1e30f;
                    if (col + 1 > rg)     s[mi][ni][1] = -1e30f;
                    if (col > rg + 8)     s[mi][ni][2] = -1e30f;
                    if (col + 1 > rg + 8) s[mi][ni][3] = -1e30f;
                }
            }
        }

        // ---- online softmax (log2 domain) + P store + O rescale ----
#pragma unroll
        for (int mi = 0; mi < 2; mi++) {
            float mx0 = -1e30f, mx1 = -1e30f;
#pragma unroll
            for (int ni = 0; ni < 8; ni++) {
                mx0 = fmaxf(mx0, fmaxf(s[mi][ni][0], s[mi][ni][1]));
                mx1 = fmaxf(mx1, fmaxf(s[mi][ni][2], s[mi][ni][3]));
            }
            mx0 = fmaxf(mx0, __shfl_xor_sync(0xffffffffu, mx0, 1));
            mx0 = fmaxf(mx0, __shfl_xor_sync(0xffffffffu, mx0, 2));
            mx1 = fmaxf(mx1, __shfl_xor_sync(0xffffffffu, mx1, 1));
            mx1 = fmaxf(mx1, __shfl_xor_sync(0xffffffffu, mx1, 2));

            float mn0 = fmaxf(m0[mi], mx0), mn1 = fmaxf(m1[mi], mx1);
            float al0 = ex2f(m0[mi] - mn0), al1 = ex2f(m1[mi] - mn1);
            m0[mi] = mn0; m1[mi] = mn1;
            l0[mi] *= al0; l1[mi] *= al1;

            int r0 = wr + mi * 16;
            float sum0 = 0.f, sum1 = 0.f;
#pragma unroll
            for (int ni = 0; ni < 8; ni++) {
                float p0 = ex2f(s[mi][ni][0] - mn0);
                float p1 = ex2f(s[mi][ni][1] - mn0);
                float p2 = ex2f(s[mi][ni][2] - mn1);
                float p3 = ex2f(s[mi][ni][3] - mn1);
                sum0 += p0 + p1;
                sum1 += p2 + p3;
                *reinterpret_cast<__half2*>(&Ps[r0 * FPS + ni * 8 + 2 * t]) =
                    __floats2half2_rn(p0, p1);
                *reinterpret_cast<__half2*>(&Ps[(r0 + 8) * FPS + ni * 8 + 2 * t]) =
                    __floats2half2_rn(p2, p3);
                o[mi][ni][0] *= al0; o[mi][ni][1] *= al0;
                o[mi][ni][2] *= al1; o[mi][ni][3] *= al1;
            }
            sum0 += __shfl_xor_sync(0xffffffffu, sum0, 1);
            sum0 += __shfl_xor_sync(0xffffffffu, sum0, 2);
            sum1 += __shfl_xor_sync(0xffffffffu, sum1, 1);
            sum1 += __shfl_xor_sync(0xffffffffu, sum1, 2);
            l0[mi] += sum0; l1[mi] += sum1;
        }

        // ---- O += P V (own rows only, no barrier) ----
#pragma unroll
        for (int k0 = 0; k0 < 64; k0 += 16) {
            uint32_t a[2][4], vb[4][4];
#pragma unroll
            for (int mi = 0; mi < 2; mi++)
                LDSM4(a[mi], ps_u + (uint32_t)(((wrb + mi * 16 + arow) * FPS
                                                + k0 + acol) * 2));
#pragma unroll
            for (int nip = 0; nip < 4; nip++)
                LDSM4(vb[nip], vBase + (uint32_t)(((nip * 16 + brow) * FPS
                                                   + k0 + bcol) * 2));
#pragma unroll
            for (int ni = 0; ni < 8; ni++) {
                MMA_F16(o[0][ni], a[0], (&vb[ni >> 1][2 * (ni & 1)]));
                MMA_F16(o[1][ni], a[1], (&vb[ni >> 1][2 * (ni & 1)]));
            }
        }
        s_cur = (s_cur == 2) ? 0 : s_cur + 1;
        s_next = (s_next == 2) ? 0 : s_next + 1;
    }

    // ---- epilogue ----
#pragma unroll
    for (int mi = 0; mi < 2; mi++) {
        float inv0 = 1.f / l0[mi], inv1 = 1.f / l1[mi];
        int gr = q0 + wr + mi * 16;
#pragma unroll
        for (int ni = 0; ni < 8; ni++) {
            int col = h * DV + ni * 8 + 2 * t;
            *reinterpret_cast<__half2*>(&O[(size_t)gr * (NH * DV) + col]) =
                __floats2half2_rn(o[mi][ni][0] * inv0, o[mi][ni][1] * inv0);
            *reinterpret_cast<__half2*>(&O[(size_t)(gr + 8) * (NH * DV) + col]) =
                __floats2half2_rn(o[mi][ni][2] * inv1, o[mi][ni][3] * inv1);
        }
    }
}

// ---------------- split-K final add ----------------
__global__ __launch_bounds__(256) void add_kernel(float* __restrict__ out,
                                                  const float* __restrict__ o1) {
    int i = (blockIdx.x * 256 + threadIdx.x) * 4;
    float4 a = *reinterpret_cast<float4*>(out + i);
    float4 b = *reinterpret_cast<const float4*>(o1 + i);
    a.x += b.x; a.y += b.y; a.z += b.z; a.w += b.w;
    *reinterpret_cast<float4*>(out + i) = a;
}

// ---------------- launch ----------------
extern "C" void kernel_launch(void* const* d_in, const int* in_sizes, int n_in,
                              void* d_out, int out_size) {
    const float* hidden   = (const float*)d_in[0];
    const float* cosb     = (const float*)d_in[1];
    const float* sinb     = (const float*)d_in[2];
    const float* wq_a     = (const float*)d_in[3];
    const float* q_a_ln_w = (const float*)d_in[4];
    const float* wq_b     = (const float*)d_in[5];
    const float* wkv_a    = (const float*)d_in[6];
    const float* kv_a_ln  = (const float*)d_in[7];
    const float* wkv_b    = (const float*)d_in[8];
    const float* wo       = (const float*)d_in[9];
    float* out = (float*)d_out;

    float *qa0, *qa1, *ckv0, *ckv1, *kpe, *q, *kv, *o1;
    __half *hidh, *wqaT, *wkvaT, *wqbT, *wkvbT, *woT, *qan, *ckvn, *Qp, *Kp, *Vt, *attn;
    cudaGetSymbolAddress((void**)&qa0,  g_qa0);
    cudaGetSymbolAddress((void**)&qa1,  g_qa1);
    cudaGetSymbolAddress((void**)&ckv0, g_ckv0);
    cudaGetSymbolAddress((void**)&ckv1, g_ckv1);
    cudaGetSymbolAddress((void**)&kpe,  g_kpe);
    cudaGetSymbolAddress((void**)&q,    g_q);
    cudaGetSymbolAddress((void**)&kv,   g_kv);
    cudaGetSymbolAddress((void**)&o1,   g_o1);
    cudaGetSymbolAddress((void**)&hidh, g_hidh);
    cudaGetSymbolAddress((void**)&wqaT, g_wqaT);
    cudaGetSymbolAddress((void**)&wkvaT,g_wkvaT);
    cudaGetSymbolAddress((void**)&wqbT, g_wqbT);
    cudaGetSymbolAddress((void**)&wkvbT,g_wkvbT);
    cudaGetSymbolAddress((void**)&woT,  g_woT);
    cudaGetSymbolAddress((void**)&qan,  g_qan);
    cudaGetSymbolAddress((void**)&ckvn, g_ckvn);
    cudaGetSymbolAddress((void**)&Qp,   g_Q);
    cudaGetSymbolAddress((void**)&Kp,   g_K);
    cudaGetSymbolAddress((void**)&Vt,   g_Vt);
    cudaGetSymbolAddress((void**)&attn, g_attn);

    cudaFuncSetAttribute(hgemm_multi, cudaFuncAttributeMaxDynamicSharedMemorySize,
                         HG_SMEM_BYTES);
    cudaFuncSetAttribute(flash5, cudaFuncAttributeMaxDynamicSharedMemorySize,
                         FLASH5_SMEM_BYTES);

    dim3 blk(256);
    const int KH = HID / 2;   // 1280

    // 1) convert
    {
        CV6 cp;
        const float* srcs[6] = { wq_a, wkv_a, wq_b, wkv_b, wo, hidden };
        __half* dsts[6] = { wqaT, wkvaT, wqbT, wkvbT, woT, hidh };
        int Ks[6] = { HID, HID, QA_DIM, CKV_DIM, NH*DV, SEQ*HID };
        int Ns[6] = { QA_DIM, KVA_DIM, QB_DIM, KVB_DIM, OUT_DIM, 0 };
        int acc = 0;
        for (int i = 0; i < 6; i++) {
            cp.src[i] = srcs[i]; cp.dst[i] = dsts[i];
            cp.K[i] = Ks[i]; cp.N[i] = Ns[i];
            cp.bstart[i] = acc;
            if (i < 5) {
                cp.trans[i] = 1;
                cp.nbx[i] = (Ns[i] + 63) / 64;
                acc += (Ks[i] / 64) * cp.nbx[i];
            } else {
                cp.trans[i] = 0;
                cp.nbx[i] = 1;
                acc += Ks[i] / 4096;
            }
        }
        cp.bstart[6] = acc;
        convtrans<<<acc, blk>>>(cp);
    }

    // 2) merged split-K down-projections
    {
        GP4 p;
        p.nprob = 4;
        p.A[0] = hidh;      p.B[0] = wqaT;       p.C[0] = qa0;
        p.N[0] = QA_DIM;  p.K[0] = KH; p.lda[0] = HID; p.ldb[0] = HID;
        p.nbx[0] = QA_DIM / 128;
        p.A[1] = hidh + KH; p.B[1] = wqaT + KH;  p.C[1] = qa1;
        p.N[1] = QA_DIM;  p.K[1] = KH; p.lda[1] = HID; p.ldb[1] = HID;
        p.nbx[1] = QA_DIM / 128;
        p.A[2] = hidh;      p.B[2] = wkvaT;      p.C[2] = ckv0;
        p.N[2] = KVA_DIM; p.K[2] = KH; p.lda[2] = HID; p.ldb[2] = HID;
        p.nbx[2] = (KVA_DIM + 127) / 128;
        p.A[3] = hidh + KH; p.B[3] = wkvaT + KH; p.C[3] = ckv1;
        p.N[3] = KVA_DIM; p.K[3] = KH; p.lda[3] = HID; p.ldb[3] = HID;
        p.nbx[3] = (KVA_DIM + 127) / 128;
        int nb0 = p.nbx[0] * (SEQ / 128);
        int nb2 = p.nbx[2] * (SEQ / 128);
        p.bstart[0] = 0; p.bstart[1] = nb0;
        p.bstart[2] = 2 * nb0; p.bstart[3] = 2 * nb0 + nb2;
        hgemm_multi<<<2 * nb0 + 2 * nb2, blk, HG_SMEM_BYTES>>>(p);
    }
    // 3) fused norms + rope
    norm_rope<<<SEQ, 256>>>(qa0, qa1, q_a_ln_w, ckv0, ckv1, kv_a_ln,
                            cosb, sinb, qan, ckvn, kpe);
    // 4) merged up-projections
    {
        GP4 p;
        p.nprob = 2;
        p.A[0] = qan;  p.B[0] = wqbT;  p.C[0] = q;
        p.N[0] = QB_DIM;  p.K[0] = QA_DIM; p.lda[0] = QA_DIM; p.ldb[0] = QA_DIM;
        p.nbx[0] = QB_DIM / 128;
        p.A[1] = ckvn; p.B[1] = wkvbT; p.C[1] = kv;
        p.N[1] = KVB_DIM; p.K[1] = CKV_DIM; p.lda[1] = CKV_DIM; p.ldb[1] = CKV_DIM;
        p.nbx[1] = KVB_DIM / 128;
        p.A[2] = p.A[0]; p.B[2] = p.B[0]; p.C[2] = p.C[0];
        p.N[2] = p.N[0]; p.K[2] = p.K[0]; p.lda[2] = p.lda[0]; p.ldb[2] = p.ldb[0];
        p.nbx[2] = 1;
        p.A[3] = p.A[0]; p.B[3] = p.B[0]; p.C[3] = p.C[0];
        p.N[3] = p.N[0]; p.K[3] = p.K[0]; p.lda[3] = p.lda[0]; p.ldb[3] = p.ldb[0];
        p.nbx[3] = 1;
        int nb0 = p.nbx[0] * (SEQ / 128);
        int nb1 = p.nbx[1] * (SEQ / 128);
        p.bstart[0] = 0; p.bstart[1] = nb0;
        p.bstart[2] = nb0 + nb1; p.bstart[3] = nb0 + nb1;
        hgemm_multi<<<nb0 + nb1, blk, HG_SMEM_BYTES>>>(p);
    }
    // 5) prep
    prep_kernel<<<dim3(SEQ / 64, NH), blk>>>(q, kv, kpe, cosb, sinb, Qp, Kp, Vt);
    // 6) flash attention
    flash5<<<dim3(SEQ / 256, NH), blk, FLASH5_SMEM_BYTES>>>(Qp, Kp, Vt, attn);
    // 7) attn @ wo, split-K x2
    {
        const int KW = (NH * DV) / 2;   // 1280
        GP4 p;
        p.nprob = 2;
        p.A[0] = attn;      p.B[0] = woT;       p.C[0] = out;
        p.N[0] = OUT_DIM; p.K[0] = KW; p.lda[0] = NH * DV; p.ldb[0] = NH * DV;
        p.nbx[0] = OUT_DIM / 128;
        p.A[1] = attn + KW; p.B[1] = woT + KW;  p.C[1] = o1;
        p.N[1] = OUT_DIM; p.K[1] = KW; p.lda[1] = NH * DV; p.ldb[1] = NH * DV;
        p.nbx[1] = OUT_DIM / 128;
        p.A[2] = p.A[0]; p.B[2] = p.B[0]; p.C[2] = p.C[0];
        p.N[2] = p.N[0]; p.K[2] = p.K[0]; p.lda[2] = p.lda[0]; p.ldb[2] = p.ldb[0];
        p.nbx[2] = 1;
        p.A[3] = p.A[0]; p.B[3] = p.B[0]; p.C[3] = p.C[0];
        p.N[3] = p.N[0]; p.K[3] = p.K[0]; p.lda[3] = p.lda[0]; p.ldb[3] = p.ldb[0];
        p.nbx[3] = 1;
        int nb = p.nbx[0] * (SEQ / 128);
        p.bstart[0] = 0; p.bstart[1] = nb;
        p.bstart[2] = 2 * nb; p.bstart[3] = 2 * nb;
        hgemm_multi<<<2 * nb, blk, HG_SMEM_BYTES>>>(p);
    }
    // 8) out += o1
    add_kernel<<<(SEQ * OUT_DIM) / (256 * 4), blk>>>(out, o1);
}